// round 1
// baseline (speedup 1.0000x reference)
#include <cuda_runtime.h>
#include <cuda_bf16.h>
#include <cstdint>

// ---------------------------------------------------------------------------
// SAGESparseLayer:
//   feat_n[e]   = feature[src[e]] * rw[e]                (E x 128)
//   seg_sum[n]  = sum_{e: dst[e]==n} feat_n[e]
//   cnt[n]      = #edges into n
//   mean[n]     = seg_sum[n] / max(cnt[n], 1)
//   out[n]      = [feature[n], mean[n]] @ W + b          (N x 128)
//
// Inputs (metadata order):
//   d_in[0] feature  f32 [N,128]
//   d_in[1] rw       f32 [E,1]
//   d_in[2] W        f32 [256,128]
//   d_in[3] b        f32 [128]
//   d_in[4] rel_idx  i32 [2,E]  (row0=dst, row1=src)
// ---------------------------------------------------------------------------

#define D_FEAT   128
#define OUT_DIM  128
#define MAX_NODES 131072

static __device__ __align__(16) float g_segsum[(size_t)MAX_NODES * D_FEAT];
static __device__ int   g_cnt[MAX_NODES];

// ---------------------------------------------------------------------------
// Kernel 1: zero the accumulators
// ---------------------------------------------------------------------------
__global__ void zero_kernel(int n_nodes) {
    size_t total4 = (size_t)n_nodes * D_FEAT / 4;   // float4 count
    size_t idx = (size_t)blockIdx.x * blockDim.x + threadIdx.x;
    size_t stride = (size_t)gridDim.x * blockDim.x;
    float4 z = make_float4(0.f, 0.f, 0.f, 0.f);
    float4* s4 = reinterpret_cast<float4*>(g_segsum);
    for (size_t i = idx; i < total4; i += stride) s4[i] = z;
    for (size_t i = idx; i < (size_t)n_nodes; i += stride) g_cnt[i] = 0;
}

// ---------------------------------------------------------------------------
// Kernel 2: edge scatter. One warp per edge. Lane l handles floats [4l..4l+3].
// Vector reduction (red.global.add.v4.f32) -> REDG.128, no return value.
// ---------------------------------------------------------------------------
__global__ void __launch_bounds__(256) edge_kernel(
    const float* __restrict__ feat,
    const float* __restrict__ rw,
    const int*   __restrict__ rel_idx,
    int E)
{
    int gtid = blockIdx.x * blockDim.x + threadIdx.x;
    int warp = gtid >> 5;
    int lane = gtid & 31;
    if (warp >= E) return;

    int dst = __ldg(&rel_idx[warp]);       // row 0
    int src = __ldg(&rel_idx[E + warp]);   // row 1
    float w = __ldg(&rw[warp]);

    const float4 f = *reinterpret_cast<const float4*>(
        &feat[(size_t)src * D_FEAT + lane * 4]);
    float x = f.x * w, y = f.y * w, z = f.z * w, v = f.w * w;

    float* p = &g_segsum[(size_t)dst * D_FEAT + lane * 4];
    asm volatile("red.global.add.v4.f32 [%0], {%1, %2, %3, %4};"
                 :: "l"(p), "f"(x), "f"(y), "f"(z), "f"(v)
                 : "memory");
    if (lane == 0) atomicAdd(&g_cnt[dst], 1);
}

// ---------------------------------------------------------------------------
// Kernel 3: fused mean + concat + dense.
//   Block: 256 threads, 64-node tile, all 128 output cols.
//   smem: W [256][128] (128 KB) + h tile [64][256] (64 KB) = 192 KB.
//   Per-thread micro-tile: 8 rows x 4 cols; packed fma.rn.f32x2 over
//   adjacent output-column pairs (contiguous in W -> conflict-free LDS.128).
// ---------------------------------------------------------------------------
#define TILE_NODES 64
#define GEMM_THREADS 256
#define GEMM_SMEM (256 * 128 * 4 + TILE_NODES * 256 * 4)   // 196608 B

__global__ void __launch_bounds__(GEMM_THREADS, 1) gemm_kernel(
    const float* __restrict__ feat,
    const float* __restrict__ W,
    const float* __restrict__ b,
    float*       __restrict__ out,
    int N)
{
    extern __shared__ float smem[];
    float* Ws = smem;                 // [256][128]
    float* Hs = smem + 256 * 128;     // [64][256]

    const int tid  = threadIdx.x;
    const int wid  = tid >> 5;
    const int lane = tid & 31;
    const int tile = blockIdx.x * TILE_NODES;

    // --- stage W into smem (contiguous float4 copy) ---
    {
        const float4* Wg = reinterpret_cast<const float4*>(W);
        float4* Ws4 = reinterpret_cast<float4*>(Ws);
        #pragma unroll
        for (int i = tid; i < 256 * 128 / 4; i += GEMM_THREADS) Ws4[i] = Wg[i];
    }

    // --- stage h tile: [feature | segsum/max(cnt,1)] ---
    for (int r = wid; r < TILE_NODES; r += 8) {
        int node = tile + r;
        float4 fv = make_float4(0.f, 0.f, 0.f, 0.f);
        float4 sv = make_float4(0.f, 0.f, 0.f, 0.f);
        if (node < N) {
            fv = *reinterpret_cast<const float4*>(&feat[(size_t)node * D_FEAT + lane * 4]);
            float4 ss = *reinterpret_cast<const float4*>(&g_segsum[(size_t)node * D_FEAT + lane * 4]);
            float c = fmaxf((float)g_cnt[node], 1.0f);
            float inv = 1.0f / c;
            sv = make_float4(ss.x * inv, ss.y * inv, ss.z * inv, ss.w * inv);
        }
        *reinterpret_cast<float4*>(&Hs[r * 256 + lane * 4]) = fv;
        *reinterpret_cast<float4*>(&Hs[r * 256 + 128 + lane * 4]) = sv;
    }
    __syncthreads();

    // --- register-blocked GEMM: rows r0..r0+7, cols col..col+3 ---
    const int r0  = wid * 8;
    const int col = lane * 4;

    unsigned long long acc[8][2];
    #pragma unroll
    for (int r = 0; r < 8; r++) { acc[r][0] = 0ull; acc[r][1] = 0ull; }

    #pragma unroll 1
    for (int k0 = 0; k0 < 256; k0 += 4) {
        float ha[8][4];
        #pragma unroll
        for (int r = 0; r < 8; r++) {
            float4 hv = *reinterpret_cast<const float4*>(&Hs[(r0 + r) * 256 + k0]);
            ha[r][0] = hv.x; ha[r][1] = hv.y; ha[r][2] = hv.z; ha[r][3] = hv.w;
        }
        #pragma unroll
        for (int kk = 0; kk < 4; kk++) {
            // W row k, column pair (col,col+1) and (col+2,col+3): contiguous 16 B
            const ulonglong2 wv = *reinterpret_cast<const ulonglong2*>(
                &Ws[(k0 + kk) * 128 + col]);
            #pragma unroll
            for (int r = 0; r < 8; r++) {
                unsigned long long hh;
                unsigned int hu = __float_as_uint(ha[r][kk]);
                asm("mov.b64 %0, {%1, %1};" : "=l"(hh) : "r"(hu));
                asm("fma.rn.f32x2 %0, %1, %2, %0;" : "+l"(acc[r][0]) : "l"(hh), "l"(wv.x));
                asm("fma.rn.f32x2 %0, %1, %2, %0;" : "+l"(acc[r][1]) : "l"(hh), "l"(wv.y));
            }
        }
    }

    // --- epilogue: unpack pairs, add bias, vector store ---
    const float4 bias = *reinterpret_cast<const float4*>(&b[col]);
    #pragma unroll
    for (int r = 0; r < 8; r++) {
        int node = tile + r0 + r;
        if (node < N) {
            unsigned int l0, h0, l1, h1;
            asm("mov.b64 {%0, %1}, %2;" : "=r"(l0), "=r"(h0) : "l"(acc[r][0]));
            asm("mov.b64 {%0, %1}, %2;" : "=r"(l1), "=r"(h1) : "l"(acc[r][1]));
            float4 o;
            o.x = __uint_as_float(l0) + bias.x;
            o.y = __uint_as_float(h0) + bias.y;
            o.z = __uint_as_float(l1) + bias.z;
            o.w = __uint_as_float(h1) + bias.w;
            *reinterpret_cast<float4*>(&out[(size_t)node * OUT_DIM + col]) = o;
        }
    }
}

// ---------------------------------------------------------------------------
// Launch
// ---------------------------------------------------------------------------
extern "C" void kernel_launch(void* const* d_in, const int* in_sizes, int n_in,
                              void* d_out, int out_size)
{
    const float* feat    = (const float*)d_in[0];
    const float* rw      = (const float*)d_in[1];
    const float* W       = (const float*)d_in[2];
    const float* b       = (const float*)d_in[3];
    const int*   rel_idx = (const int*)d_in[4];

    const int N = in_sizes[0] / D_FEAT;
    const int E = in_sizes[1];
    float* out = (float*)d_out;

    // 1. zero accumulators
    zero_kernel<<<1024, 256>>>(N);

    // 2. edge scatter: one warp per edge
    {
        int warps_per_block = 256 / 32;
        int blocks = (E + warps_per_block - 1) / warps_per_block;
        edge_kernel<<<blocks, 256>>>(feat, rw, rel_idx, E);
    }

    // 3. fused mean/concat/dense
    {
        static bool attr_set = false;
        // setting the attribute is idempotent and not a stream op; do it every call
        cudaFuncSetAttribute(gemm_kernel,
                             cudaFuncAttributeMaxDynamicSharedMemorySize,
                             GEMM_SMEM);
        (void)attr_set;
        int blocks = (N + TILE_NODES - 1) / TILE_NODES;
        gemm_kernel<<<blocks, GEMM_THREADS, GEMM_SMEM>>>(feat, W, b, out, N);
    }
}

// round 2
// speedup vs baseline: 1.1253x; 1.1253x over previous
#include <cuda_runtime.h>
#include <cuda_bf16.h>
#include <cstdint>

// ---------------------------------------------------------------------------
// SAGESparseLayer, CSR-sorted edge aggregation version.
//
//   mean[n] = (1/max(deg(n),1)) * sum_{e: dst[e]==n} feature[src[e]] * rw[e]
//   out[n]  = [feature[n], mean[n]] @ W + b
//
// Pipeline:
//   1. zero_cnt           : g_cnt = 0
//   2. hist_kernel        : g_cnt[dst[e]]++          (atomic int)
//   3. scan1/scan2/scan3  : g_rowstart = exclusive_scan(g_cnt); g_cursor copy
//   4. scatter_kernel     : CSR bucket fill of {src, w} per edge
//   5. agg_kernel         : warp per node, register accumulate, write mean
//   6. gemm_kernel        : fused concat + dense, packed fma.rn.f32x2
//
// Inputs (metadata order):
//   d_in[0] feature  f32 [N,128]
//   d_in[1] rw       f32 [E,1]
//   d_in[2] W        f32 [256,128]
//   d_in[3] b        f32 [128]
//   d_in[4] rel_idx  i32 [2,E]  (row0=dst, row1=src)
// ---------------------------------------------------------------------------

#define D_FEAT    128
#define OUT_DIM   128
#define MAX_NODES 131072
#define MAX_EDGES (1 << 20)
#define SCAN_BLOCK 1024
#define MAX_SCAN_BLOCKS 256

static __device__ __align__(16) float g_mean[(size_t)MAX_NODES * D_FEAT];
static __device__ int  g_cnt[MAX_NODES];
static __device__ int  g_rowstart[MAX_NODES + 1];
static __device__ int  g_cursor[MAX_NODES];
static __device__ int  g_blocksum[MAX_SCAN_BLOCKS];
static __device__ __align__(8) int2 g_edges[MAX_EDGES];

// ---------------------------------------------------------------------------
// 1. zero counters
// ---------------------------------------------------------------------------
__global__ void zero_cnt_kernel(int N) {
    int i = blockIdx.x * blockDim.x + threadIdx.x;
    int stride = gridDim.x * blockDim.x;
    for (; i < N; i += stride) g_cnt[i] = 0;
}

// ---------------------------------------------------------------------------
// 2. histogram of destination ids
// ---------------------------------------------------------------------------
__global__ void hist_kernel(const int* __restrict__ rel_idx, int E) {
    int e = blockIdx.x * blockDim.x + threadIdx.x;
    if (e < E) atomicAdd(&g_cnt[rel_idx[e]], 1);
}

// ---------------------------------------------------------------------------
// 3. exclusive scan of g_cnt -> g_rowstart (3 kernels)
// ---------------------------------------------------------------------------
__global__ void __launch_bounds__(SCAN_BLOCK) scan1_kernel(int N) {
    __shared__ int warpsums[SCAN_BLOCK / 32];
    int t = threadIdx.x;
    int i = blockIdx.x * SCAN_BLOCK + t;
    int v = (i < N) ? g_cnt[i] : 0;

    // warp inclusive scan
    int x = v;
    #pragma unroll
    for (int o = 1; o < 32; o <<= 1) {
        int y = __shfl_up_sync(0xffffffffu, x, o);
        if ((t & 31) >= o) x += y;
    }
    if ((t & 31) == 31) warpsums[t >> 5] = x;
    __syncthreads();
    if (t < 32) {
        int w = (t < SCAN_BLOCK / 32) ? warpsums[t] : 0;
        int xx = w;
        #pragma unroll
        for (int o = 1; o < 32; o <<= 1) {
            int y = __shfl_up_sync(0xffffffffu, xx, o);
            if (t >= o) xx += y;
        }
        if (t < SCAN_BLOCK / 32) warpsums[t] = xx - w;   // exclusive warp offsets
    }
    __syncthreads();
    int excl = (x - v) + warpsums[t >> 5];
    if (i < N) g_rowstart[i] = excl;
    if (t == SCAN_BLOCK - 1) g_blocksum[blockIdx.x] = excl + v;  // block total
}

__global__ void scan2_kernel(int nb) {
    __shared__ int ws[8];
    int t = threadIdx.x;                     // blockDim = 256 >= nb
    int v = (t < nb) ? g_blocksum[t] : 0;
    int x = v;
    #pragma unroll
    for (int o = 1; o < 32; o <<= 1) {
        int y = __shfl_up_sync(0xffffffffu, x, o);
        if ((t & 31) >= o) x += y;
    }
    if ((t & 31) == 31) ws[t >> 5] = x;
    __syncthreads();
    if (t == 0) {
        int acc = 0;
        #pragma unroll
        for (int i = 0; i < 8; i++) { int tmp = ws[i]; ws[i] = acc; acc += tmp; }
    }
    __syncthreads();
    int excl = (x - v) + ws[t >> 5];
    if (t < nb) g_blocksum[t] = excl;
}

__global__ void __launch_bounds__(SCAN_BLOCK) scan3_kernel(int N, int E) {
    int i = blockIdx.x * SCAN_BLOCK + threadIdx.x;
    if (i < N) {
        int v = g_rowstart[i] + g_blocksum[blockIdx.x];
        g_rowstart[i] = v;
        g_cursor[i]   = v;
    }
    if (i == 0) g_rowstart[N] = E;
}

// ---------------------------------------------------------------------------
// 4. scatter edges into CSR buckets as {src, w_bits}
// ---------------------------------------------------------------------------
__global__ void scatter_kernel(const int* __restrict__ rel_idx,
                               const float* __restrict__ rw, int E) {
    int e = blockIdx.x * blockDim.x + threadIdx.x;
    if (e >= E) return;
    int dst = rel_idx[e];
    int src = rel_idx[E + e];
    float w = rw[e];
    int p = atomicAdd(&g_cursor[dst], 1);
    g_edges[p] = make_int2(src, __float_as_int(w));
}

// ---------------------------------------------------------------------------
// 5. per-node aggregation: one warp per node, register accumulate.
// ---------------------------------------------------------------------------
__global__ void __launch_bounds__(256) agg_kernel(const float* __restrict__ feat,
                                                  int N) {
    int warp = (blockIdx.x * 256 + threadIdx.x) >> 5;
    int lane = threadIdx.x & 31;
    if (warp >= N) return;

    int beg = g_rowstart[warp];
    int end = g_rowstart[warp + 1];

    float ax = 0.f, ay = 0.f, az = 0.f, aw = 0.f;
    int i = beg;
    #pragma unroll 1
    for (; i + 2 <= end; i += 2) {
        int2 e0 = g_edges[i];
        int2 e1 = g_edges[i + 1];
        const float4 f0 = *reinterpret_cast<const float4*>(
            &feat[(size_t)e0.x * D_FEAT + lane * 4]);
        const float4 f1 = *reinterpret_cast<const float4*>(
            &feat[(size_t)e1.x * D_FEAT + lane * 4]);
        float w0 = __int_as_float(e0.y);
        float w1 = __int_as_float(e1.y);
        ax = fmaf(f0.x, w0, ax); ay = fmaf(f0.y, w0, ay);
        az = fmaf(f0.z, w0, az); aw = fmaf(f0.w, w0, aw);
        ax = fmaf(f1.x, w1, ax); ay = fmaf(f1.y, w1, ay);
        az = fmaf(f1.z, w1, az); aw = fmaf(f1.w, w1, aw);
    }
    if (i < end) {
        int2 e0 = g_edges[i];
        const float4 f0 = *reinterpret_cast<const float4*>(
            &feat[(size_t)e0.x * D_FEAT + lane * 4]);
        float w0 = __int_as_float(e0.y);
        ax = fmaf(f0.x, w0, ax); ay = fmaf(f0.y, w0, ay);
        az = fmaf(f0.z, w0, az); aw = fmaf(f0.w, w0, aw);
    }

    int deg = end - beg;
    float inv = 1.0f / (float)(deg > 1 ? deg : 1);
    float4 o = make_float4(ax * inv, ay * inv, az * inv, aw * inv);
    *reinterpret_cast<float4*>(&g_mean[(size_t)warp * D_FEAT + lane * 4]) = o;
}

// ---------------------------------------------------------------------------
// 6. fused concat + dense GEMM (packed fma.rn.f32x2 over output-column pairs)
// ---------------------------------------------------------------------------
#define TILE_NODES 64
#define GEMM_THREADS 256
#define GEMM_SMEM (256 * 128 * 4 + TILE_NODES * 256 * 4)   // 196608 B

__global__ void __launch_bounds__(GEMM_THREADS, 1) gemm_kernel(
    const float* __restrict__ feat,
    const float* __restrict__ W,
    const float* __restrict__ b,
    float*       __restrict__ out,
    int N)
{
    extern __shared__ float smem[];
    float* Ws = smem;                 // [256][128]
    float* Hs = smem + 256 * 128;     // [64][256]

    const int tid  = threadIdx.x;
    const int wid  = tid >> 5;
    const int lane = tid & 31;
    const int tile = blockIdx.x * TILE_NODES;

    // --- stage W into smem ---
    {
        const float4* Wg = reinterpret_cast<const float4*>(W);
        float4* Ws4 = reinterpret_cast<float4*>(Ws);
        #pragma unroll
        for (int i = tid; i < 256 * 128 / 4; i += GEMM_THREADS) Ws4[i] = Wg[i];
    }

    // --- stage h tile: [feature | mean] ---
    for (int r = wid; r < TILE_NODES; r += 8) {
        int node = tile + r;
        float4 fv = make_float4(0.f, 0.f, 0.f, 0.f);
        float4 sv = make_float4(0.f, 0.f, 0.f, 0.f);
        if (node < N) {
            fv = *reinterpret_cast<const float4*>(&feat[(size_t)node * D_FEAT + lane * 4]);
            sv = *reinterpret_cast<const float4*>(&g_mean[(size_t)node * D_FEAT + lane * 4]);
        }
        *reinterpret_cast<float4*>(&Hs[r * 256 + lane * 4]) = fv;
        *reinterpret_cast<float4*>(&Hs[r * 256 + 128 + lane * 4]) = sv;
    }
    __syncthreads();

    // --- register-blocked GEMM: rows r0..r0+7, cols col..col+3 ---
    const int r0  = wid * 8;
    const int col = lane * 4;

    unsigned long long acc[8][2];
    #pragma unroll
    for (int r = 0; r < 8; r++) { acc[r][0] = 0ull; acc[r][1] = 0ull; }

    #pragma unroll 1
    for (int k0 = 0; k0 < 256; k0 += 4) {
        float ha[8][4];
        #pragma unroll
        for (int r = 0; r < 8; r++) {
            float4 hv = *reinterpret_cast<const float4*>(&Hs[(r0 + r) * 256 + k0]);
            ha[r][0] = hv.x; ha[r][1] = hv.y; ha[r][2] = hv.z; ha[r][3] = hv.w;
        }
        #pragma unroll
        for (int kk = 0; kk < 4; kk++) {
            const ulonglong2 wv = *reinterpret_cast<const ulonglong2*>(
                &Ws[(k0 + kk) * 128 + col]);
            #pragma unroll
            for (int r = 0; r < 8; r++) {
                unsigned long long hh;
                unsigned int hu = __float_as_uint(ha[r][kk]);
                asm("mov.b64 %0, {%1, %1};" : "=l"(hh) : "r"(hu));
                asm("fma.rn.f32x2 %0, %1, %2, %0;" : "+l"(acc[r][0]) : "l"(hh), "l"(wv.x));
                asm("fma.rn.f32x2 %0, %1, %2, %0;" : "+l"(acc[r][1]) : "l"(hh), "l"(wv.y));
            }
        }
    }

    // --- epilogue: unpack pairs, add bias, vector store ---
    const float4 bias = *reinterpret_cast<const float4*>(&b[col]);
    #pragma unroll
    for (int r = 0; r < 8; r++) {
        int node = tile + r0 + r;
        if (node < N) {
            unsigned int l0, h0, l1, h1;
            asm("mov.b64 {%0, %1}, %2;" : "=r"(l0), "=r"(h0) : "l"(acc[r][0]));
            asm("mov.b64 {%0, %1}, %2;" : "=r"(l1), "=r"(h1) : "l"(acc[r][1]));
            float4 o;
            o.x = __uint_as_float(l0) + bias.x;
            o.y = __uint_as_float(h0) + bias.y;
            o.z = __uint_as_float(l1) + bias.z;
            o.w = __uint_as_float(h1) + bias.w;
            *reinterpret_cast<float4*>(&out[(size_t)node * OUT_DIM + col]) = o;
        }
    }
}

// ---------------------------------------------------------------------------
// Launch
// ---------------------------------------------------------------------------
extern "C" void kernel_launch(void* const* d_in, const int* in_sizes, int n_in,
                              void* d_out, int out_size)
{
    const float* feat    = (const float*)d_in[0];
    const float* rw      = (const float*)d_in[1];
    const float* W       = (const float*)d_in[2];
    const float* b       = (const float*)d_in[3];
    const int*   rel_idx = (const int*)d_in[4];

    const int N = in_sizes[0] / D_FEAT;
    const int E = in_sizes[1];
    float* out = (float*)d_out;

    // 1. zero counters
    zero_cnt_kernel<<<128, 256>>>(N);

    // 2. histogram
    hist_kernel<<<(E + 255) / 256, 256>>>(rel_idx, E);

    // 3. scan
    int nb = (N + SCAN_BLOCK - 1) / SCAN_BLOCK;
    scan1_kernel<<<nb, SCAN_BLOCK>>>(N);
    scan2_kernel<<<1, 256>>>(nb);
    scan3_kernel<<<nb, SCAN_BLOCK>>>(N, E);

    // 4. scatter into CSR
    scatter_kernel<<<(E + 255) / 256, 256>>>(rel_idx, rw, E);

    // 5. per-node aggregate (one warp per node)
    agg_kernel<<<(N * 32 + 255) / 256, 256>>>(feat, N);

    // 6. fused concat + dense
    cudaFuncSetAttribute(gemm_kernel,
                         cudaFuncAttributeMaxDynamicSharedMemorySize,
                         GEMM_SMEM);
    gemm_kernel<<<(N + TILE_NODES - 1) / TILE_NODES, GEMM_THREADS, GEMM_SMEM>>>(
        feat, W, b, out, N);
}

// round 4
// speedup vs baseline: 1.3938x; 1.2385x over previous
#include <cuda_runtime.h>
#include <cuda_bf16.h>
#include <cstdint>

// ---------------------------------------------------------------------------
// SAGESparseLayer: CSR edge aggregation + tf32 mma.sync GEMM (sm_100-safe).
//
//   mean[n] = (1/max(deg(n),1)) * sum_{e: dst[e]==n} feature[src[e]] * rw[e]
//   out[n]  = [feature[n], mean[n]] @ W + b
// ---------------------------------------------------------------------------

#define D_FEAT    128
#define OUT_DIM   128
#define MAX_NODES 131072
#define MAX_EDGES (1 << 20)
#define SCAN_BLOCK 1024
#define MAX_SCAN_BLOCKS 256

static __device__ __align__(16) float g_mean[(size_t)MAX_NODES * D_FEAT];
static __device__ int  g_cnt[MAX_NODES];
static __device__ int  g_rowstart[MAX_NODES + 1];
static __device__ int  g_cursor[MAX_NODES];
static __device__ int  g_blocksum[MAX_SCAN_BLOCKS];
static __device__ __align__(8) int2 g_edges[MAX_EDGES];

// ---------------------------------------------------------------------------
// 1. zero counters
// ---------------------------------------------------------------------------
__global__ void zero_cnt_kernel(int N) {
    int i = blockIdx.x * blockDim.x + threadIdx.x;
    int stride = gridDim.x * blockDim.x;
    for (; i < N; i += stride) g_cnt[i] = 0;
}

// ---------------------------------------------------------------------------
// 2. histogram of destination ids
// ---------------------------------------------------------------------------
__global__ void hist_kernel(const int* __restrict__ rel_idx, int E) {
    int e = blockIdx.x * blockDim.x + threadIdx.x;
    if (e < E) atomicAdd(&g_cnt[rel_idx[e]], 1);
}

// ---------------------------------------------------------------------------
// 3. exclusive scan of g_cnt -> g_rowstart
// ---------------------------------------------------------------------------
__global__ void __launch_bounds__(SCAN_BLOCK) scan1_kernel(int N) {
    __shared__ int warpsums[SCAN_BLOCK / 32];
    int t = threadIdx.x;
    int i = blockIdx.x * SCAN_BLOCK + t;
    int v = (i < N) ? g_cnt[i] : 0;
    int x = v;
    #pragma unroll
    for (int o = 1; o < 32; o <<= 1) {
        int y = __shfl_up_sync(0xffffffffu, x, o);
        if ((t & 31) >= o) x += y;
    }
    if ((t & 31) == 31) warpsums[t >> 5] = x;
    __syncthreads();
    if (t < 32) {
        int w = (t < SCAN_BLOCK / 32) ? warpsums[t] : 0;
        int xx = w;
        #pragma unroll
        for (int o = 1; o < 32; o <<= 1) {
            int y = __shfl_up_sync(0xffffffffu, xx, o);
            if (t >= o) xx += y;
        }
        if (t < SCAN_BLOCK / 32) warpsums[t] = xx - w;
    }
    __syncthreads();
    int excl = (x - v) + warpsums[t >> 5];
    if (i < N) g_rowstart[i] = excl;
    if (t == SCAN_BLOCK - 1) g_blocksum[blockIdx.x] = excl + v;
}

__global__ void scan2_kernel(int nb) {
    __shared__ int ws[8];
    int t = threadIdx.x;
    int v = (t < nb) ? g_blocksum[t] : 0;
    int x = v;
    #pragma unroll
    for (int o = 1; o < 32; o <<= 1) {
        int y = __shfl_up_sync(0xffffffffu, x, o);
        if ((t & 31) >= o) x += y;
    }
    if ((t & 31) == 31) ws[t >> 5] = x;
    __syncthreads();
    if (t == 0) {
        int acc = 0;
        #pragma unroll
        for (int i = 0; i < 8; i++) { int tmp = ws[i]; ws[i] = acc; acc += tmp; }
    }
    __syncthreads();
    int excl = (x - v) + ws[t >> 5];
    if (t < nb) g_blocksum[t] = excl;
}

__global__ void __launch_bounds__(SCAN_BLOCK) scan3_kernel(int N, int E) {
    int i = blockIdx.x * SCAN_BLOCK + threadIdx.x;
    if (i < N) {
        int v = g_rowstart[i] + g_blocksum[blockIdx.x];
        g_rowstart[i] = v;
        g_cursor[i]   = v;
    }
    if (i == 0) g_rowstart[N] = E;
}

// ---------------------------------------------------------------------------
// 4. scatter edges into CSR buckets as {src, w_bits}
// ---------------------------------------------------------------------------
__global__ void scatter_kernel(const int* __restrict__ rel_idx,
                               const float* __restrict__ rw, int E) {
    int e = blockIdx.x * blockDim.x + threadIdx.x;
    if (e >= E) return;
    int dst = rel_idx[e];
    int src = rel_idx[E + e];
    float w = rw[e];
    int p = atomicAdd(&g_cursor[dst], 1);
    g_edges[p] = make_int2(src, __float_as_int(w));
}

// ---------------------------------------------------------------------------
// 5. per-node aggregation: one warp per node, register accumulate.
// ---------------------------------------------------------------------------
__global__ void __launch_bounds__(256) agg_kernel(const float* __restrict__ feat,
                                                  int N) {
    int warp = (blockIdx.x * 256 + threadIdx.x) >> 5;
    int lane = threadIdx.x & 31;
    if (warp >= N) return;

    int beg = g_rowstart[warp];
    int end = g_rowstart[warp + 1];

    float ax = 0.f, ay = 0.f, az = 0.f, aw = 0.f;
    int i = beg;
    #pragma unroll 1
    for (; i + 4 <= end; i += 4) {
        int2 e0 = g_edges[i];
        int2 e1 = g_edges[i + 1];
        int2 e2 = g_edges[i + 2];
        int2 e3 = g_edges[i + 3];
        const float4 f0 = *reinterpret_cast<const float4*>(&feat[(size_t)e0.x * D_FEAT + lane * 4]);
        const float4 f1 = *reinterpret_cast<const float4*>(&feat[(size_t)e1.x * D_FEAT + lane * 4]);
        const float4 f2 = *reinterpret_cast<const float4*>(&feat[(size_t)e2.x * D_FEAT + lane * 4]);
        const float4 f3 = *reinterpret_cast<const float4*>(&feat[(size_t)e3.x * D_FEAT + lane * 4]);
        float w0 = __int_as_float(e0.y), w1 = __int_as_float(e1.y);
        float w2 = __int_as_float(e2.y), w3 = __int_as_float(e3.y);
        ax = fmaf(f0.x, w0, ax); ay = fmaf(f0.y, w0, ay);
        az = fmaf(f0.z, w0, az); aw = fmaf(f0.w, w0, aw);
        ax = fmaf(f1.x, w1, ax); ay = fmaf(f1.y, w1, ay);
        az = fmaf(f1.z, w1, az); aw = fmaf(f1.w, w1, aw);
        ax = fmaf(f2.x, w2, ax); ay = fmaf(f2.y, w2, ay);
        az = fmaf(f2.z, w2, az); aw = fmaf(f2.w, w2, aw);
        ax = fmaf(f3.x, w3, ax); ay = fmaf(f3.y, w3, ay);
        az = fmaf(f3.z, w3, az); aw = fmaf(f3.w, w3, aw);
    }
    for (; i < end; i++) {
        int2 e0 = g_edges[i];
        const float4 f0 = *reinterpret_cast<const float4*>(&feat[(size_t)e0.x * D_FEAT + lane * 4]);
        float w0 = __int_as_float(e0.y);
        ax = fmaf(f0.x, w0, ax); ay = fmaf(f0.y, w0, ay);
        az = fmaf(f0.z, w0, az); aw = fmaf(f0.w, w0, aw);
    }

    int deg = end - beg;
    float inv = 1.0f / (float)(deg > 1 ? deg : 1);
    float4 o = make_float4(ax * inv, ay * inv, az * inv, aw * inv);
    *reinterpret_cast<float4*>(&g_mean[(size_t)warp * D_FEAT + lane * 4]) = o;
}

// ---------------------------------------------------------------------------
// 6. tf32 mma.sync GEMM: out[128-tile][128] = [feat|mean] @ W + b
//    256 threads (8 warps), warp w -> rows [16w, 16w+16), all 128 cols.
//    K processed in two 128-halves (feature | mean); smem restaged per half.
//    Hs stride 132 floats (A-frag conflict-free), Ws stride 136 (B-frag c-f).
// ---------------------------------------------------------------------------
#define GEMM_THREADS 256
#define HS_STRIDE 132
#define WS_STRIDE 136
#define HS_WORDS (128 * HS_STRIDE)
#define WS_WORDS (128 * WS_STRIDE)
#define GEMM_SMEM ((HS_WORDS + WS_WORDS) * 4)   // 137216 B

__device__ __forceinline__ uint32_t f2tf32(float f) {
    uint32_t r;
    asm("cvt.rna.tf32.f32 %0, %1;" : "=r"(r) : "f"(f));
    return r;
}

__device__ __forceinline__ void mma_tf32(float& c0, float& c1, float& c2, float& c3,
                                         uint32_t a0, uint32_t a1, uint32_t a2, uint32_t a3,
                                         uint32_t b0, uint32_t b1) {
    asm volatile(
        "mma.sync.aligned.m16n8k8.row.col.f32.tf32.tf32.f32 "
        "{%0,%1,%2,%3}, {%4,%5,%6,%7}, {%8,%9}, {%0,%1,%2,%3};"
        : "+f"(c0), "+f"(c1), "+f"(c2), "+f"(c3)
        : "r"(a0), "r"(a1), "r"(a2), "r"(a3), "r"(b0), "r"(b1));
}

__global__ void __launch_bounds__(GEMM_THREADS, 1) gemm_kernel(
    const float* __restrict__ feat,
    const float* __restrict__ W,
    const float* __restrict__ b,
    float*       __restrict__ out,
    int N)
{
    extern __shared__ uint32_t smem[];
    uint32_t* Hs = smem;              // [128][HS_STRIDE] tf32
    uint32_t* Ws = smem + HS_WORDS;   // [128][WS_STRIDE] tf32

    const int tid  = threadIdx.x;
    const int wid  = tid >> 5;
    const int lane = tid & 31;
    const int gid  = lane >> 2;       // groupID 0..7
    const int tig  = lane & 3;        // threadID in group 0..3
    const int tile = blockIdx.x * 128;

    float acc[16][4];
    #pragma unroll
    for (int nt = 0; nt < 16; nt++)
        #pragma unroll
        for (int q = 0; q < 4; q++) acc[nt][q] = 0.f;

    const int wrow = wid * 16;        // warp's first row in tile

    #pragma unroll 1
    for (int half = 0; half < 2; half++) {
        // --- stage W half: k in [half*128, half*128+128), W[k][n] ---
        #pragma unroll
        for (int idx = tid; idx < 128 * 128; idx += GEMM_THREADS) {
            int k = idx >> 7;
            int n = idx & 127;
            Ws[k * WS_STRIDE + n] = f2tf32(W[(half * 128 + k) * OUT_DIM + n]);
        }
        // --- stage H half: row r <- feat/mean[tile+r][0..128) ---
        #pragma unroll
        for (int idx4 = tid; idx4 < 128 * 32; idx4 += GEMM_THREADS) {
            int r = idx4 >> 5;
            int j = idx4 & 31;
            int node = tile + r;
            float4 v = make_float4(0.f, 0.f, 0.f, 0.f);
            if (node < N) {
                const float* srcp = (half == 0)
                    ? &feat[(size_t)node * D_FEAT]
                    : &g_mean[(size_t)node * D_FEAT];
                v = *reinterpret_cast<const float4*>(srcp + j * 4);
            }
            uint32_t* dp = &Hs[r * HS_STRIDE + j * 4];
            dp[0] = f2tf32(v.x); dp[1] = f2tf32(v.y);
            dp[2] = f2tf32(v.z); dp[3] = f2tf32(v.w);
        }
        __syncthreads();

        // --- MMA: 16 k-steps of 8 ---
        #pragma unroll 1
        for (int k0 = 0; k0 < 128; k0 += 8) {
            uint32_t a0 = Hs[(wrow + gid)     * HS_STRIDE + k0 + tig];
            uint32_t a1 = Hs[(wrow + gid + 8) * HS_STRIDE + k0 + tig];
            uint32_t a2 = Hs[(wrow + gid)     * HS_STRIDE + k0 + tig + 4];
            uint32_t a3 = Hs[(wrow + gid + 8) * HS_STRIDE + k0 + tig + 4];
            #pragma unroll
            for (int nt = 0; nt < 16; nt++) {
                uint32_t b0 = Ws[(k0 + tig)     * WS_STRIDE + nt * 8 + gid];
                uint32_t b1 = Ws[(k0 + tig + 4) * WS_STRIDE + nt * 8 + gid];
                mma_tf32(acc[nt][0], acc[nt][1], acc[nt][2], acc[nt][3],
                         a0, a1, a2, a3, b0, b1);
            }
        }
        __syncthreads();   // protect smem before restaging next half
    }

    // --- epilogue: bias + store ---
    int row0 = tile + wrow + gid;
    int row1 = row0 + 8;
    #pragma unroll
    for (int nt = 0; nt < 16; nt++) {
        int col = nt * 8 + tig * 2;
        float2 bi = *reinterpret_cast<const float2*>(&b[col]);
        if (row0 < N) {
            float2 o = make_float2(acc[nt][0] + bi.x, acc[nt][1] + bi.y);
            *reinterpret_cast<float2*>(&out[(size_t)row0 * OUT_DIM + col]) = o;
        }
        if (row1 < N) {
            float2 o = make_float2(acc[nt][2] + bi.x, acc[nt][3] + bi.y);
            *reinterpret_cast<float2*>(&out[(size_t)row1 * OUT_DIM + col]) = o;
        }
    }
}

// ---------------------------------------------------------------------------
// Launch
// ---------------------------------------------------------------------------
extern "C" void kernel_launch(void* const* d_in, const int* in_sizes, int n_in,
                              void* d_out, int out_size)
{
    const float* feat    = (const float*)d_in[0];
    const float* rw      = (const float*)d_in[1];
    const float* W       = (const float*)d_in[2];
    const float* b       = (const float*)d_in[3];
    const int*   rel_idx = (const int*)d_in[4];

    const int N = in_sizes[0] / D_FEAT;
    const int E = in_sizes[1];
    float* out = (float*)d_out;

    zero_cnt_kernel<<<128, 256>>>(N);
    hist_kernel<<<(E + 255) / 256, 256>>>(rel_idx, E);

    int nb = (N + SCAN_BLOCK - 1) / SCAN_BLOCK;
    scan1_kernel<<<nb, SCAN_BLOCK>>>(N);
    scan2_kernel<<<1, 256>>>(nb);
    scan3_kernel<<<nb, SCAN_BLOCK>>>(N, E);

    scatter_kernel<<<(E + 255) / 256, 256>>>(rel_idx, rw, E);
    agg_kernel<<<(N * 32 + 255) / 256, 256>>>(feat, N);

    cudaFuncSetAttribute(gemm_kernel,
                         cudaFuncAttributeMaxDynamicSharedMemorySize, GEMM_SMEM);
    int blocks = (N + 127) / 128;
    gemm_kernel<<<blocks, GEMM_THREADS, GEMM_SMEM>>>(feat, W, b, out, N);
}

// round 5
// speedup vs baseline: 1.4608x; 1.0481x over previous
#include <cuda_runtime.h>
#include <cuda_bf16.h>
#include <cuda_fp16.h>
#include <cstdint>

// ---------------------------------------------------------------------------
// SAGESparseLayer: CSR edge aggregation (fp16 gather) + persistent tf32 GEMM.
//
//   mean[n] = (1/max(deg(n),1)) * sum_{e: dst[e]==n} feature[src[e]] * rw[e]
//   out[n]  = [feature[n], mean[n]] @ W + b
// ---------------------------------------------------------------------------

#define D_FEAT    128
#define OUT_DIM   128
#define MAX_NODES 131072
#define MAX_EDGES (1 << 20)
#define SCAN_BLOCK 1024
#define MAX_SCAN_BLOCKS 256

static __device__ __align__(16) float g_mean[(size_t)MAX_NODES * D_FEAT];
static __device__ __align__(16) uint2 g_feat16[(size_t)MAX_NODES * 32];  // fp16 feat
static __device__ int  g_cnt[MAX_NODES];
static __device__ int  g_rowstart[MAX_NODES + 1];
static __device__ int  g_cursor[MAX_NODES];
static __device__ int  g_blocksum[MAX_SCAN_BLOCKS];
static __device__ __align__(8) int2 g_edges[MAX_EDGES];

// ---------------------------------------------------------------------------
// 1. init: zero counters + convert feature table to fp16
// ---------------------------------------------------------------------------
__global__ void init_kernel(const float* __restrict__ feat, int N) {
    int idx = blockIdx.x * blockDim.x + threadIdx.x;
    int stride = gridDim.x * blockDim.x;
    for (int i = idx; i < N; i += stride) g_cnt[i] = 0;
    const float4* f4 = reinterpret_cast<const float4*>(feat);
    int total = N * 32;
    for (int i = idx; i < total; i += stride) {
        float4 v = f4[i];
        __half2 a = __floats2half2_rn(v.x, v.y);
        __half2 c = __floats2half2_rn(v.z, v.w);
        uint2 o;
        o.x = *reinterpret_cast<uint32_t*>(&a);
        o.y = *reinterpret_cast<uint32_t*>(&c);
        g_feat16[i] = o;
    }
}

// ---------------------------------------------------------------------------
// 2. histogram of destination ids
// ---------------------------------------------------------------------------
__global__ void hist_kernel(const int* __restrict__ rel_idx, int E) {
    int e = blockIdx.x * blockDim.x + threadIdx.x;
    if (e < E) atomicAdd(&g_cnt[rel_idx[e]], 1);
}

// ---------------------------------------------------------------------------
// 3. exclusive scan of g_cnt -> g_rowstart
// ---------------------------------------------------------------------------
__global__ void __launch_bounds__(SCAN_BLOCK) scan1_kernel(int N) {
    __shared__ int warpsums[SCAN_BLOCK / 32];
    int t = threadIdx.x;
    int i = blockIdx.x * SCAN_BLOCK + t;
    int v = (i < N) ? g_cnt[i] : 0;
    int x = v;
    #pragma unroll
    for (int o = 1; o < 32; o <<= 1) {
        int y = __shfl_up_sync(0xffffffffu, x, o);
        if ((t & 31) >= o) x += y;
    }
    if ((t & 31) == 31) warpsums[t >> 5] = x;
    __syncthreads();
    if (t < 32) {
        int w = (t < SCAN_BLOCK / 32) ? warpsums[t] : 0;
        int xx = w;
        #pragma unroll
        for (int o = 1; o < 32; o <<= 1) {
            int y = __shfl_up_sync(0xffffffffu, xx, o);
            if (t >= o) xx += y;
        }
        if (t < SCAN_BLOCK / 32) warpsums[t] = xx - w;
    }
    __syncthreads();
    int excl = (x - v) + warpsums[t >> 5];
    if (i < N) g_rowstart[i] = excl;
    if (t == SCAN_BLOCK - 1) g_blocksum[blockIdx.x] = excl + v;
}

__global__ void scan2_kernel(int nb) {
    __shared__ int ws[8];
    int t = threadIdx.x;
    int v = (t < nb) ? g_blocksum[t] : 0;
    int x = v;
    #pragma unroll
    for (int o = 1; o < 32; o <<= 1) {
        int y = __shfl_up_sync(0xffffffffu, x, o);
        if ((t & 31) >= o) x += y;
    }
    if ((t & 31) == 31) ws[t >> 5] = x;
    __syncthreads();
    if (t == 0) {
        int acc = 0;
        #pragma unroll
        for (int i = 0; i < 8; i++) { int tmp = ws[i]; ws[i] = acc; acc += tmp; }
    }
    __syncthreads();
    int excl = (x - v) + ws[t >> 5];
    if (t < nb) g_blocksum[t] = excl;
}

__global__ void __launch_bounds__(SCAN_BLOCK) scan3_kernel(int N, int E) {
    int i = blockIdx.x * SCAN_BLOCK + threadIdx.x;
    if (i < N) {
        int v = g_rowstart[i] + g_blocksum[blockIdx.x];
        g_rowstart[i] = v;
        g_cursor[i]   = v;
    }
    if (i == 0) g_rowstart[N] = E;
}

// ---------------------------------------------------------------------------
// 4. scatter edges into CSR buckets as {src, w_bits}
// ---------------------------------------------------------------------------
__global__ void scatter_kernel(const int* __restrict__ rel_idx,
                               const float* __restrict__ rw, int E) {
    int e = blockIdx.x * blockDim.x + threadIdx.x;
    if (e >= E) return;
    int dst = rel_idx[e];
    int src = rel_idx[E + e];
    float w = rw[e];
    int p = atomicAdd(&g_cursor[dst], 1);
    g_edges[p] = make_int2(src, __float_as_int(w));
}

// ---------------------------------------------------------------------------
// 5. per-node aggregation: one warp per node, fp16 gather, fp32 accumulate.
// ---------------------------------------------------------------------------
__global__ void __launch_bounds__(256) agg_kernel(int N) {
    int warp = (blockIdx.x * 256 + threadIdx.x) >> 5;
    int lane = threadIdx.x & 31;
    if (warp >= N) return;

    int beg = g_rowstart[warp];
    int end = g_rowstart[warp + 1];

    float ax = 0.f, ay = 0.f, az = 0.f, aw = 0.f;
    int i = beg;
    #pragma unroll 1
    for (; i + 4 <= end; i += 4) {
        int2 e0 = g_edges[i];
        int2 e1 = g_edges[i + 1];
        int2 e2 = g_edges[i + 2];
        int2 e3 = g_edges[i + 3];
        uint2 u0 = g_feat16[(size_t)e0.x * 32 + lane];
        uint2 u1 = g_feat16[(size_t)e1.x * 32 + lane];
        uint2 u2 = g_feat16[(size_t)e2.x * 32 + lane];
        uint2 u3 = g_feat16[(size_t)e3.x * 32 + lane];
        float w0 = __int_as_float(e0.y), w1 = __int_as_float(e1.y);
        float w2 = __int_as_float(e2.y), w3 = __int_as_float(e3.y);
        {
            float2 p = __half22float2(*reinterpret_cast<__half2*>(&u0.x));
            float2 q = __half22float2(*reinterpret_cast<__half2*>(&u0.y));
            ax = fmaf(p.x, w0, ax); ay = fmaf(p.y, w0, ay);
            az = fmaf(q.x, w0, az); aw = fmaf(q.y, w0, aw);
        }
        {
            float2 p = __half22float2(*reinterpret_cast<__half2*>(&u1.x));
            float2 q = __half22float2(*reinterpret_cast<__half2*>(&u1.y));
            ax = fmaf(p.x, w1, ax); ay = fmaf(p.y, w1, ay);
            az = fmaf(q.x, w1, az); aw = fmaf(q.y, w1, aw);
        }
        {
            float2 p = __half22float2(*reinterpret_cast<__half2*>(&u2.x));
            float2 q = __half22float2(*reinterpret_cast<__half2*>(&u2.y));
            ax = fmaf(p.x, w2, ax); ay = fmaf(p.y, w2, ay);
            az = fmaf(q.x, w2, az); aw = fmaf(q.y, w2, aw);
        }
        {
            float2 p = __half22float2(*reinterpret_cast<__half2*>(&u3.x));
            float2 q = __half22float2(*reinterpret_cast<__half2*>(&u3.y));
            ax = fmaf(p.x, w3, ax); ay = fmaf(p.y, w3, ay);
            az = fmaf(q.x, w3, az); aw = fmaf(q.y, w3, aw);
        }
    }
    for (; i < end; i++) {
        int2 e0 = g_edges[i];
        uint2 u0 = g_feat16[(size_t)e0.x * 32 + lane];
        float w0 = __int_as_float(e0.y);
        float2 p = __half22float2(*reinterpret_cast<__half2*>(&u0.x));
        float2 q = __half22float2(*reinterpret_cast<__half2*>(&u0.y));
        ax = fmaf(p.x, w0, ax); ay = fmaf(p.y, w0, ay);
        az = fmaf(q.x, w0, az); aw = fmaf(q.y, w0, aw);
    }

    int deg = end - beg;
    float inv = 1.0f / (float)(deg > 1 ? deg : 1);
    float4 o = make_float4(ax * inv, ay * inv, az * inv, aw * inv);
    *reinterpret_cast<float4*>(&g_mean[(size_t)warp * D_FEAT + lane * 4]) = o;
}

// ---------------------------------------------------------------------------
// 6. persistent tf32 mma.sync GEMM.
//    148 CTAs x 128 threads (4 warps x 32 rows). Full W (256x128 tf32)
//    resident in smem; H restaged per 128-k half per tile.
//    Hs stride 132 (A-frag conflict-free), Ws stride 136 (B-frag c-f).
// ---------------------------------------------------------------------------
#define GEMM_THREADS 128
#define HS_STRIDE 132
#define WS_STRIDE 136
#define WS_WORDS (256 * WS_STRIDE)
#define HS_WORDS (128 * HS_STRIDE)
#define GEMM_SMEM ((WS_WORDS + HS_WORDS) * 4)   // 206848 B

__device__ __forceinline__ uint32_t f2tf32(float f) {
    uint32_t r;
    asm("cvt.rna.tf32.f32 %0, %1;" : "=r"(r) : "f"(f));
    return r;
}

__device__ __forceinline__ void mma_tf32(float& c0, float& c1, float& c2, float& c3,
                                         uint32_t a0, uint32_t a1, uint32_t a2, uint32_t a3,
                                         uint32_t b0, uint32_t b1) {
    asm volatile(
        "mma.sync.aligned.m16n8k8.row.col.f32.tf32.tf32.f32 "
        "{%0,%1,%2,%3}, {%4,%5,%6,%7}, {%8,%9}, {%0,%1,%2,%3};"
        : "+f"(c0), "+f"(c1), "+f"(c2), "+f"(c3)
        : "r"(a0), "r"(a1), "r"(a2), "r"(a3), "r"(b0), "r"(b1));
}

__global__ void __launch_bounds__(GEMM_THREADS, 1) gemm_kernel(
    const float* __restrict__ feat,
    const float* __restrict__ W,
    const float* __restrict__ b,
    float*       __restrict__ out,
    int N, int n_tiles)
{
    extern __shared__ uint32_t smem[];
    uint32_t* Ws = smem;              // [256][WS_STRIDE] tf32
    uint32_t* Hs = smem + WS_WORDS;   // [128][HS_STRIDE] tf32

    const int tid  = threadIdx.x;
    const int wid  = tid >> 5;
    const int lane = tid & 31;
    const int gid  = lane >> 2;       // 0..7
    const int tig  = lane & 3;        // 0..3
    const int wrow = wid * 32;        // warp's first row (4 warps x 32 rows)

    // --- stage full W once (converted to tf32) ---
    for (int idx = tid; idx < 256 * 128; idx += GEMM_THREADS) {
        int k = idx >> 7;
        int n = idx & 127;
        Ws[k * WS_STRIDE + n] = f2tf32(W[idx]);
    }
    __syncthreads();

    for (int tile = blockIdx.x; tile < n_tiles; tile += gridDim.x) {
        const int node0 = tile * 128;

        float acc[2][16][4];
        #pragma unroll
        for (int m = 0; m < 2; m++)
            #pragma unroll
            for (int nt = 0; nt < 16; nt++)
                #pragma unroll
                for (int q = 0; q < 4; q++) acc[m][nt][q] = 0.f;

        #pragma unroll 1
        for (int half = 0; half < 2; half++) {
            // --- stage H half ---
            #pragma unroll 4
            for (int idx4 = tid; idx4 < 128 * 32; idx4 += GEMM_THREADS) {
                int r = idx4 >> 5;
                int j = idx4 & 31;
                int node = node0 + r;
                float4 v = make_float4(0.f, 0.f, 0.f, 0.f);
                if (node < N) {
                    const float* srcp = (half == 0)
                        ? &feat[(size_t)node * D_FEAT]
                        : &g_mean[(size_t)node * D_FEAT];
                    v = *reinterpret_cast<const float4*>(srcp + j * 4);
                }
                uint32_t* dp = &Hs[r * HS_STRIDE + j * 4];
                dp[0] = f2tf32(v.x); dp[1] = f2tf32(v.y);
                dp[2] = f2tf32(v.z); dp[3] = f2tf32(v.w);
            }
            __syncthreads();

            const int wbase = half * 128;
            #pragma unroll 1
            for (int k0 = 0; k0 < 128; k0 += 8) {
                uint32_t a[2][4];
                #pragma unroll
                for (int m = 0; m < 2; m++) {
                    int r = wrow + m * 16 + gid;
                    a[m][0] = Hs[r       * HS_STRIDE + k0 + tig];
                    a[m][1] = Hs[(r + 8) * HS_STRIDE + k0 + tig];
                    a[m][2] = Hs[r       * HS_STRIDE + k0 + tig + 4];
                    a[m][3] = Hs[(r + 8) * HS_STRIDE + k0 + tig + 4];
                }
                #pragma unroll
                for (int nt = 0; nt < 16; nt++) {
                    uint32_t b0 = Ws[(wbase + k0 + tig)     * WS_STRIDE + nt * 8 + gid];
                    uint32_t b1 = Ws[(wbase + k0 + tig + 4) * WS_STRIDE + nt * 8 + gid];
                    mma_tf32(acc[0][nt][0], acc[0][nt][1], acc[0][nt][2], acc[0][nt][3],
                             a[0][0], a[0][1], a[0][2], a[0][3], b0, b1);
                    mma_tf32(acc[1][nt][0], acc[1][nt][1], acc[1][nt][2], acc[1][nt][3],
                             a[1][0], a[1][1], a[1][2], a[1][3], b0, b1);
                }
            }
            __syncthreads();
        }

        // --- epilogue: bias + float2 stores ---
        #pragma unroll
        for (int m = 0; m < 2; m++) {
            int row0 = node0 + wrow + m * 16 + gid;
            int row1 = row0 + 8;
            #pragma unroll
            for (int nt = 0; nt < 16; nt++) {
                int col = nt * 8 + tig * 2;
                float2 bi = *reinterpret_cast<const float2*>(&b[col]);
                if (row0 < N) {
                    float2 o = make_float2(acc[m][nt][0] + bi.x, acc[m][nt][1] + bi.y);
                    *reinterpret_cast<float2*>(&out[(size_t)row0 * OUT_DIM + col]) = o;
                }
                if (row1 < N) {
                    float2 o = make_float2(acc[m][nt][2] + bi.x, acc[m][nt][3] + bi.y);
                    *reinterpret_cast<float2*>(&out[(size_t)row1 * OUT_DIM + col]) = o;
                }
            }
        }
        // no sync needed: next iteration's staging waits at its own barrier,
        // and epilogue reads only registers.
        __syncthreads();
    }
}

// ---------------------------------------------------------------------------
// Launch
// ---------------------------------------------------------------------------
extern "C" void kernel_launch(void* const* d_in, const int* in_sizes, int n_in,
                              void* d_out, int out_size)
{
    const float* feat    = (const float*)d_in[0];
    const float* rw      = (const float*)d_in[1];
    const float* W       = (const float*)d_in[2];
    const float* b       = (const float*)d_in[3];
    const int*   rel_idx = (const int*)d_in[4];

    const int N = in_sizes[0] / D_FEAT;
    const int E = in_sizes[1];
    float* out = (float*)d_out;

    init_kernel<<<512, 256>>>(feat, N);
    hist_kernel<<<(E + 255) / 256, 256>>>(rel_idx, E);

    int nb = (N + SCAN_BLOCK - 1) / SCAN_BLOCK;
    scan1_kernel<<<nb, SCAN_BLOCK>>>(N);
    scan2_kernel<<<1, 256>>>(nb);
    scan3_kernel<<<nb, SCAN_BLOCK>>>(N, E);

    scatter_kernel<<<(E + 255) / 256, 256>>>(rel_idx, rw, E);
    agg_kernel<<<(N * 32 + 255) / 256, 256>>>(N);

    int n_tiles = (N + 127) / 128;
    cudaFuncSetAttribute(gemm_kernel,
                         cudaFuncAttributeMaxDynamicSharedMemorySize, GEMM_SMEM);
    int grid = n_tiles < 148 ? n_tiles : 148;
    gemm_kernel<<<grid, GEMM_THREADS, GEMM_SMEM>>>(feat, W, b, out, N, n_tiles);
}

// round 6
// speedup vs baseline: 2.1290x; 1.4574x over previous
#include <cuda_runtime.h>
#include <cuda_bf16.h>
#include <cuda_fp16.h>
#include <cstdint>

// ---------------------------------------------------------------------------
// SAGESparseLayer: persistent fused edge pipeline + fp16 mma GEMM.
//
//   mean[n] = (1/max(deg(n),1)) * sum_{e: dst[e]==n} feature[src[e]] * rw[e]
//   out[n]  = [feature[n], mean[n]] @ W + b
//
// Launch 1 (mega_kernel, persistent, software grid barrier):
//   P0 zero cnt + feat->fp16   P1 hist   P2 chunk scan   P3 partial scan
//   P4 offsets->rowstart/cursor   P5 CSR scatter   P6 warp-per-node agg (fp16)
// Launch 2 (gemm_kernel): fp16 m16n8k16 MMA, W resident in smem, occupancy 2.
// ---------------------------------------------------------------------------

#define D_FEAT    128
#define OUT_DIM   128
#define MAX_NODES 131072
#define MAX_EDGES (1 << 20)
#define MAX_CHUNKS 256          // ceil(N/1024) = 98 for N=100000
#define MEGA_THREADS 1024

static __device__ __align__(16) uint2 g_feat16[(size_t)MAX_NODES * 32];  // fp16 feat
static __device__ __align__(16) uint2 g_mean16[(size_t)MAX_NODES * 32];  // fp16 mean
static __device__ int  g_cnt[MAX_NODES];
static __device__ int  g_rowstart[MAX_NODES + 1];
static __device__ int  g_cursor[MAX_NODES];
static __device__ int  g_chunksum[MAX_CHUNKS];
static __device__ __align__(8) int2 g_edges[MAX_EDGES];

// software grid barrier state (replay-safe: even #barriers per launch)
static __device__ int g_bar_cnt;            // 0 at launch start and end
static __device__ volatile int g_bar_sense; // 0 at launch start and end

__device__ __forceinline__ void gbar(int grid, int* lsense) {
    __syncthreads();
    if (threadIdx.x == 0) {
        int s = *lsense ^ 1;
        *lsense = s;
        __threadfence();
        if (atomicAdd(&g_bar_cnt, 1) == grid - 1) {
            g_bar_cnt = 0;
            __threadfence();
            g_bar_sense = s;
        } else {
            while (g_bar_sense != s) __nanosleep(64);
        }
        __threadfence();
    }
    __syncthreads();
}

// ---------------------------------------------------------------------------
// mega kernel: entire edge pipeline in one launch
// ---------------------------------------------------------------------------
__global__ void __launch_bounds__(MEGA_THREADS, 1) mega_kernel(
    const float* __restrict__ feat,
    const float* __restrict__ rw,
    const int*   __restrict__ rel_idx,
    int N, int E, int grid)
{
    __shared__ int ws[32];
    const int tid = threadIdx.x;
    const int cta = blockIdx.x;
    const int gthreads = grid * MEGA_THREADS;
    const int gtid = cta * MEGA_THREADS + tid;
    int lsense = 0;

    // ---- P0: zero counters + convert feature table to fp16 ----
    for (int i = gtid; i < N; i += gthreads) g_cnt[i] = 0;
    {
        const float4* f4 = reinterpret_cast<const float4*>(feat);
        int total = N * 32;
        for (int i = gtid; i < total; i += gthreads) {
            float4 v = f4[i];
            __half2 a = __floats2half2_rn(v.x, v.y);
            __half2 c = __floats2half2_rn(v.z, v.w);
            uint2 o;
            o.x = *reinterpret_cast<uint32_t*>(&a);
            o.y = *reinterpret_cast<uint32_t*>(&c);
            g_feat16[i] = o;
        }
    }
    gbar(grid, &lsense);   // 1

    // ---- P1: histogram of dst ids ----
    for (int e = gtid; e < E; e += gthreads)
        atomicAdd(&g_cnt[rel_idx[e]], 1);
    gbar(grid, &lsense);   // 2

    // ---- P2: per-chunk (1024) exclusive scan + chunk totals ----
    {
        int nchunks = (N + MEGA_THREADS - 1) / MEGA_THREADS;
        for (int c = cta; c < nchunks; c += grid) {
            int i = c * MEGA_THREADS + tid;
            int v = (i < N) ? g_cnt[i] : 0;
            int x = v;
            #pragma unroll
            for (int o = 1; o < 32; o <<= 1) {
                int y = __shfl_up_sync(0xffffffffu, x, o);
                if ((tid & 31) >= o) x += y;
            }
            if ((tid & 31) == 31) ws[tid >> 5] = x;
            __syncthreads();
            if (tid < 32) {
                int w = ws[tid];
                int xx = w;
                #pragma unroll
                for (int o = 1; o < 32; o <<= 1) {
                    int y = __shfl_up_sync(0xffffffffu, xx, o);
                    if (tid >= o) xx += y;
                }
                ws[tid] = xx - w;
            }
            __syncthreads();
            int excl = (x - v) + ws[tid >> 5];
            if (i < N) g_rowstart[i] = excl;
            if (tid == MEGA_THREADS - 1) g_chunksum[c] = excl + v;
            __syncthreads();
        }
    }
    gbar(grid, &lsense);   // 3

    // ---- P3: CTA 0 scans chunk totals (nchunks <= 1024) ----
    if (cta == 0) {
        int nchunks = (N + MEGA_THREADS - 1) / MEGA_THREADS;
        int v = (tid < nchunks) ? g_chunksum[tid] : 0;
        int x = v;
        #pragma unroll
        for (int o = 1; o < 32; o <<= 1) {
            int y = __shfl_up_sync(0xffffffffu, x, o);
            if ((tid & 31) >= o) x += y;
        }
        if ((tid & 31) == 31) ws[tid >> 5] = x;
        __syncthreads();
        if (tid < 32) {
            int w = ws[tid];
            int xx = w;
            #pragma unroll
            for (int o = 1; o < 32; o <<= 1) {
                int y = __shfl_up_sync(0xffffffffu, xx, o);
                if (tid >= o) xx += y;
            }
            ws[tid] = xx - w;
        }
        __syncthreads();
        int excl = (x - v) + ws[tid >> 5];
        if (tid < nchunks) g_chunksum[tid] = excl;
    }
    gbar(grid, &lsense);   // 4

    // ---- P4: add chunk offsets, init cursor ----
    for (int i = gtid; i < N; i += gthreads) {
        int v = g_rowstart[i] + g_chunksum[i >> 10];
        g_rowstart[i] = v;
        g_cursor[i]   = v;
    }
    if (gtid == 0) g_rowstart[N] = E;
    gbar(grid, &lsense);   // 5

    // ---- P5: scatter edges into CSR buckets ----
    for (int e = gtid; e < E; e += gthreads) {
        int dst = rel_idx[e];
        int src = rel_idx[E + e];
        float w = rw[e];
        int p = atomicAdd(&g_cursor[dst], 1);
        g_edges[p] = make_int2(src, __float_as_int(w));
    }
    gbar(grid, &lsense);   // 6

    // ---- P6: per-node aggregation (warp per node), write fp16 mean ----
    {
        int gwarps = gthreads >> 5;
        int lane = tid & 31;
        for (int node = gtid >> 5; node < N; node += gwarps) {
            int beg = g_rowstart[node];
            int end = g_rowstart[node + 1];

            float ax = 0.f, ay = 0.f, az = 0.f, aw = 0.f;
            int i = beg;
            #pragma unroll 1
            for (; i + 4 <= end; i += 4) {
                int2 e0 = g_edges[i];
                int2 e1 = g_edges[i + 1];
                int2 e2 = g_edges[i + 2];
                int2 e3 = g_edges[i + 3];
                uint2 u0 = g_feat16[(size_t)e0.x * 32 + lane];
                uint2 u1 = g_feat16[(size_t)e1.x * 32 + lane];
                uint2 u2 = g_feat16[(size_t)e2.x * 32 + lane];
                uint2 u3 = g_feat16[(size_t)e3.x * 32 + lane];
                float w0 = __int_as_float(e0.y), w1 = __int_as_float(e1.y);
                float w2 = __int_as_float(e2.y), w3 = __int_as_float(e3.y);
                float2 p, q;
                p = __half22float2(*reinterpret_cast<__half2*>(&u0.x));
                q = __half22float2(*reinterpret_cast<__half2*>(&u0.y));
                ax = fmaf(p.x, w0, ax); ay = fmaf(p.y, w0, ay);
                az = fmaf(q.x, w0, az); aw = fmaf(q.y, w0, aw);
                p = __half22float2(*reinterpret_cast<__half2*>(&u1.x));
                q = __half22float2(*reinterpret_cast<__half2*>(&u1.y));
                ax = fmaf(p.x, w1, ax); ay = fmaf(p.y, w1, ay);
                az = fmaf(q.x, w1, az); aw = fmaf(q.y, w1, aw);
                p = __half22float2(*reinterpret_cast<__half2*>(&u2.x));
                q = __half22float2(*reinterpret_cast<__half2*>(&u2.y));
                ax = fmaf(p.x, w2, ax); ay = fmaf(p.y, w2, ay);
                az = fmaf(q.x, w2, az); aw = fmaf(q.y, w2, aw);
                p = __half22float2(*reinterpret_cast<__half2*>(&u3.x));
                q = __half22float2(*reinterpret_cast<__half2*>(&u3.y));
                ax = fmaf(p.x, w3, ax); ay = fmaf(p.y, w3, ay);
                az = fmaf(q.x, w3, az); aw = fmaf(q.y, w3, aw);
            }
            for (; i < end; i++) {
                int2 e0 = g_edges[i];
                uint2 u0 = g_feat16[(size_t)e0.x * 32 + lane];
                float w0 = __int_as_float(e0.y);
                float2 p = __half22float2(*reinterpret_cast<__half2*>(&u0.x));
                float2 q = __half22float2(*reinterpret_cast<__half2*>(&u0.y));
                ax = fmaf(p.x, w0, ax); ay = fmaf(p.y, w0, ay);
                az = fmaf(q.x, w0, az); aw = fmaf(q.y, w0, aw);
            }

            int deg = end - beg;
            float inv = 1.0f / (float)(deg > 1 ? deg : 1);
            __half2 m0 = __floats2half2_rn(ax * inv, ay * inv);
            __half2 m1 = __floats2half2_rn(az * inv, aw * inv);
            uint2 o;
            o.x = *reinterpret_cast<uint32_t*>(&m0);
            o.y = *reinterpret_cast<uint32_t*>(&m1);
            g_mean16[(size_t)node * 32 + lane] = o;
        }
    }
}

// ---------------------------------------------------------------------------
// fp16 mma GEMM: out[128-tile][128] = [feat16|mean16] @ W + b
//   4 warps x 32 rows, 16 col-tiles of 8. W resident as fp16 [n][k] pairs.
//   Ws_u32 stride 132 (B-frag conflict-free), Hs_u32 stride 68 (A-frag c-f).
// ---------------------------------------------------------------------------
#define GEMM_THREADS 128
#define WS_STRIDE 132                  // uint32 (fp16 pair) stride per n-row
#define HS_STRIDE 68                   // uint32 stride per m-row
#define WS_WORDS (128 * WS_STRIDE)
#define HS_WORDS (128 * HS_STRIDE)
#define GEMM_SMEM ((WS_WORDS + HS_WORDS) * 4)   // 102400 B

__device__ __forceinline__ void mma_fp16(float& c0, float& c1, float& c2, float& c3,
                                         uint32_t a0, uint32_t a1, uint32_t a2, uint32_t a3,
                                         uint32_t b0, uint32_t b1) {
    asm volatile(
        "mma.sync.aligned.m16n8k16.row.col.f32.f16.f16.f32 "
        "{%0,%1,%2,%3}, {%4,%5,%6,%7}, {%8,%9}, {%0,%1,%2,%3};"
        : "+f"(c0), "+f"(c1), "+f"(c2), "+f"(c3)
        : "r"(a0), "r"(a1), "r"(a2), "r"(a3), "r"(b0), "r"(b1));
}

__global__ void __launch_bounds__(GEMM_THREADS, 2) gemm_kernel(
    const float* __restrict__ W,
    const float* __restrict__ b,
    float*       __restrict__ out,
    int N, int n_tiles)
{
    extern __shared__ uint32_t smem[];
    uint32_t* Ws = smem;              // [128 n][WS_STRIDE] fp16-pairs along k
    uint32_t* Hs = smem + WS_WORDS;   // [128 m][HS_STRIDE] fp16-pairs along k

    const int tid  = threadIdx.x;
    const int wid  = tid >> 5;
    const int lane = tid & 31;
    const int gid  = lane >> 2;       // 0..7
    const int tig  = lane & 3;        // 0..3
    const int wrow = wid * 32;

    // --- stage W once: Ws[n][kp] = (fp16 W[2kp][n], fp16 W[2kp+1][n]) ---
    {
        __half* Wh = reinterpret_cast<__half*>(Ws);
        for (int idx = tid; idx < 256 * 128; idx += GEMM_THREADS) {
            int k = idx >> 7;
            int n = idx & 127;
            Wh[n * (2 * WS_STRIDE) + k] = __float2half(W[idx]);
        }
    }
    __syncthreads();

    for (int tile = blockIdx.x; tile < n_tiles; tile += gridDim.x) {
        const int node0 = tile * 128;

        float acc[2][16][4];
        #pragma unroll
        for (int m = 0; m < 2; m++)
            #pragma unroll
            for (int nt = 0; nt < 16; nt++)
                #pragma unroll
                for (int q = 0; q < 4; q++) acc[m][nt][q] = 0.f;

        #pragma unroll 1
        for (int half = 0; half < 2; half++) {
            // --- stage H half: pure uint2 copies from fp16 tables ---
            const uint2* srct = (half == 0) ? g_feat16 : g_mean16;
            #pragma unroll 4
            for (int idx = tid; idx < 128 * 32; idx += GEMM_THREADS) {
                int r = idx >> 5;
                int j = idx & 31;
                int node = node0 + r;
                uint2 v = make_uint2(0u, 0u);
                if (node < N) v = srct[(size_t)node * 32 + j];
                Hs[r * HS_STRIDE + j * 2]     = v.x;
                Hs[r * HS_STRIDE + j * 2 + 1] = v.y;
            }
            __syncthreads();

            const int kpg_base = half * 64;
            #pragma unroll 1
            for (int ks = 0; ks < 8; ks++) {
                int kpl = ks * 8;            // local kp within half
                uint32_t a[2][4];
                #pragma unroll
                for (int m = 0; m < 2; m++) {
                    int r = wrow + m * 16 + gid;
                    a[m][0] = Hs[r       * HS_STRIDE + kpl + tig];
                    a[m][1] = Hs[(r + 8) * HS_STRIDE + kpl + tig];
                    a[m][2] = Hs[r       * HS_STRIDE + kpl + tig + 4];
                    a[m][3] = Hs[(r + 8) * HS_STRIDE + kpl + tig + 4];
                }
                int kpg = kpg_base + kpl;
                #pragma unroll
                for (int nt = 0; nt < 16; nt++) {
                    uint32_t b0 = Ws[(nt * 8 + gid) * WS_STRIDE + kpg + tig];
                    uint32_t b1 = Ws[(nt * 8 + gid) * WS_STRIDE + kpg + tig + 4];
                    mma_fp16(acc[0][nt][0], acc[0][nt][1], acc[0][nt][2], acc[0][nt][3],
                             a[0][0], a[0][1], a[0][2], a[0][3], b0, b1);
                    mma_fp16(acc[1][nt][0], acc[1][nt][1], acc[1][nt][2], acc[1][nt][3],
                             a[1][0], a[1][1], a[1][2], a[1][3], b0, b1);
                }
            }
            __syncthreads();
        }

        // --- epilogue: bias + float2 stores ---
        #pragma unroll
        for (int m = 0; m < 2; m++) {
            int row0 = node0 + wrow + m * 16 + gid;
            int row1 = row0 + 8;
            #pragma unroll
            for (int nt = 0; nt < 16; nt++) {
                int col = nt * 8 + tig * 2;
                float2 bi = *reinterpret_cast<const float2*>(&b[col]);
                if (row0 < N) {
                    float2 o = make_float2(acc[m][nt][0] + bi.x, acc[m][nt][1] + bi.y);
                    *reinterpret_cast<float2*>(&out[(size_t)row0 * OUT_DIM + col]) = o;
                }
                if (row1 < N) {
                    float2 o = make_float2(acc[m][nt][2] + bi.x, acc[m][nt][3] + bi.y);
                    *reinterpret_cast<float2*>(&out[(size_t)row1 * OUT_DIM + col]) = o;
                }
            }
        }
        __syncthreads();
    }
}

// ---------------------------------------------------------------------------
// Launch
// ---------------------------------------------------------------------------
extern "C" void kernel_launch(void* const* d_in, const int* in_sizes, int n_in,
                              void* d_out, int out_size)
{
    const float* feat    = (const float*)d_in[0];
    const float* rw      = (const float*)d_in[1];
    const float* W       = (const float*)d_in[2];
    const float* b       = (const float*)d_in[3];
    const int*   rel_idx = (const int*)d_in[4];

    const int N = in_sizes[0] / D_FEAT;
    const int E = in_sizes[1];
    float* out = (float*)d_out;

    int sm = 0;
    cudaDeviceGetAttribute(&sm, cudaDevAttrMultiProcessorCount, 0);
    if (sm <= 0) sm = 148;
    int grid = sm;   // all-resident: 1024 thr/CTA, 1 CTA/SM guaranteed

    mega_kernel<<<grid, MEGA_THREADS>>>(feat, rw, rel_idx, N, E, grid);

    int n_tiles = (N + 127) / 128;
    cudaFuncSetAttribute(gemm_kernel,
                         cudaFuncAttributeMaxDynamicSharedMemorySize, GEMM_SMEM);
    int ggrid = 2 * sm;
    if (ggrid > n_tiles) ggrid = n_tiles;
    gemm_kernel<<<ggrid, GEMM_THREADS, GEMM_SMEM>>>(W, b, out, N, n_tiles);
}

// round 7
// speedup vs baseline: 2.3384x; 1.0984x over previous
#include <cuda_runtime.h>
#include <cuda_bf16.h>
#include <cuda_fp16.h>
#include <cstdint>

// ---------------------------------------------------------------------------
// SAGESparseLayer: persistent fused edge pipeline + streaming fp16 mma GEMM.
//
//   mean[n] = (1/max(deg(n),1)) * sum_{e: dst[e]==n} feature[src[e]] * rw[e]
//   out[n]  = [feature[n], mean[n]] @ W + b
//
// Launch 1 (mega_kernel, persistent, software grid barrier): edge pipeline.
// Launch 2 (gemm_kernel): warp-per-16-rows, A fragments straight from the
//   L2-resident fp16 tables (double-buffered), W resident in smem, B via
//   ldmatrix.x2, no syncs in the main loop, occupancy 2 CTAs/SM.
// ---------------------------------------------------------------------------

#define D_FEAT    128
#define OUT_DIM   128
#define MAX_NODES 131072
#define MAX_EDGES (1 << 20)
#define MAX_CHUNKS 256
#define MEGA_THREADS 1024

static __device__ __align__(16) uint2 g_feat16[(size_t)MAX_NODES * 32];  // fp16 feat
static __device__ __align__(16) uint2 g_mean16[(size_t)MAX_NODES * 32];  // fp16 mean
static __device__ int  g_cnt[MAX_NODES];
static __device__ int  g_rowstart[MAX_NODES + 1];
static __device__ int  g_cursor[MAX_NODES];
static __device__ int  g_chunksum[MAX_CHUNKS];
static __device__ __align__(8) int2 g_edges[MAX_EDGES];

// software grid barrier state (replay-safe: even #barriers per launch)
static __device__ int g_bar_cnt;
static __device__ volatile int g_bar_sense;

__device__ __forceinline__ void gbar(int grid, int* lsense) {
    __syncthreads();
    if (threadIdx.x == 0) {
        int s = *lsense ^ 1;
        *lsense = s;
        __threadfence();
        if (atomicAdd(&g_bar_cnt, 1) == grid - 1) {
            g_bar_cnt = 0;
            __threadfence();
            g_bar_sense = s;
        } else {
            while (g_bar_sense != s) __nanosleep(64);
        }
        __threadfence();
    }
    __syncthreads();
}

// ---------------------------------------------------------------------------
// mega kernel: entire edge pipeline in one launch
// ---------------------------------------------------------------------------
__global__ void __launch_bounds__(MEGA_THREADS, 1) mega_kernel(
    const float* __restrict__ feat,
    const float* __restrict__ rw,
    const int*   __restrict__ rel_idx,
    int N, int E, int grid)
{
    __shared__ int ws[32];
    const int tid = threadIdx.x;
    const int cta = blockIdx.x;
    const int gthreads = grid * MEGA_THREADS;
    const int gtid = cta * MEGA_THREADS + tid;
    int lsense = 0;

    // ---- P0: zero counters + convert feature table to fp16 ----
    for (int i = gtid; i < N; i += gthreads) g_cnt[i] = 0;
    {
        const float4* f4 = reinterpret_cast<const float4*>(feat);
        int total = N * 32;
        for (int i = gtid; i < total; i += gthreads) {
            float4 v = f4[i];
            __half2 a = __floats2half2_rn(v.x, v.y);
            __half2 c = __floats2half2_rn(v.z, v.w);
            uint2 o;
            o.x = *reinterpret_cast<uint32_t*>(&a);
            o.y = *reinterpret_cast<uint32_t*>(&c);
            g_feat16[i] = o;
        }
    }
    gbar(grid, &lsense);   // 1

    // ---- P1: histogram of dst ids ----
    for (int e = gtid; e < E; e += gthreads)
        atomicAdd(&g_cnt[rel_idx[e]], 1);
    gbar(grid, &lsense);   // 2

    // ---- P2: per-chunk (1024) exclusive scan + chunk totals ----
    {
        int nchunks = (N + MEGA_THREADS - 1) / MEGA_THREADS;
        for (int c = cta; c < nchunks; c += grid) {
            int i = c * MEGA_THREADS + tid;
            int v = (i < N) ? g_cnt[i] : 0;
            int x = v;
            #pragma unroll
            for (int o = 1; o < 32; o <<= 1) {
                int y = __shfl_up_sync(0xffffffffu, x, o);
                if ((tid & 31) >= o) x += y;
            }
            if ((tid & 31) == 31) ws[tid >> 5] = x;
            __syncthreads();
            if (tid < 32) {
                int w = ws[tid];
                int xx = w;
                #pragma unroll
                for (int o = 1; o < 32; o <<= 1) {
                    int y = __shfl_up_sync(0xffffffffu, xx, o);
                    if (tid >= o) xx += y;
                }
                ws[tid] = xx - w;
            }
            __syncthreads();
            int excl = (x - v) + ws[tid >> 5];
            if (i < N) g_rowstart[i] = excl;
            if (tid == MEGA_THREADS - 1) g_chunksum[c] = excl + v;
            __syncthreads();
        }
    }
    gbar(grid, &lsense);   // 3

    // ---- P3: CTA 0 scans chunk totals ----
    if (cta == 0) {
        int nchunks = (N + MEGA_THREADS - 1) / MEGA_THREADS;
        int v = (tid < nchunks) ? g_chunksum[tid] : 0;
        int x = v;
        #pragma unroll
        for (int o = 1; o < 32; o <<= 1) {
            int y = __shfl_up_sync(0xffffffffu, x, o);
            if ((tid & 31) >= o) x += y;
        }
        if ((tid & 31) == 31) ws[tid >> 5] = x;
        __syncthreads();
        if (tid < 32) {
            int w = ws[tid];
            int xx = w;
            #pragma unroll
            for (int o = 1; o < 32; o <<= 1) {
                int y = __shfl_up_sync(0xffffffffu, xx, o);
                if (tid >= o) xx += y;
            }
            ws[tid] = xx - w;
        }
        __syncthreads();
        int excl = (x - v) + ws[tid >> 5];
        if (tid < nchunks) g_chunksum[tid] = excl;
    }
    gbar(grid, &lsense);   // 4

    // ---- P4: add chunk offsets, init cursor ----
    for (int i = gtid; i < N; i += gthreads) {
        int v = g_rowstart[i] + g_chunksum[i >> 10];
        g_rowstart[i] = v;
        g_cursor[i]   = v;
    }
    if (gtid == 0) g_rowstart[N] = E;
    gbar(grid, &lsense);   // 5

    // ---- P5: scatter edges into CSR buckets ----
    for (int e = gtid; e < E; e += gthreads) {
        int dst = rel_idx[e];
        int src = rel_idx[E + e];
        float w = rw[e];
        int p = atomicAdd(&g_cursor[dst], 1);
        g_edges[p] = make_int2(src, __float_as_int(w));
    }
    gbar(grid, &lsense);   // 6

    // ---- P6: per-node aggregation (warp per node), write fp16 mean ----
    {
        int gwarps = gthreads >> 5;
        int lane = tid & 31;
        for (int node = gtid >> 5; node < N; node += gwarps) {
            int beg = g_rowstart[node];
            int end = g_rowstart[node + 1];

            float ax = 0.f, ay = 0.f, az = 0.f, aw = 0.f;
            int i = beg;
            #pragma unroll 1
            for (; i + 4 <= end; i += 4) {
                int2 e0 = g_edges[i];
                int2 e1 = g_edges[i + 1];
                int2 e2 = g_edges[i + 2];
                int2 e3 = g_edges[i + 3];
                uint2 u0 = g_feat16[(size_t)e0.x * 32 + lane];
                uint2 u1 = g_feat16[(size_t)e1.x * 32 + lane];
                uint2 u2 = g_feat16[(size_t)e2.x * 32 + lane];
                uint2 u3 = g_feat16[(size_t)e3.x * 32 + lane];
                float w0 = __int_as_float(e0.y), w1 = __int_as_float(e1.y);
                float w2 = __int_as_float(e2.y), w3 = __int_as_float(e3.y);
                float2 p, q;
                p = __half22float2(*reinterpret_cast<__half2*>(&u0.x));
                q = __half22float2(*reinterpret_cast<__half2*>(&u0.y));
                ax = fmaf(p.x, w0, ax); ay = fmaf(p.y, w0, ay);
                az = fmaf(q.x, w0, az); aw = fmaf(q.y, w0, aw);
                p = __half22float2(*reinterpret_cast<__half2*>(&u1.x));
                q = __half22float2(*reinterpret_cast<__half2*>(&u1.y));
                ax = fmaf(p.x, w1, ax); ay = fmaf(p.y, w1, ay);
                az = fmaf(q.x, w1, az); aw = fmaf(q.y, w1, aw);
                p = __half22float2(*reinterpret_cast<__half2*>(&u2.x));
                q = __half22float2(*reinterpret_cast<__half2*>(&u2.y));
                ax = fmaf(p.x, w2, ax); ay = fmaf(p.y, w2, ay);
                az = fmaf(q.x, w2, az); aw = fmaf(q.y, w2, aw);
                p = __half22float2(*reinterpret_cast<__half2*>(&u3.x));
                q = __half22float2(*reinterpret_cast<__half2*>(&u3.y));
                ax = fmaf(p.x, w3, ax); ay = fmaf(p.y, w3, ay);
                az = fmaf(q.x, w3, az); aw = fmaf(q.y, w3, aw);
            }
            for (; i < end; i++) {
                int2 e0 = g_edges[i];
                uint2 u0 = g_feat16[(size_t)e0.x * 32 + lane];
                float w0 = __int_as_float(e0.y);
                float2 p = __half22float2(*reinterpret_cast<__half2*>(&u0.x));
                float2 q = __half22float2(*reinterpret_cast<__half2*>(&u0.y));
                ax = fmaf(p.x, w0, ax); ay = fmaf(p.y, w0, ay);
                az = fmaf(q.x, w0, az); aw = fmaf(q.y, w0, aw);
            }

            int deg = end - beg;
            float inv = 1.0f / (float)(deg > 1 ? deg : 1);
            __half2 m0 = __floats2half2_rn(ax * inv, ay * inv);
            __half2 m1 = __floats2half2_rn(az * inv, aw * inv);
            uint2 o;
            o.x = *reinterpret_cast<uint32_t*>(&m0);
            o.y = *reinterpret_cast<uint32_t*>(&m1);
            g_mean16[(size_t)node * 32 + lane] = o;
        }
    }
}

// ---------------------------------------------------------------------------
// Streaming fp16 mma GEMM.
//   Warp-per-16-rows. A fragments loaded directly from fp16 tables (global,
//   L2-resident), double-buffered across the 16 k-steps. W resident in smem
//   (fp16, [128 n][132 uint32], pairs along k); B frags via ldmatrix.x2.
//   No __syncthreads after W staging. 2 CTAs/SM.
// ---------------------------------------------------------------------------
#define GEMM_THREADS 256
#define WS_STRIDE 132                              // uint32 per n-row
#define GEMM_SMEM (128 * WS_STRIDE * 4)            // 67584 B

__device__ __forceinline__ uint32_t smem_u32(const void* p) {
    uint32_t a;
    asm("{ .reg .u64 t; cvta.to.shared.u64 t, %1; cvt.u32.u64 %0, t; }"
        : "=r"(a) : "l"(p));
    return a;
}

__device__ __forceinline__ void mma_fp16(float& c0, float& c1, float& c2, float& c3,
                                         uint32_t a0, uint32_t a1, uint32_t a2, uint32_t a3,
                                         uint32_t b0, uint32_t b1) {
    asm volatile(
        "mma.sync.aligned.m16n8k16.row.col.f32.f16.f16.f32 "
        "{%0,%1,%2,%3}, {%4,%5,%6,%7}, {%8,%9}, {%0,%1,%2,%3};"
        : "+f"(c0), "+f"(c1), "+f"(c2), "+f"(c3)
        : "r"(a0), "r"(a1), "r"(a2), "r"(a3), "r"(b0), "r"(b1));
}

__global__ void __launch_bounds__(GEMM_THREADS, 2) gemm_kernel(
    const float* __restrict__ W,
    const float* __restrict__ b,
    float*       __restrict__ out,
    int N, int n_wtiles)
{
    extern __shared__ uint32_t Ws[];   // [128 n][WS_STRIDE] fp16 pairs along k

    const int tid  = threadIdx.x;
    const int wid  = tid >> 5;
    const int lane = tid & 31;
    const int gid  = lane >> 2;        // 0..7
    const int tig  = lane & 3;         // 0..3

    // --- stage W: Ws[n][kp] = (fp16 W[2kp][n], fp16 W[2kp+1][n]) ---
    for (int idx = tid; idx < 128 * 128; idx += GEMM_THREADS) {
        int kp = idx >> 7;
        int n  = idx & 127;
        __half2 h = __floats2half2_rn(W[(2 * kp) * OUT_DIM + n],
                                      (W[(2 * kp + 1) * OUT_DIM + n]));
        Ws[n * WS_STRIDE + kp] = *reinterpret_cast<uint32_t*>(&h);
    }
    __syncthreads();

    const int wt = blockIdx.x * 8 + wid;      // warp-tile index (16 rows)
    if (wt >= n_wtiles) return;

    const int nd0 = wt * 16 + gid;
    const int nd1 = nd0 + 8;
    const bool v0 = nd0 < N;
    const bool v1 = nd1 < N;

    const uint32_t* featw = reinterpret_cast<const uint32_t*>(g_feat16);
    const uint32_t* meanw = reinterpret_cast<const uint32_t*>(g_mean16);
    const size_t o0 = (size_t)nd0 * 64 + tig;
    const size_t o1 = (size_t)nd1 * 64 + tig;

    // per-lane ldmatrix base address (x2: lanes 0-7 mat0 rows, 8-15 mat1)
    const uint32_t lm_base = smem_u32(Ws)
        + (((lane & 7) * WS_STRIDE) + ((lane >> 3) & 1) * 4) * 4;

    float acc[16][4];
    #pragma unroll
    for (int nt = 0; nt < 16; nt++)
        #pragma unroll
        for (int q = 0; q < 4; q++) acc[nt][q] = 0.f;

    uint32_t ac[4], an[4];
    // prefetch step 0 (half 0, ks 0)
    ac[0] = v0 ? featw[o0]     : 0u;
    ac[1] = v1 ? featw[o1]     : 0u;
    ac[2] = v0 ? featw[o0 + 4] : 0u;
    ac[3] = v1 ? featw[o1 + 4] : 0u;

    #pragma unroll
    for (int step = 0; step < 16; step++) {
        // prefetch next step's A fragments
        if (step < 15) {
            int s = step + 1;
            const uint32_t* t = (s < 8) ? featw : meanw;
            int kw = (s & 7) * 8;
            an[0] = v0 ? t[o0 + kw]     : 0u;
            an[1] = v1 ? t[o1 + kw]     : 0u;
            an[2] = v0 ? t[o0 + kw + 4] : 0u;
            an[3] = v1 ? t[o1 + kw + 4] : 0u;
        }

        const uint32_t lm_step = lm_base + step * 32;   // + step*8 words
        #pragma unroll
        for (int nt = 0; nt < 16; nt++) {
            uint32_t b0, b1;
            asm volatile("ldmatrix.sync.aligned.m8n8.x2.shared.b16 {%0,%1}, [%2];"
                         : "=r"(b0), "=r"(b1)
                         : "r"(lm_step + nt * (8 * WS_STRIDE * 4)));
            mma_fp16(acc[nt][0], acc[nt][1], acc[nt][2], acc[nt][3],
                     ac[0], ac[1], ac[2], ac[3], b0, b1);
        }

        #pragma unroll
        for (int q = 0; q < 4; q++) ac[q] = an[q];
    }

    // --- epilogue: bias + float2 stores ---
    #pragma unroll
    for (int nt = 0; nt < 16; nt++) {
        int col = nt * 8 + tig * 2;
        float2 bi = *reinterpret_cast<const float2*>(&b[col]);
        if (v0) {
            float2 o = make_float2(acc[nt][0] + bi.x, acc[nt][1] + bi.y);
            *reinterpret_cast<float2*>(&out[(size_t)nd0 * OUT_DIM + col]) = o;
        }
        if (v1) {
            float2 o = make_float2(acc[nt][2] + bi.x, acc[nt][3] + bi.y);
            *reinterpret_cast<float2*>(&out[(size_t)nd1 * OUT_DIM + col]) = o;
        }
    }
}

// ---------------------------------------------------------------------------
// Launch
// ---------------------------------------------------------------------------
extern "C" void kernel_launch(void* const* d_in, const int* in_sizes, int n_in,
                              void* d_out, int out_size)
{
    const float* feat    = (const float*)d_in[0];
    const float* rw      = (const float*)d_in[1];
    const float* W       = (const float*)d_in[2];
    const float* b       = (const float*)d_in[3];
    const int*   rel_idx = (const int*)d_in[4];

    const int N = in_sizes[0] / D_FEAT;
    const int E = in_sizes[1];
    float* out = (float*)d_out;

    int sm = 0;
    cudaDeviceGetAttribute(&sm, cudaDevAttrMultiProcessorCount, 0);
    if (sm <= 0) sm = 148;

    mega_kernel<<<sm, MEGA_THREADS>>>(feat, rw, rel_idx, N, E, sm);

    int n_wtiles = (N + 15) / 16;
    int blocks = (n_wtiles + 7) / 8;
    cudaFuncSetAttribute(gemm_kernel,
                         cudaFuncAttributeMaxDynamicSharedMemorySize, GEMM_SMEM);
    gemm_kernel<<<blocks, GEMM_THREADS, GEMM_SMEM>>>(W, b, out, N, n_wtiles);
}

// round 8
// speedup vs baseline: 2.4399x; 1.0434x over previous
#include <cuda_runtime.h>
#include <cuda_bf16.h>
#include <cuda_fp16.h>
#include <cstdint>

// ---------------------------------------------------------------------------
// SAGESparseLayer: persistent fused edge pipeline + persistent fp16 mma GEMM.
//
//   mean[n] = (1/max(deg(n),1)) * sum_{e: dst[e]==n} feature[src[e]] * rw[e]
//   out[n]  = [feature[n], mean[n]] @ W + b
// ---------------------------------------------------------------------------

#define D_FEAT    128
#define OUT_DIM   128
#define MAX_NODES 131072
#define MAX_EDGES (1 << 20)
#define MAX_CHUNKS 256
#define MEGA_THREADS 1024

static __device__ __align__(16) uint2 g_feat16[(size_t)MAX_NODES * 32];  // fp16 feat
static __device__ __align__(16) uint2 g_mean16[(size_t)MAX_NODES * 32];  // fp16 mean
static __device__ int  g_cnt[MAX_NODES];
static __device__ int  g_rowstart[MAX_NODES + 1];
static __device__ int  g_cursor[MAX_NODES];
static __device__ int  g_chunksum[MAX_CHUNKS];
static __device__ __align__(8) int2 g_edges[MAX_EDGES];

// software grid barrier state (replay-safe: even #barriers per launch)
static __device__ int g_bar_cnt;
static __device__ volatile int g_bar_sense;

__device__ __forceinline__ void gbar(int grid, int* lsense) {
    __syncthreads();
    if (threadIdx.x == 0) {
        int s = *lsense ^ 1;
        *lsense = s;
        __threadfence();
        if (atomicAdd(&g_bar_cnt, 1) == grid - 1) {
            g_bar_cnt = 0;
            __threadfence();
            g_bar_sense = s;
        } else {
            while (g_bar_sense != s) __nanosleep(64);
        }
        __threadfence();
    }
    __syncthreads();
}

// ---------------------------------------------------------------------------
// mega kernel: entire edge pipeline in one launch
// ---------------------------------------------------------------------------
__global__ void __launch_bounds__(MEGA_THREADS, 1) mega_kernel(
    const float* __restrict__ feat,
    const float* __restrict__ rw,
    const int*   __restrict__ rel_idx,
    int N, int E, int grid)
{
    __shared__ int ws[32];
    const int tid = threadIdx.x;
    const int cta = blockIdx.x;
    const int gthreads = grid * MEGA_THREADS;
    const int gtid = cta * MEGA_THREADS + tid;
    int lsense = 0;

    // ---- P0: zero counters (tiny) ----
    for (int i = gtid; i < N; i += gthreads) g_cnt[i] = 0;
    gbar(grid, &lsense);   // 1

    // ---- P1: histogram of dst ids + fp16 feature conversion (overlapped) ----
    for (int e = gtid; e < E; e += gthreads)
        atomicAdd(&g_cnt[rel_idx[e]], 1);
    {
        const float4* f4 = reinterpret_cast<const float4*>(feat);
        int total = N * 32;
        for (int i = gtid; i < total; i += gthreads) {
            float4 v = f4[i];
            __half2 a = __floats2half2_rn(v.x, v.y);
            __half2 c = __floats2half2_rn(v.z, v.w);
            uint2 o;
            o.x = *reinterpret_cast<uint32_t*>(&a);
            o.y = *reinterpret_cast<uint32_t*>(&c);
            g_feat16[i] = o;
        }
    }
    gbar(grid, &lsense);   // 2

    // ---- P2: per-chunk (1024) exclusive scan + chunk totals ----
    {
        int nchunks = (N + MEGA_THREADS - 1) / MEGA_THREADS;
        for (int c = cta; c < nchunks; c += grid) {
            int i = c * MEGA_THREADS + tid;
            int v = (i < N) ? g_cnt[i] : 0;
            int x = v;
            #pragma unroll
            for (int o = 1; o < 32; o <<= 1) {
                int y = __shfl_up_sync(0xffffffffu, x, o);
                if ((tid & 31) >= o) x += y;
            }
            if ((tid & 31) == 31) ws[tid >> 5] = x;
            __syncthreads();
            if (tid < 32) {
                int w = ws[tid];
                int xx = w;
                #pragma unroll
                for (int o = 1; o < 32; o <<= 1) {
                    int y = __shfl_up_sync(0xffffffffu, xx, o);
                    if (tid >= o) xx += y;
                }
                ws[tid] = xx - w;
            }
            __syncthreads();
            int excl = (x - v) + ws[tid >> 5];
            if (i < N) g_rowstart[i] = excl;
            if (tid == MEGA_THREADS - 1) g_chunksum[c] = excl + v;
            __syncthreads();
        }
    }
    gbar(grid, &lsense);   // 3

    // ---- P3: CTA 0 scans chunk totals ----
    if (cta == 0) {
        int nchunks = (N + MEGA_THREADS - 1) / MEGA_THREADS;
        int v = (tid < nchunks) ? g_chunksum[tid] : 0;
        int x = v;
        #pragma unroll
        for (int o = 1; o < 32; o <<= 1) {
            int y = __shfl_up_sync(0xffffffffu, x, o);
            if ((tid & 31) >= o) x += y;
        }
        if ((tid & 31) == 31) ws[tid >> 5] = x;
        __syncthreads();
        if (tid < 32) {
            int w = ws[tid];
            int xx = w;
            #pragma unroll
            for (int o = 1; o < 32; o <<= 1) {
                int y = __shfl_up_sync(0xffffffffu, xx, o);
                if (tid >= o) xx += y;
            }
            ws[tid] = xx - w;
        }
        __syncthreads();
        int excl = (x - v) + ws[tid >> 5];
        if (tid < nchunks) g_chunksum[tid] = excl;
    }
    gbar(grid, &lsense);   // 4

    // ---- P4: add chunk offsets, init cursor ----
    for (int i = gtid; i < N; i += gthreads) {
        int v = g_rowstart[i] + g_chunksum[i >> 10];
        g_rowstart[i] = v;
        g_cursor[i]   = v;
    }
    if (gtid == 0) g_rowstart[N] = E;
    gbar(grid, &lsense);   // 5

    // ---- P5: scatter edges into CSR buckets ----
    for (int e = gtid; e < E; e += gthreads) {
        int dst = rel_idx[e];
        int src = rel_idx[E + e];
        float w = rw[e];
        int p = atomicAdd(&g_cursor[dst], 1);
        g_edges[p] = make_int2(src, __float_as_int(w));
    }
    gbar(grid, &lsense);   // 6

    // ---- P6: per-node aggregation (warp per node), write fp16 mean ----
    {
        int gwarps = gthreads >> 5;
        int lane = tid & 31;
        for (int node = gtid >> 5; node < N; node += gwarps) {
            int beg = g_rowstart[node];
            int end = g_rowstart[node + 1];

            float ax = 0.f, ay = 0.f, az = 0.f, aw = 0.f;
            int i = beg;
            #pragma unroll 1
            for (; i + 4 <= end; i += 4) {
                int2 e0 = g_edges[i];
                int2 e1 = g_edges[i + 1];
                int2 e2 = g_edges[i + 2];
                int2 e3 = g_edges[i + 3];
                uint2 u0 = g_feat16[(size_t)e0.x * 32 + lane];
                uint2 u1 = g_feat16[(size_t)e1.x * 32 + lane];
                uint2 u2 = g_feat16[(size_t)e2.x * 32 + lane];
                uint2 u3 = g_feat16[(size_t)e3.x * 32 + lane];
                float w0 = __int_as_float(e0.y), w1 = __int_as_float(e1.y);
                float w2 = __int_as_float(e2.y), w3 = __int_as_float(e3.y);
                float2 p, q;
                p = __half22float2(*reinterpret_cast<__half2*>(&u0.x));
                q = __half22float2(*reinterpret_cast<__half2*>(&u0.y));
                ax = fmaf(p.x, w0, ax); ay = fmaf(p.y, w0, ay);
                az = fmaf(q.x, w0, az); aw = fmaf(q.y, w0, aw);
                p = __half22float2(*reinterpret_cast<__half2*>(&u1.x));
                q = __half22float2(*reinterpret_cast<__half2*>(&u1.y));
                ax = fmaf(p.x, w1, ax); ay = fmaf(p.y, w1, ay);
                az = fmaf(q.x, w1, az); aw = fmaf(q.y, w1, aw);
                p = __half22float2(*reinterpret_cast<__half2*>(&u2.x));
                q = __half22float2(*reinterpret_cast<__half2*>(&u2.y));
                ax = fmaf(p.x, w2, ax); ay = fmaf(p.y, w2, ay);
                az = fmaf(q.x, w2, az); aw = fmaf(q.y, w2, aw);
                p = __half22float2(*reinterpret_cast<__half2*>(&u3.x));
                q = __half22float2(*reinterpret_cast<__half2*>(&u3.y));
                ax = fmaf(p.x, w3, ax); ay = fmaf(p.y, w3, ay);
                az = fmaf(q.x, w3, az); aw = fmaf(q.y, w3, aw);
            }
            for (; i < end; i++) {
                int2 e0 = g_edges[i];
                uint2 u0 = g_feat16[(size_t)e0.x * 32 + lane];
                float w0 = __int_as_float(e0.y);
                float2 p = __half22float2(*reinterpret_cast<__half2*>(&u0.x));
                float2 q = __half22float2(*reinterpret_cast<__half2*>(&u0.y));
                ax = fmaf(p.x, w0, ax); ay = fmaf(p.y, w0, ay);
                az = fmaf(q.x, w0, az); aw = fmaf(q.y, w0, aw);
            }

            int deg = end - beg;
            float inv = 1.0f / (float)(deg > 1 ? deg : 1);
            __half2 m0 = __floats2half2_rn(ax * inv, ay * inv);
            __half2 m1 = __floats2half2_rn(az * inv, aw * inv);
            uint2 o;
            o.x = *reinterpret_cast<uint32_t*>(&m0);
            o.y = *reinterpret_cast<uint32_t*>(&m1);
            g_mean16[(size_t)node * 32 + lane] = o;
        }
    }
}

// ---------------------------------------------------------------------------
// Persistent streaming fp16 mma GEMM.
//   2 CTAs/SM x 192 threads (6 warps). W staged ONCE per CTA (fp16 smem,
//   ldmatrix.x4 for B). Each warp: 16 rows; A (all 16 k-steps, 64 regs)
//   batch-prefetched from the L2-resident fp16 tables in two 32-LDG waves.
//   No __syncthreads in the tile loop.
// ---------------------------------------------------------------------------
#define GEMM_THREADS 192
#define WS_STRIDE 132                              // uint32 per n-row
#define GEMM_SMEM (128 * WS_STRIDE * 4)            // 67584 B

__device__ __forceinline__ uint32_t smem_u32(const void* p) {
    uint32_t a;
    asm("{ .reg .u64 t; cvta.to.shared.u64 t, %1; cvt.u32.u64 %0, t; }"
        : "=r"(a) : "l"(p));
    return a;
}

__device__ __forceinline__ void mma_fp16(float& c0, float& c1, float& c2, float& c3,
                                         uint32_t a0, uint32_t a1, uint32_t a2, uint32_t a3,
                                         uint32_t b0, uint32_t b1) {
    asm volatile(
        "mma.sync.aligned.m16n8k16.row.col.f32.f16.f16.f32 "
        "{%0,%1,%2,%3}, {%4,%5,%6,%7}, {%8,%9}, {%0,%1,%2,%3};"
        : "+f"(c0), "+f"(c1), "+f"(c2), "+f"(c3)
        : "r"(a0), "r"(a1), "r"(a2), "r"(a3), "r"(b0), "r"(b1));
}

__global__ void __launch_bounds__(GEMM_THREADS, 2) gemm_kernel(
    const float* __restrict__ W,
    const float* __restrict__ b,
    float*       __restrict__ out,
    int N, int n_ctatiles)
{
    extern __shared__ uint32_t Ws[];   // [128 n][WS_STRIDE] fp16 pairs along k

    const int tid  = threadIdx.x;
    const int wid  = tid >> 5;
    const int lane = tid & 31;
    const int gid  = lane >> 2;        // 0..7
    const int tig  = lane & 3;         // 0..3

    // --- stage W once: Ws[n][kp] = (fp16 W[2kp][n], fp16 W[2kp+1][n]) ---
    for (int idx = tid; idx < 128 * 128; idx += GEMM_THREADS) {
        int kp = idx >> 7;
        int n  = idx & 127;
        __half2 h = __floats2half2_rn(W[(2 * kp) * OUT_DIM + n],
                                      W[(2 * kp + 1) * OUT_DIM + n]);
        Ws[n * WS_STRIDE + kp] = *reinterpret_cast<uint32_t*>(&h);
    }
    __syncthreads();

    const uint32_t* featw = reinterpret_cast<const uint32_t*>(g_feat16);
    const uint32_t* meanw = reinterpret_cast<const uint32_t*>(g_mean16);

    // per-lane ldmatrix.x4 base: row = (lane&7) + ((lane>>4)&1)*8 (two nt
    // tiles per load), word offset ((lane>>3)&1)*4 selects b0/b1 matrix.
    const uint32_t lm_base = smem_u32(Ws)
        + ((((lane & 7) + ((lane >> 4) & 1) * 8) * WS_STRIDE)
           + ((lane >> 3) & 1) * 4) * 4;

    for (int ct = blockIdx.x; ct < n_ctatiles; ct += gridDim.x) {
        const int nd0 = ct * 96 + wid * 16 + gid;
        const int nd1 = nd0 + 8;
        const bool v0 = nd0 < N;
        const bool v1 = nd1 < N;
        const size_t o0 = (size_t)nd0 * 64 + tig;
        const size_t o1 = (size_t)nd1 * 64 + tig;

        uint32_t a[16][4];
        // batch 1: steps 0..7 (feature half), 32 LDGs
        #pragma unroll
        for (int s = 0; s < 8; s++) {
            int kw = s * 8;
            a[s][0] = v0 ? featw[o0 + kw]     : 0u;
            a[s][1] = v1 ? featw[o1 + kw]     : 0u;
            a[s][2] = v0 ? featw[o0 + kw + 4] : 0u;
            a[s][3] = v1 ? featw[o1 + kw + 4] : 0u;
        }

        float acc[16][4];
        #pragma unroll
        for (int nt = 0; nt < 16; nt++)
            #pragma unroll
            for (int q = 0; q < 4; q++) acc[nt][q] = 0.f;

        #pragma unroll
        for (int step = 0; step < 16; step++) {
            if (step == 1) {
                // batch 2: steps 8..15 (mean half), issued while batch-1
                // results are being consumed
                #pragma unroll
                for (int s = 8; s < 16; s++) {
                    int kw = (s & 7) * 8;
                    a[s][0] = v0 ? meanw[o0 + kw]     : 0u;
                    a[s][1] = v1 ? meanw[o1 + kw]     : 0u;
                    a[s][2] = v0 ? meanw[o0 + kw + 4] : 0u;
                    a[s][3] = v1 ? meanw[o1 + kw + 4] : 0u;
                }
            }
            const uint32_t lm_step = lm_base + step * 32;   // +8 words per step
            #pragma unroll
            for (int p = 0; p < 8; p++) {
                uint32_t b0, b1, b2, b3;
                asm volatile(
                    "ldmatrix.sync.aligned.m8n8.x4.shared.b16 {%0,%1,%2,%3}, [%4];"
                    : "=r"(b0), "=r"(b1), "=r"(b2), "=r"(b3)
                    : "r"(lm_step + p * (16 * WS_STRIDE * 4)));
                mma_fp16(acc[2*p][0], acc[2*p][1], acc[2*p][2], acc[2*p][3],
                         a[step][0], a[step][1], a[step][2], a[step][3], b0, b1);
                mma_fp16(acc[2*p+1][0], acc[2*p+1][1], acc[2*p+1][2], acc[2*p+1][3],
                         a[step][0], a[step][1], a[step][2], a[step][3], b2, b3);
            }
        }

        // --- epilogue: bias + float2 stores ---
        #pragma unroll
        for (int nt = 0; nt < 16; nt++) {
            int col = nt * 8 + tig * 2;
            float2 bi = *reinterpret_cast<const float2*>(&b[col]);
            if (v0) {
                float2 o = make_float2(acc[nt][0] + bi.x, acc[nt][1] + bi.y);
                *reinterpret_cast<float2*>(&out[(size_t)nd0 * OUT_DIM + col]) = o;
            }
            if (v1) {
                float2 o = make_float2(acc[nt][2] + bi.x, acc[nt][3] + bi.y);
                *reinterpret_cast<float2*>(&out[(size_t)nd1 * OUT_DIM + col]) = o;
            }
        }
    }
}

// ---------------------------------------------------------------------------
// Launch
// ---------------------------------------------------------------------------
extern "C" void kernel_launch(void* const* d_in, const int* in_sizes, int n_in,
                              void* d_out, int out_size)
{
    const float* feat    = (const float*)d_in[0];
    const float* rw      = (const float*)d_in[1];
    const float* W       = (const float*)d_in[2];
    const float* b       = (const float*)d_in[3];
    const int*   rel_idx = (const int*)d_in[4];

    const int N = in_sizes[0] / D_FEAT;
    const int E = in_sizes[1];
    float* out = (float*)d_out;

    int sm = 0;
    cudaDeviceGetAttribute(&sm, cudaDevAttrMultiProcessorCount, 0);
    if (sm <= 0) sm = 148;

    mega_kernel<<<sm, MEGA_THREADS>>>(feat, rw, rel_idx, N, E, sm);

    int n_ctatiles = (N + 95) / 96;           // 96 rows per CTA-tile
    int grid = 2 * sm;
    if (grid > n_ctatiles) grid = n_ctatiles;
    cudaFuncSetAttribute(gemm_kernel,
                         cudaFuncAttributeMaxDynamicSharedMemorySize, GEMM_SMEM);
    gemm_kernel<<<grid, GEMM_THREADS, GEMM_SMEM>>>(W, b, out, N, n_ctatiles);
}

// round 9
// speedup vs baseline: 2.4442x; 1.0018x over previous
#include <cuda_runtime.h>
#include <cuda_bf16.h>
#include <cuda_fp16.h>
#include <cstdint>

// ---------------------------------------------------------------------------
// SAGESparseLayer: persistent fused edge pipeline + persistent fp16 mma GEMM.
//
//   mean[n] = (1/max(deg(n),1)) * sum_{e: dst[e]==n} feature[src[e]] * rw[e]
//   out[n]  = [feature[n], mean[n]] @ W + b
//
// GEMM: warp tile 32 rows x 64 cols (2 m16 x 8 n8). CTA = 4 warps = 128 rows
// x 64 cols; W column-half resident in 33 KB static smem; 3 CTAs/SM.
// A fragments double-buffered from L2-resident fp16 tables in 4-step batches.
// ---------------------------------------------------------------------------

#define D_FEAT    128
#define OUT_DIM   128
#define MAX_NODES 131072
#define MAX_EDGES (1 << 20)
#define MAX_CHUNKS 256
#define MEGA_THREADS 1024

static __device__ __align__(16) uint2 g_feat16[(size_t)MAX_NODES * 32];  // fp16 feat
static __device__ __align__(16) uint2 g_mean16[(size_t)MAX_NODES * 32];  // fp16 mean
static __device__ int  g_cnt[MAX_NODES];
static __device__ int  g_rowstart[MAX_NODES + 1];
static __device__ int  g_cursor[MAX_NODES];
static __device__ int  g_chunksum[MAX_CHUNKS];
static __device__ __align__(8) int2 g_edges[MAX_EDGES];

// software grid barrier state (replay-safe: even #barriers per launch)
static __device__ int g_bar_cnt;
static __device__ volatile int g_bar_sense;

__device__ __forceinline__ void gbar(int grid, int* lsense) {
    __syncthreads();
    if (threadIdx.x == 0) {
        int s = *lsense ^ 1;
        *lsense = s;
        __threadfence();
        if (atomicAdd(&g_bar_cnt, 1) == grid - 1) {
            g_bar_cnt = 0;
            __threadfence();
            g_bar_sense = s;
        } else {
            while (g_bar_sense != s) __nanosleep(64);
        }
        __threadfence();
    }
    __syncthreads();
}

// ---------------------------------------------------------------------------
// mega kernel: entire edge pipeline in one launch
// ---------------------------------------------------------------------------
__global__ void __launch_bounds__(MEGA_THREADS, 1) mega_kernel(
    const float* __restrict__ feat,
    const float* __restrict__ rw,
    const int*   __restrict__ rel_idx,
    int N, int E, int grid)
{
    __shared__ int ws[32];
    const int tid = threadIdx.x;
    const int cta = blockIdx.x;
    const int gthreads = grid * MEGA_THREADS;
    const int gtid = cta * MEGA_THREADS + tid;
    int lsense = 0;

    // ---- P0: zero counters ----
    for (int i = gtid; i < N; i += gthreads) g_cnt[i] = 0;
    gbar(grid, &lsense);   // 1

    // ---- P1: histogram + fp16 feature conversion (overlapped) ----
    for (int e = gtid; e < E; e += gthreads)
        atomicAdd(&g_cnt[rel_idx[e]], 1);
    {
        const float4* f4 = reinterpret_cast<const float4*>(feat);
        int total = N * 32;
        for (int i = gtid; i < total; i += gthreads) {
            float4 v = f4[i];
            __half2 a = __floats2half2_rn(v.x, v.y);
            __half2 c = __floats2half2_rn(v.z, v.w);
            uint2 o;
            o.x = *reinterpret_cast<uint32_t*>(&a);
            o.y = *reinterpret_cast<uint32_t*>(&c);
            g_feat16[i] = o;
        }
    }
    gbar(grid, &lsense);   // 2

    // ---- P2: per-chunk (1024) exclusive scan + chunk totals ----
    {
        int nchunks = (N + MEGA_THREADS - 1) / MEGA_THREADS;
        for (int c = cta; c < nchunks; c += grid) {
            int i = c * MEGA_THREADS + tid;
            int v = (i < N) ? g_cnt[i] : 0;
            int x = v;
            #pragma unroll
            for (int o = 1; o < 32; o <<= 1) {
                int y = __shfl_up_sync(0xffffffffu, x, o);
                if ((tid & 31) >= o) x += y;
            }
            if ((tid & 31) == 31) ws[tid >> 5] = x;
            __syncthreads();
            if (tid < 32) {
                int w = ws[tid];
                int xx = w;
                #pragma unroll
                for (int o = 1; o < 32; o <<= 1) {
                    int y = __shfl_up_sync(0xffffffffu, xx, o);
                    if (tid >= o) xx += y;
                }
                ws[tid] = xx - w;
            }
            __syncthreads();
            int excl = (x - v) + ws[tid >> 5];
            if (i < N) g_rowstart[i] = excl;
            if (tid == MEGA_THREADS - 1) g_chunksum[c] = excl + v;
            __syncthreads();
        }
    }
    gbar(grid, &lsense);   // 3

    // ---- P3: CTA 0 scans chunk totals ----
    if (cta == 0) {
        int nchunks = (N + MEGA_THREADS - 1) / MEGA_THREADS;
        int v = (tid < nchunks) ? g_chunksum[tid] : 0;
        int x = v;
        #pragma unroll
        for (int o = 1; o < 32; o <<= 1) {
            int y = __shfl_up_sync(0xffffffffu, x, o);
            if ((tid & 31) >= o) x += y;
        }
        if ((tid & 31) == 31) ws[tid >> 5] = x;
        __syncthreads();
        if (tid < 32) {
            int w = ws[tid];
            int xx = w;
            #pragma unroll
            for (int o = 1; o < 32; o <<= 1) {
                int y = __shfl_up_sync(0xffffffffu, xx, o);
                if (tid >= o) xx += y;
            }
            ws[tid] = xx - w;
        }
        __syncthreads();
        int excl = (x - v) + ws[tid >> 5];
        if (tid < nchunks) g_chunksum[tid] = excl;
    }
    gbar(grid, &lsense);   // 4

    // ---- P4: add chunk offsets, init cursor ----
    for (int i = gtid; i < N; i += gthreads) {
        int v = g_rowstart[i] + g_chunksum[i >> 10];
        g_rowstart[i] = v;
        g_cursor[i]   = v;
    }
    if (gtid == 0) g_rowstart[N] = E;
    gbar(grid, &lsense);   // 5

    // ---- P5: scatter edges into CSR buckets ----
    for (int e = gtid; e < E; e += gthreads) {
        int dst = rel_idx[e];
        int src = rel_idx[E + e];
        float w = rw[e];
        int p = atomicAdd(&g_cursor[dst], 1);
        g_edges[p] = make_int2(src, __float_as_int(w));
    }
    gbar(grid, &lsense);   // 6

    // ---- P6: per-node aggregation (warp per node), write fp16 mean ----
    {
        int gwarps = gthreads >> 5;
        int lane = tid & 31;
        for (int node = gtid >> 5; node < N; node += gwarps) {
            int beg = g_rowstart[node];
            int end = g_rowstart[node + 1];

            float ax = 0.f, ay = 0.f, az = 0.f, aw = 0.f;
            int i = beg;
            #pragma unroll 1
            for (; i + 4 <= end; i += 4) {
                int2 e0 = g_edges[i];
                int2 e1 = g_edges[i + 1];
                int2 e2 = g_edges[i + 2];
                int2 e3 = g_edges[i + 3];
                uint2 u0 = g_feat16[(size_t)e0.x * 32 + lane];
                uint2 u1 = g_feat16[(size_t)e1.x * 32 + lane];
                uint2 u2 = g_feat16[(size_t)e2.x * 32 + lane];
                uint2 u3 = g_feat16[(size_t)e3.x * 32 + lane];
                float w0 = __int_as_float(e0.y), w1 = __int_as_float(e1.y);
                float w2 = __int_as_float(e2.y), w3 = __int_as_float(e3.y);
                float2 p, q;
                p = __half22float2(*reinterpret_cast<__half2*>(&u0.x));
                q = __half22float2(*reinterpret_cast<__half2*>(&u0.y));
                ax = fmaf(p.x, w0, ax); ay = fmaf(p.y, w0, ay);
                az = fmaf(q.x, w0, az); aw = fmaf(q.y, w0, aw);
                p = __half22float2(*reinterpret_cast<__half2*>(&u1.x));
                q = __half22float2(*reinterpret_cast<__half2*>(&u1.y));
                ax = fmaf(p.x, w1, ax); ay = fmaf(p.y, w1, ay);
                az = fmaf(q.x, w1, az); aw = fmaf(q.y, w1, aw);
                p = __half22float2(*reinterpret_cast<__half2*>(&u2.x));
                q = __half22float2(*reinterpret_cast<__half2*>(&u2.y));
                ax = fmaf(p.x, w2, ax); ay = fmaf(p.y, w2, ay);
                az = fmaf(q.x, w2, az); aw = fmaf(q.y, w2, aw);
                p = __half22float2(*reinterpret_cast<__half2*>(&u3.x));
                q = __half22float2(*reinterpret_cast<__half2*>(&u3.y));
                ax = fmaf(p.x, w3, ax); ay = fmaf(p.y, w3, ay);
                az = fmaf(q.x, w3, az); aw = fmaf(q.y, w3, aw);
            }
            for (; i < end; i++) {
                int2 e0 = g_edges[i];
                uint2 u0 = g_feat16[(size_t)e0.x * 32 + lane];
                float w0 = __int_as_float(e0.y);
                float2 p = __half22float2(*reinterpret_cast<__half2*>(&u0.x));
                float2 q = __half22float2(*reinterpret_cast<__half2*>(&u0.y));
                ax = fmaf(p.x, w0, ax); ay = fmaf(p.y, w0, ay);
                az = fmaf(q.x, w0, az); aw = fmaf(q.y, w0, aw);
            }

            int deg = end - beg;
            float inv = 1.0f / (float)(deg > 1 ? deg : 1);
            __half2 m0 = __floats2half2_rn(ax * inv, ay * inv);
            __half2 m1 = __floats2half2_rn(az * inv, aw * inv);
            uint2 o;
            o.x = *reinterpret_cast<uint32_t*>(&m0);
            o.y = *reinterpret_cast<uint32_t*>(&m1);
            g_mean16[(size_t)node * 32 + lane] = o;
        }
    }
}

// ---------------------------------------------------------------------------
// GEMM: persistent, warp tile 32x64, CTA 128 rows x 64-col half, 3 CTAs/SM.
// ---------------------------------------------------------------------------
#define GEMM_THREADS 128
#define WS_STRIDE 132                     // uint32 per n-row

__device__ __forceinline__ uint32_t smem_u32(const void* p) {
    uint32_t a;
    asm("{ .reg .u64 t; cvta.to.shared.u64 t, %1; cvt.u32.u64 %0, t; }"
        : "=r"(a) : "l"(p));
    return a;
}

__device__ __forceinline__ void mma_fp16(float& c0, float& c1, float& c2, float& c3,
                                         uint32_t a0, uint32_t a1, uint32_t a2, uint32_t a3,
                                         uint32_t b0, uint32_t b1) {
    asm volatile(
        "mma.sync.aligned.m16n8k16.row.col.f32.f16.f16.f32 "
        "{%0,%1,%2,%3}, {%4,%5,%6,%7}, {%8,%9}, {%0,%1,%2,%3};"
        : "+f"(c0), "+f"(c1), "+f"(c2), "+f"(c3)
        : "r"(a0), "r"(a1), "r"(a2), "r"(a3), "r"(b0), "r"(b1));
}

__global__ void __launch_bounds__(GEMM_THREADS, 3) gemm_kernel(
    const float* __restrict__ W,
    const float* __restrict__ b,
    float*       __restrict__ out,
    int N, int n_rowtiles)
{
    __shared__ uint32_t Ws[64 * WS_STRIDE];   // 33792 B: W col-half, fp16 pairs

    const int tid  = threadIdx.x;
    const int wid  = tid >> 5;
    const int lane = tid & 31;
    const int gid  = lane >> 2;
    const int tig  = lane & 3;
    const int ch   = blockIdx.x & 1;          // column half

    // --- stage W col-half once: Ws[nl][kp] = (W[2kp][ch*64+nl], W[2kp+1][...]) ---
    for (int idx = tid; idx < 64 * 128; idx += GEMM_THREADS) {
        int kp = idx >> 6;
        int nl = idx & 63;
        int n  = ch * 64 + nl;
        __half2 h = __floats2half2_rn(W[(2 * kp) * OUT_DIM + n],
                                      W[(2 * kp + 1) * OUT_DIM + n]);
        Ws[nl * WS_STRIDE + kp] = *reinterpret_cast<uint32_t*>(&h);
    }
    __syncthreads();

    const uint32_t* featw = reinterpret_cast<const uint32_t*>(g_feat16);
    const uint32_t* meanw = reinterpret_cast<const uint32_t*>(g_mean16);

    // ldmatrix.x4 lane mapping (proven in round 7/8):
    // row = (lane&7) + ((lane>>4)&1)*8, word = ((lane>>3)&1)*4
    const uint32_t lm_base = smem_u32(Ws)
        + ((((lane & 7) + ((lane >> 4) & 1) * 8) * WS_STRIDE)
           + ((lane >> 3) & 1) * 4) * 4;

    const int rstep = gridDim.x >> 1;

    for (int rt = blockIdx.x >> 1; rt < n_rowtiles; rt += rstep) {
        const int ndb = rt * 128 + wid * 32 + gid;   // warp's base row
        const int nd[4] = { ndb, ndb + 8, ndb + 16, ndb + 24 };
        bool v[4];
        size_t o[4];
        #pragma unroll
        for (int r = 0; r < 4; r++) {
            v[r] = nd[r] < N;
            o[r] = (size_t)nd[r] * 64 + tig;
        }

        float acc[2][8][4];
        #pragma unroll
        for (int m = 0; m < 2; m++)
            #pragma unroll
            for (int nt = 0; nt < 8; nt++)
                #pragma unroll
                for (int q = 0; q < 4; q++) acc[m][nt][q] = 0.f;

        // A double-buffer: 4-step batches, 8 regs/step (2 m16 frags)
        uint32_t abuf[2][4][8];

        // load batch 0 (steps 0..3, feature half)
        #pragma unroll
        for (int s = 0; s < 4; s++) {
            int kw = s * 8;
            #pragma unroll
            for (int m = 0; m < 2; m++) {
                abuf[0][s][m*4+0] = v[2*m]   ? featw[o[2*m]   + kw]     : 0u;
                abuf[0][s][m*4+1] = v[2*m+1] ? featw[o[2*m+1] + kw]     : 0u;
                abuf[0][s][m*4+2] = v[2*m]   ? featw[o[2*m]   + kw + 4] : 0u;
                abuf[0][s][m*4+3] = v[2*m+1] ? featw[o[2*m+1] + kw + 4] : 0u;
            }
        }

        #pragma unroll
        for (int bi = 0; bi < 4; bi++) {
            const int cur = bi & 1;
            // prefetch next batch while computing this one
            if (bi < 3) {
                const int nb = bi + 1;
                const uint32_t* t = (nb < 2) ? featw : meanw;
                #pragma unroll
                for (int s = 0; s < 4; s++) {
                    int kw = ((nb * 4 + s) & 7) * 8;
                    #pragma unroll
                    for (int m = 0; m < 2; m++) {
                        abuf[nb & 1][s][m*4+0] = v[2*m]   ? t[o[2*m]   + kw]     : 0u;
                        abuf[nb & 1][s][m*4+1] = v[2*m+1] ? t[o[2*m+1] + kw]     : 0u;
                        abuf[nb & 1][s][m*4+2] = v[2*m]   ? t[o[2*m]   + kw + 4] : 0u;
                        abuf[nb & 1][s][m*4+3] = v[2*m+1] ? t[o[2*m+1] + kw + 4] : 0u;
                    }
                }
            }
            #pragma unroll
            for (int s = 0; s < 4; s++) {
                const int step = bi * 4 + s;
                const uint32_t lm_step = lm_base + step * 32;  // +8 words/step
                #pragma unroll
                for (int p = 0; p < 4; p++) {
                    uint32_t b0, b1, b2, b3;
                    asm volatile(
                        "ldmatrix.sync.aligned.m8n8.x4.shared.b16 {%0,%1,%2,%3}, [%4];"
                        : "=r"(b0), "=r"(b1), "=r"(b2), "=r"(b3)
                        : "r"(lm_step + p * (16 * WS_STRIDE * 4)));
                    #pragma unroll
                    for (int m = 0; m < 2; m++) {
                        mma_fp16(acc[m][2*p][0], acc[m][2*p][1],
                                 acc[m][2*p][2], acc[m][2*p][3],
                                 abuf[cur][s][m*4+0], abuf[cur][s][m*4+1],
                                 abuf[cur][s][m*4+2], abuf[cur][s][m*4+3], b0, b1);
                        mma_fp16(acc[m][2*p+1][0], acc[m][2*p+1][1],
                                 acc[m][2*p+1][2], acc[m][2*p+1][3],
                                 abuf[cur][s][m*4+0], abuf[cur][s][m*4+1],
                                 abuf[cur][s][m*4+2], abuf[cur][s][m*4+3], b2, b3);
                    }
                }
            }
        }

        // --- epilogue: bias + float2 stores ---
        #pragma unroll
        for (int m = 0; m < 2; m++) {
            int row0 = nd[2*m];
            int row1 = nd[2*m+1];
            #pragma unroll
            for (int nt = 0; nt < 8; nt++) {
                int col = ch * 64 + nt * 8 + tig * 2;
                float2 bi2 = *reinterpret_cast<const float2*>(&b[col]);
                if (v[2*m]) {
                    float2 oo = make_float2(acc[m][nt][0] + bi2.x,
                                            acc[m][nt][1] + bi2.y);
                    *reinterpret_cast<float2*>(&out[(size_t)row0 * OUT_DIM + col]) = oo;
                }
                if (v[2*m+1]) {
                    float2 oo = make_float2(acc[m][nt][2] + bi2.x,
                                            acc[m][nt][3] + bi2.y);
                    *reinterpret_cast<float2*>(&out[(size_t)row1 * OUT_DIM + col]) = oo;
                }
            }
        }
    }
}

// ---------------------------------------------------------------------------
// Launch
// ---------------------------------------------------------------------------
extern "C" void kernel_launch(void* const* d_in, const int* in_sizes, int n_in,
                              void* d_out, int out_size)
{
    const float* feat    = (const float*)d_in[0];
    const float* rw      = (const float*)d_in[1];
    const float* W       = (const float*)d_in[2];
    const float* b       = (const float*)d_in[3];
    const int*   rel_idx = (const int*)d_in[4];

    const int N = in_sizes[0] / D_FEAT;
    const int E = in_sizes[1];
    float* out = (float*)d_out;

    int sm = 0;
    cudaDeviceGetAttribute(&sm, cudaDevAttrMultiProcessorCount, 0);
    if (sm <= 0) sm = 148;

    mega_kernel<<<sm, MEGA_THREADS>>>(feat, rw, rel_idx, N, E, sm);

    int n_rowtiles = (N + 127) / 128;
    int grid = 3 * sm;                   // persistent, even (col-half parity)
    if (grid > 2 * n_rowtiles) grid = 2 * n_rowtiles;
    gemm_kernel<<<grid, GEMM_THREADS>>>(W, b, out, N, n_rowtiles);
}

// round 10
// speedup vs baseline: 2.5327x; 1.0362x over previous
#include <cuda_runtime.h>
#include <cuda_bf16.h>
#include <cuda_fp16.h>
#include <cstdint>

// ---------------------------------------------------------------------------
// SAGESparseLayer: persistent fused edge pipeline + persistent fp16 mma GEMM.
//
//   mean[n] = (1/max(deg(n),1)) * sum_{e: dst[e]==n} feature[src[e]] * rw[e]
//   out[n]  = [feature[n], mean[n]] @ W + b
//
// GEMM round 10: CTA 256 thr = 8 warps (4 row-groups x 2 col-halves),
// tile 128 rows x 128 cols. W resident (67.6 KB). A staged COALESCED into
// smem per half-table (34.8 KB, stride 68 words); A and B fragments both via
// ldmatrix.x4. 2 CTAs/SM (16 warps/SM).
// ---------------------------------------------------------------------------

#define D_FEAT    128
#define OUT_DIM   128
#define MAX_NODES 131072
#define MAX_EDGES (1 << 20)
#define MAX_CHUNKS 256
#define MEGA_THREADS 1024

static __device__ __align__(16) uint2 g_feat16[(size_t)MAX_NODES * 32];  // fp16 feat
static __device__ __align__(16) uint2 g_mean16[(size_t)MAX_NODES * 32];  // fp16 mean
static __device__ int  g_cnt[MAX_NODES];
static __device__ int  g_rowstart[MAX_NODES + 1];
static __device__ int  g_cursor[MAX_NODES];
static __device__ int  g_chunksum[MAX_CHUNKS];
static __device__ __align__(8) int2 g_edges[MAX_EDGES];

// software grid barrier state (replay-safe: even #barriers per launch)
static __device__ int g_bar_cnt;
static __device__ volatile int g_bar_sense;

__device__ __forceinline__ void gbar(int grid, int* lsense) {
    __syncthreads();
    if (threadIdx.x == 0) {
        int s = *lsense ^ 1;
        *lsense = s;
        __threadfence();
        if (atomicAdd(&g_bar_cnt, 1) == grid - 1) {
            g_bar_cnt = 0;
            __threadfence();
            g_bar_sense = s;
        } else {
            while (g_bar_sense != s) __nanosleep(64);
        }
        __threadfence();
    }
    __syncthreads();
}

// ---------------------------------------------------------------------------
// mega kernel: entire edge pipeline in one launch (unchanged from round 9)
// ---------------------------------------------------------------------------
__global__ void __launch_bounds__(MEGA_THREADS, 1) mega_kernel(
    const float* __restrict__ feat,
    const float* __restrict__ rw,
    const int*   __restrict__ rel_idx,
    int N, int E, int grid)
{
    __shared__ int ws[32];
    const int tid = threadIdx.x;
    const int cta = blockIdx.x;
    const int gthreads = grid * MEGA_THREADS;
    const int gtid = cta * MEGA_THREADS + tid;
    int lsense = 0;

    // ---- P0: zero counters ----
    for (int i = gtid; i < N; i += gthreads) g_cnt[i] = 0;
    gbar(grid, &lsense);   // 1

    // ---- P1: histogram + fp16 feature conversion (overlapped) ----
    for (int e = gtid; e < E; e += gthreads)
        atomicAdd(&g_cnt[rel_idx[e]], 1);
    {
        const float4* f4 = reinterpret_cast<const float4*>(feat);
        int total = N * 32;
        for (int i = gtid; i < total; i += gthreads) {
            float4 v = f4[i];
            __half2 a = __floats2half2_rn(v.x, v.y);
            __half2 c = __floats2half2_rn(v.z, v.w);
            uint2 o;
            o.x = *reinterpret_cast<uint32_t*>(&a);
            o.y = *reinterpret_cast<uint32_t*>(&c);
            g_feat16[i] = o;
        }
    }
    gbar(grid, &lsense);   // 2

    // ---- P2: per-chunk (1024) exclusive scan + chunk totals ----
    {
        int nchunks = (N + MEGA_THREADS - 1) / MEGA_THREADS;
        for (int c = cta; c < nchunks; c += grid) {
            int i = c * MEGA_THREADS + tid;
            int v = (i < N) ? g_cnt[i] : 0;
            int x = v;
            #pragma unroll
            for (int o = 1; o < 32; o <<= 1) {
                int y = __shfl_up_sync(0xffffffffu, x, o);
                if ((tid & 31) >= o) x += y;
            }
            if ((tid & 31) == 31) ws[tid >> 5] = x;
            __syncthreads();
            if (tid < 32) {
                int w = ws[tid];
                int xx = w;
                #pragma unroll
                for (int o = 1; o < 32; o <<= 1) {
                    int y = __shfl_up_sync(0xffffffffu, xx, o);
                    if (tid >= o) xx += y;
                }
                ws[tid] = xx - w;
            }
            __syncthreads();
            int excl = (x - v) + ws[tid >> 5];
            if (i < N) g_rowstart[i] = excl;
            if (tid == MEGA_THREADS - 1) g_chunksum[c] = excl + v;
            __syncthreads();
        }
    }
    gbar(grid, &lsense);   // 3

    // ---- P3: CTA 0 scans chunk totals ----
    if (cta == 0) {
        int nchunks = (N + MEGA_THREADS - 1) / MEGA_THREADS;
        int v = (tid < nchunks) ? g_chunksum[tid] : 0;
        int x = v;
        #pragma unroll
        for (int o = 1; o < 32; o <<= 1) {
            int y = __shfl_up_sync(0xffffffffu, x, o);
            if ((tid & 31) >= o) x += y;
        }
        if ((tid & 31) == 31) ws[tid >> 5] = x;
        __syncthreads();
        if (tid < 32) {
            int w = ws[tid];
            int xx = w;
            #pragma unroll
            for (int o = 1; o < 32; o <<= 1) {
                int y = __shfl_up_sync(0xffffffffu, xx, o);
                if (tid >= o) xx += y;
            }
            ws[tid] = xx - w;
        }
        __syncthreads();
        int excl = (x - v) + ws[tid >> 5];
        if (tid < nchunks) g_chunksum[tid] = excl;
    }
    gbar(grid, &lsense);   // 4

    // ---- P4: add chunk offsets, init cursor ----
    for (int i = gtid; i < N; i += gthreads) {
        int v = g_rowstart[i] + g_chunksum[i >> 10];
        g_rowstart[i] = v;
        g_cursor[i]   = v;
    }
    if (gtid == 0) g_rowstart[N] = E;
    gbar(grid, &lsense);   // 5

    // ---- P5: scatter edges into CSR buckets ----
    for (int e = gtid; e < E; e += gthreads) {
        int dst = rel_idx[e];
        int src = rel_idx[E + e];
        float w = rw[e];
        int p = atomicAdd(&g_cursor[dst], 1);
        g_edges[p] = make_int2(src, __float_as_int(w));
    }
    gbar(grid, &lsense);   // 6

    // ---- P6: per-node aggregation (warp per node), write fp16 mean ----
    {
        int gwarps = gthreads >> 5;
        int lane = tid & 31;
        for (int node = gtid >> 5; node < N; node += gwarps) {
            int beg = g_rowstart[node];
            int end = g_rowstart[node + 1];

            float ax = 0.f, ay = 0.f, az = 0.f, aw = 0.f;
            int i = beg;
            #pragma unroll 1
            for (; i + 4 <= end; i += 4) {
                int2 e0 = g_edges[i];
                int2 e1 = g_edges[i + 1];
                int2 e2 = g_edges[i + 2];
                int2 e3 = g_edges[i + 3];
                uint2 u0 = g_feat16[(size_t)e0.x * 32 + lane];
                uint2 u1 = g_feat16[(size_t)e1.x * 32 + lane];
                uint2 u2 = g_feat16[(size_t)e2.x * 32 + lane];
                uint2 u3 = g_feat16[(size_t)e3.x * 32 + lane];
                float w0 = __int_as_float(e0.y), w1 = __int_as_float(e1.y);
                float w2 = __int_as_float(e2.y), w3 = __int_as_float(e3.y);
                float2 p, q;
                p = __half22float2(*reinterpret_cast<__half2*>(&u0.x));
                q = __half22float2(*reinterpret_cast<__half2*>(&u0.y));
                ax = fmaf(p.x, w0, ax); ay = fmaf(p.y, w0, ay);
                az = fmaf(q.x, w0, az); aw = fmaf(q.y, w0, aw);
                p = __half22float2(*reinterpret_cast<__half2*>(&u1.x));
                q = __half22float2(*reinterpret_cast<__half2*>(&u1.y));
                ax = fmaf(p.x, w1, ax); ay = fmaf(p.y, w1, ay);
                az = fmaf(q.x, w1, az); aw = fmaf(q.y, w1, aw);
                p = __half22float2(*reinterpret_cast<__half2*>(&u2.x));
                q = __half22float2(*reinterpret_cast<__half2*>(&u2.y));
                ax = fmaf(p.x, w2, ax); ay = fmaf(p.y, w2, ay);
                az = fmaf(q.x, w2, az); aw = fmaf(q.y, w2, aw);
                p = __half22float2(*reinterpret_cast<__half2*>(&u3.x));
                q = __half22float2(*reinterpret_cast<__half2*>(&u3.y));
                ax = fmaf(p.x, w3, ax); ay = fmaf(p.y, w3, ay);
                az = fmaf(q.x, w3, az); aw = fmaf(q.y, w3, aw);
            }
            for (; i < end; i++) {
                int2 e0 = g_edges[i];
                uint2 u0 = g_feat16[(size_t)e0.x * 32 + lane];
                float w0 = __int_as_float(e0.y);
                float2 p = __half22float2(*reinterpret_cast<__half2*>(&u0.x));
                float2 q = __half22float2(*reinterpret_cast<__half2*>(&u0.y));
                ax = fmaf(p.x, w0, ax); ay = fmaf(p.y, w0, ay);
                az = fmaf(q.x, w0, az); aw = fmaf(q.y, w0, aw);
            }

            int deg = end - beg;
            float inv = 1.0f / (float)(deg > 1 ? deg : 1);
            __half2 m0 = __floats2half2_rn(ax * inv, ay * inv);
            __half2 m1 = __floats2half2_rn(az * inv, aw * inv);
            uint2 o;
            o.x = *reinterpret_cast<uint32_t*>(&m0);
            o.y = *reinterpret_cast<uint32_t*>(&m1);
            g_mean16[(size_t)node * 32 + lane] = o;
        }
    }
}

// ---------------------------------------------------------------------------
// GEMM: persistent, CTA 256 thr = 8 warps (4 row-groups x 2 col-halves),
// tile 128x128. A staged coalesced per half-table; A and B via ldmatrix.x4.
// ---------------------------------------------------------------------------
#define GEMM_THREADS 256
#define WS_STRIDE 132                  // uint32 per n-row (W)
#define AS_STRIDE 68                   // uint32 per m-row (A tile)
#define WS_WORDS (128 * WS_STRIDE)     // 16896
#define AS_WORDS (128 * AS_STRIDE)     // 8704
#define GEMM_SMEM ((WS_WORDS + AS_WORDS) * 4)   // 102400 B

__device__ __forceinline__ uint32_t smem_u32(const void* p) {
    uint32_t a;
    asm("{ .reg .u64 t; cvta.to.shared.u64 t, %1; cvt.u32.u64 %0, t; }"
        : "=r"(a) : "l"(p));
    return a;
}

__device__ __forceinline__ void mma_fp16(float& c0, float& c1, float& c2, float& c3,
                                         uint32_t a0, uint32_t a1, uint32_t a2, uint32_t a3,
                                         uint32_t b0, uint32_t b1) {
    asm volatile(
        "mma.sync.aligned.m16n8k16.row.col.f32.f16.f16.f32 "
        "{%0,%1,%2,%3}, {%4,%5,%6,%7}, {%8,%9}, {%0,%1,%2,%3};"
        : "+f"(c0), "+f"(c1), "+f"(c2), "+f"(c3)
        : "r"(a0), "r"(a1), "r"(a2), "r"(a3), "r"(b0), "r"(b1));
}

__global__ void __launch_bounds__(GEMM_THREADS, 2) gemm_kernel(
    const float* __restrict__ W,
    const float* __restrict__ b,
    float*       __restrict__ out,
    int N, int n_tiles)
{
    extern __shared__ uint32_t smem[];
    uint32_t* Ws = smem;               // [128 n][WS_STRIDE] fp16 pairs along k
    uint32_t* As = smem + WS_WORDS;    // [128 m][AS_STRIDE] fp16 pairs along k

    const int tid  = threadIdx.x;
    const int wid  = tid >> 5;
    const int lane = tid & 31;
    const int gid  = lane >> 2;
    const int tig  = lane & 3;
    const int wr   = wid >> 1;         // warp row-group 0..3 (32 rows each)
    const int c    = wid & 1;          // warp col-half 0..1 (64 cols each)

    // --- stage W once: Ws[n][kp] = (fp16 W[2kp][n], fp16 W[2kp+1][n]) ---
    for (int idx = tid; idx < 128 * 128; idx += GEMM_THREADS) {
        int kp = idx >> 7;
        int n  = idx & 127;
        __half2 h = __floats2half2_rn(W[(2 * kp) * OUT_DIM + n],
                                      W[(2 * kp + 1) * OUT_DIM + n]);
        Ws[n * WS_STRIDE + kp] = *reinterpret_cast<uint32_t*>(&h);
    }
    __syncthreads();

    // B ldmatrix.x4 base (proven mapping, + column-half offset):
    const uint32_t lmB = smem_u32(Ws)
        + (((c * 64 + (lane & 7) + ((lane >> 4) & 1) * 8) * WS_STRIDE)
           + ((lane >> 3) & 1) * 4) * 4;
    // A ldmatrix.x4 base: m0/m1 = row groups (+8), m2/m3 = +4-word k split.
    const uint32_t lmA = smem_u32(As)
        + ((wr * 32 + ((lane >> 3) & 1) * 8 + (lane & 7)) * AS_STRIDE
           + ((lane >> 4) & 1) * 4) * 4;

    const uint4* feat4 = reinterpret_cast<const uint4*>(g_feat16);
    const uint4* mean4 = reinterpret_cast<const uint4*>(g_mean16);
    const uint4 zero4 = make_uint4(0u, 0u, 0u, 0u);

    for (int t = blockIdx.x; t < n_tiles; t += gridDim.x) {
        const int node0 = t * 128;

        float acc[2][8][4];
        #pragma unroll
        for (int m = 0; m < 2; m++)
            #pragma unroll
            for (int nt = 0; nt < 8; nt++)
                #pragma unroll
                for (int q = 0; q < 4; q++) acc[m][nt][q] = 0.f;

        #pragma unroll 1
        for (int half = 0; half < 2; half++) {
            // --- stage A half-table tile: coalesced LDG.128 -> STS.128 ---
            const uint4* src = half ? mean4 : feat4;
            #pragma unroll
            for (int i = 0; i < 8; i++) {
                int idx = tid + i * GEMM_THREADS;
                int row = idx >> 4;
                int q   = idx & 15;
                int node = node0 + row;
                uint4 v = (node < N) ? src[(size_t)node * 16 + q] : zero4;
                *reinterpret_cast<uint4*>(&As[row * AS_STRIDE + q * 4]) = v;
            }
            __syncthreads();

            #pragma unroll
            for (int s = 0; s < 8; s++) {
                // A fragments: 2 m16 tiles, ldmatrix.x4 each
                uint32_t a[2][4];
                #pragma unroll
                for (int m = 0; m < 2; m++) {
                    asm volatile(
                        "ldmatrix.sync.aligned.m8n8.x4.shared.b16 {%0,%1,%2,%3}, [%4];"
                        : "=r"(a[m][0]), "=r"(a[m][1]), "=r"(a[m][2]), "=r"(a[m][3])
                        : "r"(lmA + (uint32_t)(m * 16 * AS_STRIDE * 4 + s * 32)));
                }
                const uint32_t kb = (uint32_t)((half * 8 + s) * 32);  // kp byte off
                #pragma unroll
                for (int p = 0; p < 4; p++) {
                    uint32_t b0, b1, b2, b3;
                    asm volatile(
                        "ldmatrix.sync.aligned.m8n8.x4.shared.b16 {%0,%1,%2,%3}, [%4];"
                        : "=r"(b0), "=r"(b1), "=r"(b2), "=r"(b3)
                        : "r"(lmB + (uint32_t)(p * 16 * WS_STRIDE * 4) + kb));
                    #pragma unroll
                    for (int m = 0; m < 2; m++) {
                        mma_fp16(acc[m][2*p][0], acc[m][2*p][1],
                                 acc[m][2*p][2], acc[m][2*p][3],
                                 a[m][0], a[m][1], a[m][2], a[m][3], b0, b1);
                        mma_fp16(acc[m][2*p+1][0], acc[m][2*p+1][1],
                                 acc[m][2*p+1][2], acc[m][2*p+1][3],
                                 a[m][0], a[m][1], a[m][2], a[m][3], b2, b3);
                    }
                }
            }
            __syncthreads();   // before restaging As / next tile
        }

        // --- epilogue: bias + float2 stores ---
        #pragma unroll
        for (int m = 0; m < 2; m++) {
            int row0 = node0 + wr * 32 + m * 16 + gid;
            int row1 = row0 + 8;
            #pragma unroll
            for (int nt = 0; nt < 8; nt++) {
                int col = c * 64 + nt * 8 + tig * 2;
                float2 bi2 = *reinterpret_cast<const float2*>(&b[col]);
                if (row0 < N) {
                    float2 oo = make_float2(acc[m][nt][0] + bi2.x,
                                            acc[m][nt][1] + bi2.y);
                    *reinterpret_cast<float2*>(&out[(size_t)row0 * OUT_DIM + col]) = oo;
                }
                if (row1 < N) {
                    float2 oo = make_float2(acc[m][nt][2] + bi2.x,
                                            acc[m][nt][3] + bi2.y);
                    *reinterpret_cast<float2*>(&out[(size_t)row1 * OUT_DIM + col]) = oo;
                }
            }
        }
        __syncthreads();   // all warps done with epilogue before next staging
    }
}

// ---------------------------------------------------------------------------
// Launch
// ---------------------------------------------------------------------------
extern "C" void kernel_launch(void* const* d_in, const int* in_sizes, int n_in,
                              void* d_out, int out_size)
{
    const float* feat    = (const float*)d_in[0];
    const float* rw      = (const float*)d_in[1];
    const float* W       = (const float*)d_in[2];
    const float* b       = (const float*)d_in[3];
    const int*   rel_idx = (const int*)d_in[4];

    const int N = in_sizes[0] / D_FEAT;
    const int E = in_sizes[1];
    float* out = (float*)d_out;

    int sm = 0;
    cudaDeviceGetAttribute(&sm, cudaDevAttrMultiProcessorCount, 0);
    if (sm <= 0) sm = 148;

    mega_kernel<<<sm, MEGA_THREADS>>>(feat, rw, rel_idx, N, E, sm);

    int n_tiles = (N + 127) / 128;
    int grid = 2 * sm;
    if (grid > n_tiles) grid = n_tiles;
    cudaFuncSetAttribute(gemm_kernel,
                         cudaFuncAttributeMaxDynamicSharedMemorySize, GEMM_SMEM);
    gemm_kernel<<<grid, GEMM_THREADS, GEMM_SMEM>>>(W, b, out, N, n_tiles);
}

// round 11
// speedup vs baseline: 2.6500x; 1.0463x over previous
#include <cuda_runtime.h>
#include <cuda_bf16.h>
#include <cuda_fp16.h>
#include <cstdint>

// ---------------------------------------------------------------------------
// SAGESparseLayer: persistent fused edge pipeline + persistent fp16 mma GEMM.
//   mean[n] = (1/max(deg(n),1)) * sum_{e: dst[e]==n} feature[src[e]] * rw[e]
//   out[n]  = [feature[n], mean[n]] @ W + b
//
// R11: GEMM A staged via cp.async in double-buffered 4-kstep chunks;
//      aggregation uses 16-lane/node uint4 gathers with 2-edge ILP.
// ---------------------------------------------------------------------------

#define D_FEAT    128
#define OUT_DIM   128
#define MAX_NODES 131072
#define MAX_EDGES (1 << 20)
#define MAX_CHUNKS 256
#define MEGA_THREADS 1024

static __device__ __align__(16) uint2 g_feat16[(size_t)MAX_NODES * 32];  // fp16 feat
static __device__ __align__(16) uint2 g_mean16[(size_t)MAX_NODES * 32];  // fp16 mean
static __device__ int  g_cnt[MAX_NODES];
static __device__ int  g_rowstart[MAX_NODES + 1];
static __device__ int  g_cursor[MAX_NODES];
static __device__ int  g_chunksum[MAX_CHUNKS];
static __device__ __align__(8) int2 g_edges[MAX_EDGES];

// software grid barrier state (replay-safe: even #barriers per launch)
static __device__ int g_bar_cnt;
static __device__ volatile int g_bar_sense;

__device__ __forceinline__ void gbar(int grid, int* lsense) {
    __syncthreads();
    if (threadIdx.x == 0) {
        int s = *lsense ^ 1;
        *lsense = s;
        __threadfence();
        if (atomicAdd(&g_bar_cnt, 1) == grid - 1) {
            g_bar_cnt = 0;
            __threadfence();
            g_bar_sense = s;
        } else {
            while (g_bar_sense != s) __nanosleep(64);
        }
        __threadfence();
    }
    __syncthreads();
}

// ---------------------------------------------------------------------------
// mega kernel: entire edge pipeline in one launch
// ---------------------------------------------------------------------------
__global__ void __launch_bounds__(MEGA_THREADS, 1) mega_kernel(
    const float* __restrict__ feat,
    const float* __restrict__ rw,
    const int*   __restrict__ rel_idx,
    int N, int E, int grid)
{
    __shared__ int ws[32];
    const int tid = threadIdx.x;
    const int cta = blockIdx.x;
    const int gthreads = grid * MEGA_THREADS;
    const int gtid = cta * MEGA_THREADS + tid;
    int lsense = 0;

    // ---- P0: zero counters ----
    for (int i = gtid; i < N; i += gthreads) g_cnt[i] = 0;
    gbar(grid, &lsense);   // 1

    // ---- P1: histogram + fp16 feature conversion (overlapped) ----
    for (int e = gtid; e < E; e += gthreads)
        atomicAdd(&g_cnt[rel_idx[e]], 1);
    {
        const float4* f4 = reinterpret_cast<const float4*>(feat);
        int total = N * 32;
        for (int i = gtid; i < total; i += gthreads) {
            float4 v = f4[i];
            __half2 a = __floats2half2_rn(v.x, v.y);
            __half2 c = __floats2half2_rn(v.z, v.w);
            uint2 o;
            o.x = *reinterpret_cast<uint32_t*>(&a);
            o.y = *reinterpret_cast<uint32_t*>(&c);
            g_feat16[i] = o;
        }
    }
    gbar(grid, &lsense);   // 2

    // ---- P2: per-chunk (1024) exclusive scan + chunk totals ----
    {
        int nchunks = (N + MEGA_THREADS - 1) / MEGA_THREADS;
        for (int c = cta; c < nchunks; c += grid) {
            int i = c * MEGA_THREADS + tid;
            int v = (i < N) ? g_cnt[i] : 0;
            int x = v;
            #pragma unroll
            for (int o = 1; o < 32; o <<= 1) {
                int y = __shfl_up_sync(0xffffffffu, x, o);
                if ((tid & 31) >= o) x += y;
            }
            if ((tid & 31) == 31) ws[tid >> 5] = x;
            __syncthreads();
            if (tid < 32) {
                int w = ws[tid];
                int xx = w;
                #pragma unroll
                for (int o = 1; o < 32; o <<= 1) {
                    int y = __shfl_up_sync(0xffffffffu, xx, o);
                    if (tid >= o) xx += y;
                }
                ws[tid] = xx - w;
            }
            __syncthreads();
            int excl = (x - v) + ws[tid >> 5];
            if (i < N) g_rowstart[i] = excl;
            if (tid == MEGA_THREADS - 1) g_chunksum[c] = excl + v;
            __syncthreads();
        }
    }
    gbar(grid, &lsense);   // 3

    // ---- P3: CTA 0 scans chunk totals ----
    if (cta == 0) {
        int nchunks = (N + MEGA_THREADS - 1) / MEGA_THREADS;
        int v = (tid < nchunks) ? g_chunksum[tid] : 0;
        int x = v;
        #pragma unroll
        for (int o = 1; o < 32; o <<= 1) {
            int y = __shfl_up_sync(0xffffffffu, x, o);
            if ((tid & 31) >= o) x += y;
        }
        if ((tid & 31) == 31) ws[tid >> 5] = x;
        __syncthreads();
        if (tid < 32) {
            int w = ws[tid];
            int xx = w;
            #pragma unroll
            for (int o = 1; o < 32; o <<= 1) {
                int y = __shfl_up_sync(0xffffffffu, xx, o);
                if (tid >= o) xx += y;
            }
            ws[tid] = xx - w;
        }
        __syncthreads();
        int excl = (x - v) + ws[tid >> 5];
        if (tid < nchunks) g_chunksum[tid] = excl;
    }
    gbar(grid, &lsense);   // 4

    // ---- P4: add chunk offsets, init cursor ----
    for (int i = gtid; i < N; i += gthreads) {
        int v = g_rowstart[i] + g_chunksum[i >> 10];
        g_rowstart[i] = v;
        g_cursor[i]   = v;
    }
    if (gtid == 0) g_rowstart[N] = E;
    gbar(grid, &lsense);   // 5

    // ---- P5: scatter edges into CSR buckets ----
    for (int e = gtid; e < E; e += gthreads) {
        int dst = rel_idx[e];
        int src = rel_idx[E + e];
        float w = rw[e];
        int p = atomicAdd(&g_cursor[dst], 1);
        g_edges[p] = make_int2(src, __float_as_int(w));
    }
    gbar(grid, &lsense);   // 6

    // ---- P6: aggregation. Warp per node, 16 lanes x uint4 per row,
    //          two edges concurrent (one per half-warp), shfl-combine.
    {
        const uint4* feat4 = reinterpret_cast<const uint4*>(g_feat16);
        int gwarps = gthreads >> 5;
        int lane = tid & 31;
        int half = lane >> 4;          // 0 or 1
        int hl   = lane & 15;          // lane within half
        for (int node = gtid >> 5; node < N; node += gwarps) {
            int beg = g_rowstart[node];
            int end = g_rowstart[node + 1];

            float a0=0.f,a1=0.f,a2=0.f,a3=0.f,a4=0.f,a5=0.f,a6=0.f,a7=0.f;
            int i = beg + half;
            #pragma unroll 1
            for (; i + 2 < end; i += 4) {
                int2 eA = g_edges[i];
                int2 eB = g_edges[i + 2];
                uint4 uA = feat4[(size_t)eA.x * 16 + hl];
                uint4 uB = feat4[(size_t)eB.x * 16 + hl];
                float wA = __int_as_float(eA.y);
                float wB = __int_as_float(eB.y);
                float2 p;
                p = __half22float2(*reinterpret_cast<__half2*>(&uA.x));
                a0 = fmaf(p.x, wA, a0); a1 = fmaf(p.y, wA, a1);
                p = __half22float2(*reinterpret_cast<__half2*>(&uA.y));
                a2 = fmaf(p.x, wA, a2); a3 = fmaf(p.y, wA, a3);
                p = __half22float2(*reinterpret_cast<__half2*>(&uA.z));
                a4 = fmaf(p.x, wA, a4); a5 = fmaf(p.y, wA, a5);
                p = __half22float2(*reinterpret_cast<__half2*>(&uA.w));
                a6 = fmaf(p.x, wA, a6); a7 = fmaf(p.y, wA, a7);
                p = __half22float2(*reinterpret_cast<__half2*>(&uB.x));
                a0 = fmaf(p.x, wB, a0); a1 = fmaf(p.y, wB, a1);
                p = __half22float2(*reinterpret_cast<__half2*>(&uB.y));
                a2 = fmaf(p.x, wB, a2); a3 = fmaf(p.y, wB, a3);
                p = __half22float2(*reinterpret_cast<__half2*>(&uB.z));
                a4 = fmaf(p.x, wB, a4); a5 = fmaf(p.y, wB, a5);
                p = __half22float2(*reinterpret_cast<__half2*>(&uB.w));
                a6 = fmaf(p.x, wB, a6); a7 = fmaf(p.y, wB, a7);
            }
            for (; i < end; i += 2) {
                int2 eA = g_edges[i];
                uint4 uA = feat4[(size_t)eA.x * 16 + hl];
                float wA = __int_as_float(eA.y);
                float2 p;
                p = __half22float2(*reinterpret_cast<__half2*>(&uA.x));
                a0 = fmaf(p.x, wA, a0); a1 = fmaf(p.y, wA, a1);
                p = __half22float2(*reinterpret_cast<__half2*>(&uA.y));
                a2 = fmaf(p.x, wA, a2); a3 = fmaf(p.y, wA, a3);
                p = __half22float2(*reinterpret_cast<__half2*>(&uA.z));
                a4 = fmaf(p.x, wA, a4); a5 = fmaf(p.y, wA, a5);
                p = __half22float2(*reinterpret_cast<__half2*>(&uA.w));
                a6 = fmaf(p.x, wA, a6); a7 = fmaf(p.y, wA, a7);
            }

            // combine the two halves (warp converged here)
            a0 += __shfl_xor_sync(0xffffffffu, a0, 16);
            a1 += __shfl_xor_sync(0xffffffffu, a1, 16);
            a2 += __shfl_xor_sync(0xffffffffu, a2, 16);
            a3 += __shfl_xor_sync(0xffffffffu, a3, 16);
            a4 += __shfl_xor_sync(0xffffffffu, a4, 16);
            a5 += __shfl_xor_sync(0xffffffffu, a5, 16);
            a6 += __shfl_xor_sync(0xffffffffu, a6, 16);
            a7 += __shfl_xor_sync(0xffffffffu, a7, 16);

            if (half == 0) {
                int deg = end - beg;
                float inv = 1.0f / (float)(deg > 1 ? deg : 1);
                __half2 m0 = __floats2half2_rn(a0 * inv, a1 * inv);
                __half2 m1 = __floats2half2_rn(a2 * inv, a3 * inv);
                __half2 m2 = __floats2half2_rn(a4 * inv, a5 * inv);
                __half2 m3 = __floats2half2_rn(a6 * inv, a7 * inv);
                uint4 o;
                o.x = *reinterpret_cast<uint32_t*>(&m0);
                o.y = *reinterpret_cast<uint32_t*>(&m1);
                o.z = *reinterpret_cast<uint32_t*>(&m2);
                o.w = *reinterpret_cast<uint32_t*>(&m3);
                reinterpret_cast<uint4*>(g_mean16)[(size_t)node * 16 + hl] = o;
            }
        }
    }
}

// ---------------------------------------------------------------------------
// GEMM: persistent, CTA 256 thr = 8 warps (4 row-groups x 2 col-halves),
// tile 128x128. W resident; A staged via cp.async in double-buffered
// 4-kstep chunks (stride 36 words, LDSM conflict-free). 2 CTAs/SM.
// ---------------------------------------------------------------------------
#define GEMM_THREADS 256
#define WS_STRIDE 132                  // uint32 per n-row (W)
#define AC_STRIDE 36                   // uint32 per m-row per A chunk
#define WS_WORDS (128 * WS_STRIDE)     // 16896
#define AC_WORDS (128 * AC_STRIDE)     // 4608
#define GEMM_SMEM ((WS_WORDS + 2 * AC_WORDS) * 4)   // 104448 B

__device__ __forceinline__ uint32_t smem_u32(const void* p) {
    uint32_t a;
    asm("{ .reg .u64 t; cvta.to.shared.u64 t, %1; cvt.u32.u64 %0, t; }"
        : "=r"(a) : "l"(p));
    return a;
}

__device__ __forceinline__ void cp_async16(uint32_t dst, const void* src,
                                           uint32_t zfill) {
    asm volatile("cp.async.cg.shared.global [%0], [%1], 16, %2;"
                 :: "r"(dst), "l"(src), "r"(zfill) : "memory");
}

__device__ __forceinline__ void mma_fp16(float& c0, float& c1, float& c2, float& c3,
                                         uint32_t a0, uint32_t a1, uint32_t a2, uint32_t a3,
                                         uint32_t b0, uint32_t b1) {
    asm volatile(
        "mma.sync.aligned.m16n8k16.row.col.f32.f16.f16.f32 "
        "{%0,%1,%2,%3}, {%4,%5,%6,%7}, {%8,%9}, {%0,%1,%2,%3};"
        : "+f"(c0), "+f"(c1), "+f"(c2), "+f"(c3)
        : "r"(a0), "r"(a1), "r"(a2), "r"(a3), "r"(b0), "r"(b1));
}

__global__ void __launch_bounds__(GEMM_THREADS, 2) gemm_kernel(
    const float* __restrict__ W,
    const float* __restrict__ b,
    float*       __restrict__ out,
    int N, int n_tiles)
{
    extern __shared__ uint32_t smem[];
    uint32_t* Ws = smem;                      // [128 n][WS_STRIDE]
    uint32_t* Ab = smem + WS_WORDS;           // 2 x [128 m][AC_STRIDE]

    const int tid  = threadIdx.x;
    const int wid  = tid >> 5;
    const int lane = tid & 31;
    const int gid  = lane >> 2;
    const int tig  = lane & 3;
    const int wr   = wid >> 1;                // row-group 0..3
    const int c2   = wid & 1;                 // col-half 0..1

    // --- stage W once ---
    for (int idx = tid; idx < 128 * 128; idx += GEMM_THREADS) {
        int kp = idx >> 7;
        int n  = idx & 127;
        __half2 h = __floats2half2_rn(W[(2 * kp) * OUT_DIM + n],
                                      W[(2 * kp + 1) * OUT_DIM + n]);
        Ws[n * WS_STRIDE + kp] = *reinterpret_cast<uint32_t*>(&h);
    }
    __syncthreads();

    const uint32_t lmB = smem_u32(Ws)
        + (((c2 * 64 + (lane & 7) + ((lane >> 4) & 1) * 8) * WS_STRIDE)
           + ((lane >> 3) & 1) * 4) * 4;
    const uint32_t lmA_row =
        ((wr * 32 + ((lane >> 3) & 1) * 8 + (lane & 7)) * AC_STRIDE
         + ((lane >> 4) & 1) * 4) * 4;
    const uint32_t abase0 = smem_u32(Ab);
    const uint32_t lmA[2] = { abase0 + lmA_row,
                              abase0 + AC_WORDS * 4 + lmA_row };

    // per-thread copy coords (4 x 16B per chunk)
    const int cp_row0 = tid >> 3;             // rows: tid>>3 + i*32
    const int cp_q    = tid & 7;              // uint4 index within 8

    const uint4* feat4 = reinterpret_cast<const uint4*>(g_feat16);
    const uint4* mean4 = reinterpret_cast<const uint4*>(g_mean16);

    for (int t = blockIdx.x; t < n_tiles; t += gridDim.x) {
        const int node0 = t * 128;

        float acc[2][8][4];
        #pragma unroll
        for (int m = 0; m < 2; m++)
            #pragma unroll
            for (int nt = 0; nt < 8; nt++)
                #pragma unroll
                for (int q = 0; q < 4; q++) acc[m][nt][q] = 0.f;

        // issue chunk ch (0..3) into buffer p
        auto issue = [&](int ch, int p) {
            const uint4* table = (ch < 2) ? feat4 : mean4;
            int qoff = (ch & 1) * 8;
            #pragma unroll
            for (int i = 0; i < 4; i++) {
                int row  = cp_row0 + i * 32;
                int node = node0 + row;
                bool v = node < N;
                const uint4* src = &table[(size_t)(v ? node : 0) * 16 + qoff + cp_q];
                uint32_t dst = abase0 + (uint32_t)(p * AC_WORDS
                              + row * AC_STRIDE + cp_q * 4) * 4;
                cp_async16(dst, src, v ? 16u : 0u);
            }
            asm volatile("cp.async.commit_group;" ::: "memory");
        };

        issue(0, 0);
        issue(1, 1);

        #pragma unroll
        for (int ch = 0; ch < 4; ch++) {
            if (ch < 3) {
                asm volatile("cp.async.wait_group 1;" ::: "memory");
            } else {
                asm volatile("cp.async.wait_group 0;" ::: "memory");
            }
            __syncthreads();

            const uint32_t lmAc = lmA[ch & 1];
            #pragma unroll
            for (int s2 = 0; s2 < 4; s2++) {
                const int step = ch * 4 + s2;
                uint32_t a[2][4];
                #pragma unroll
                for (int m = 0; m < 2; m++) {
                    asm volatile(
                        "ldmatrix.sync.aligned.m8n8.x4.shared.b16 {%0,%1,%2,%3}, [%4];"
                        : "=r"(a[m][0]), "=r"(a[m][1]), "=r"(a[m][2]), "=r"(a[m][3])
                        : "r"(lmAc + (uint32_t)(m * 16 * AC_STRIDE * 4 + s2 * 32)));
                }
                const uint32_t kb = (uint32_t)(step * 32);
                #pragma unroll
                for (int p = 0; p < 4; p++) {
                    uint32_t b0, b1, b2, b3;
                    asm volatile(
                        "ldmatrix.sync.aligned.m8n8.x4.shared.b16 {%0,%1,%2,%3}, [%4];"
                        : "=r"(b0), "=r"(b1), "=r"(b2), "=r"(b3)
                        : "r"(lmB + (uint32_t)(p * 16 * WS_STRIDE * 4) + kb));
                    #pragma unroll
                    for (int m = 0; m < 2; m++) {
                        mma_fp16(acc[m][2*p][0], acc[m][2*p][1],
                                 acc[m][2*p][2], acc[m][2*p][3],
                                 a[m][0], a[m][1], a[m][2], a[m][3], b0, b1);
                        mma_fp16(acc[m][2*p+1][0], acc[m][2*p+1][1],
                                 acc[m][2*p+1][2], acc[m][2*p+1][3],
                                 a[m][0], a[m][1], a[m][2], a[m][3], b2, b3);
                    }
                }
            }
            __syncthreads();
            if (ch < 2) issue(ch + 2, ch & 1);
        }

        // --- epilogue: bias + float2 stores ---
        #pragma unroll
        for (int m = 0; m < 2; m++) {
            int row0 = node0 + wr * 32 + m * 16 + gid;
            int row1 = row0 + 8;
            #pragma unroll
            for (int nt = 0; nt < 8; nt++) {
                int col = c2 * 64 + nt * 8 + tig * 2;
                float2 bi2 = *reinterpret_cast<const float2*>(&b[col]);
                if (row0 < N) {
                    float2 oo = make_float2(acc[m][nt][0] + bi2.x,
                                            acc[m][nt][1] + bi2.y);
                    *reinterpret_cast<float2*>(&out[(size_t)row0 * OUT_DIM + col]) = oo;
                }
                if (row1 < N) {
                    float2 oo = make_float2(acc[m][nt][2] + bi2.x,
                                            acc[m][nt][3] + bi2.y);
                    *reinterpret_cast<float2*>(&out[(size_t)row1 * OUT_DIM + col]) = oo;
                }
            }
        }
        __syncthreads();
    }
}

// ---------------------------------------------------------------------------
// Launch
// ---------------------------------------------------------------------------
extern "C" void kernel_launch(void* const* d_in, const int* in_sizes, int n_in,
                              void* d_out, int out_size)
{
    const float* feat    = (const float*)d_in[0];
    const float* rw      = (const float*)d_in[1];
    const float* W       = (const float*)d_in[2];
    const float* b       = (const float*)d_in[3];
    const int*   rel_idx = (const int*)d_in[4];

    const int N = in_sizes[0] / D_FEAT;
    const int E = in_sizes[1];
    float* out = (float*)d_out;

    int sm = 0;
    cudaDeviceGetAttribute(&sm, cudaDevAttrMultiProcessorCount, 0);
    if (sm <= 0) sm = 148;

    mega_kernel<<<sm, MEGA_THREADS>>>(feat, rw, rel_idx, N, E, sm);

    int n_tiles = (N + 127) / 128;
    int grid = 2 * sm;
    if (grid > n_tiles) grid = n_tiles;
    cudaFuncSetAttribute(gemm_kernel,
                         cudaFuncAttributeMaxDynamicSharedMemorySize, GEMM_SMEM);
    gemm_kernel<<<grid, GEMM_THREADS, GEMM_SMEM>>>(W, b, out, N, n_tiles);
}

// round 12
// speedup vs baseline: 2.7068x; 1.0214x over previous
#include <cuda_runtime.h>
#include <cuda_bf16.h>
#include <cuda_fp16.h>
#include <cstdint>

// ---------------------------------------------------------------------------
// SAGESparseLayer:
//   mean[n] = (1/max(deg(n),1)) * sum_{e: dst[e]==n} feature[src[e]] * rw[e]
//   out[n]  = [feature[n], mean[n]] @ W + b
//
// R12: launches = [build, agg, gemm, dummy] (period 4 -> ncu -s5 profiles agg).
//  - build: P0 zero, P1 hist+fp16 convert, P2-4 scan, P5 scatter (6 gbars).
//  - agg:   warp-per-node CSR aggregation (R11 code, own kernel).
//  - gemm:  warp-private strips, cp.async double buffer, NO main-loop
//           __syncthreads; W col-half per CTA; 2 CTAs/SM.
// ---------------------------------------------------------------------------

#define D_FEAT    128
#define OUT_DIM   128
#define MAX_NODES 131072
#define MAX_EDGES (1 << 20)
#define MAX_CHUNKS 256
#define MEGA_THREADS 1024

static __device__ __align__(16) uint2 g_feat16[(size_t)MAX_NODES * 32];  // fp16 feat
static __device__ __align__(16) uint2 g_mean16[(size_t)MAX_NODES * 32];  // fp16 mean
static __device__ int  g_cnt[MAX_NODES];
static __device__ int  g_rowstart[MAX_NODES + 1];
static __device__ int  g_cursor[MAX_NODES];
static __device__ int  g_chunksum[MAX_CHUNKS];
static __device__ __align__(8) int2 g_edges[MAX_EDGES];

// software grid barrier state (replay-safe: even #barriers per launch)
static __device__ int g_bar_cnt;
static __device__ volatile int g_bar_sense;

__device__ __forceinline__ void gbar(int grid, int* lsense) {
    __syncthreads();
    if (threadIdx.x == 0) {
        int s = *lsense ^ 1;
        *lsense = s;
        __threadfence();
        if (atomicAdd(&g_bar_cnt, 1) == grid - 1) {
            g_bar_cnt = 0;
            __threadfence();
            g_bar_sense = s;
        } else {
            while (g_bar_sense != s) __nanosleep(64);
        }
        __threadfence();
    }
    __syncthreads();
}

// ---------------------------------------------------------------------------
// build kernel: P0 zero, P1 hist + fp16 convert, P2-P4 scan, P5 scatter.
// 6 gbars total (even -> replay-safe).
// ---------------------------------------------------------------------------
__global__ void __launch_bounds__(MEGA_THREADS, 1) build_kernel(
    const float* __restrict__ feat,
    const float* __restrict__ rw,
    const int*   __restrict__ rel_idx,
    int N, int E, int grid)
{
    __shared__ int ws[32];
    const int tid = threadIdx.x;
    const int cta = blockIdx.x;
    const int gthreads = grid * MEGA_THREADS;
    const int gtid = cta * MEGA_THREADS + tid;
    int lsense = 0;

    // ---- P0: zero counters ----
    for (int i = gtid; i < N; i += gthreads) g_cnt[i] = 0;
    gbar(grid, &lsense);   // 1

    // ---- P1: histogram + fp16 feature conversion (overlapped) ----
    for (int e = gtid; e < E; e += gthreads)
        atomicAdd(&g_cnt[rel_idx[e]], 1);
    {
        const float4* f4 = reinterpret_cast<const float4*>(feat);
        int total = N * 32;
        for (int i = gtid; i < total; i += gthreads) {
            float4 v = f4[i];
            __half2 a = __floats2half2_rn(v.x, v.y);
            __half2 c = __floats2half2_rn(v.z, v.w);
            uint2 o;
            o.x = *reinterpret_cast<uint32_t*>(&a);
            o.y = *reinterpret_cast<uint32_t*>(&c);
            g_feat16[i] = o;
        }
    }
    gbar(grid, &lsense);   // 2

    // ---- P2: per-chunk (1024) exclusive scan + chunk totals ----
    {
        int nchunks = (N + MEGA_THREADS - 1) / MEGA_THREADS;
        for (int c = cta; c < nchunks; c += grid) {
            int i = c * MEGA_THREADS + tid;
            int v = (i < N) ? g_cnt[i] : 0;
            int x = v;
            #pragma unroll
            for (int o = 1; o < 32; o <<= 1) {
                int y = __shfl_up_sync(0xffffffffu, x, o);
                if ((tid & 31) >= o) x += y;
            }
            if ((tid & 31) == 31) ws[tid >> 5] = x;
            __syncthreads();
            if (tid < 32) {
                int w = ws[tid];
                int xx = w;
                #pragma unroll
                for (int o = 1; o < 32; o <<= 1) {
                    int y = __shfl_up_sync(0xffffffffu, xx, o);
                    if (tid >= o) xx += y;
                }
                ws[tid] = xx - w;
            }
            __syncthreads();
            int excl = (x - v) + ws[tid >> 5];
            if (i < N) g_rowstart[i] = excl;
            if (tid == MEGA_THREADS - 1) g_chunksum[c] = excl + v;
            __syncthreads();
        }
    }
    gbar(grid, &lsense);   // 3

    // ---- P3: CTA 0 scans chunk totals ----
    if (cta == 0) {
        int nchunks = (N + MEGA_THREADS - 1) / MEGA_THREADS;
        int v = (tid < nchunks) ? g_chunksum[tid] : 0;
        int x = v;
        #pragma unroll
        for (int o = 1; o < 32; o <<= 1) {
            int y = __shfl_up_sync(0xffffffffu, x, o);
            if ((tid & 31) >= o) x += y;
        }
        if ((tid & 31) == 31) ws[tid >> 5] = x;
        __syncthreads();
        if (tid < 32) {
            int w = ws[tid];
            int xx = w;
            #pragma unroll
            for (int o = 1; o < 32; o <<= 1) {
                int y = __shfl_up_sync(0xffffffffu, xx, o);
                if (tid >= o) xx += y;
            }
            ws[tid] = xx - w;
        }
        __syncthreads();
        int excl = (x - v) + ws[tid >> 5];
        if (tid < nchunks) g_chunksum[tid] = excl;
    }
    gbar(grid, &lsense);   // 4

    // ---- P4: add chunk offsets, init cursor ----
    for (int i = gtid; i < N; i += gthreads) {
        int v = g_rowstart[i] + g_chunksum[i >> 10];
        g_rowstart[i] = v;
        g_cursor[i]   = v;
    }
    if (gtid == 0) g_rowstart[N] = E;
    gbar(grid, &lsense);   // 5

    // ---- P5: scatter edges into CSR buckets ----
    for (int e = gtid; e < E; e += gthreads) {
        int dst = rel_idx[e];
        int src = rel_idx[E + e];
        float w = rw[e];
        int p = atomicAdd(&g_cursor[dst], 1);
        g_edges[p] = make_int2(src, __float_as_int(w));
    }
    gbar(grid, &lsense);   // 6 (keeps barrier count even for graph replay)
}

// ---------------------------------------------------------------------------
// agg kernel: warp per node, 16 lanes x uint4, 2 edges per half-warp (R11).
// ---------------------------------------------------------------------------
__global__ void __launch_bounds__(MEGA_THREADS, 1) agg_kernel(int N, int grid) {
    const uint4* feat4 = reinterpret_cast<const uint4*>(g_feat16);
    const int tid = threadIdx.x;
    const int gthreads = grid * MEGA_THREADS;
    const int gtid = blockIdx.x * MEGA_THREADS + tid;
    int gwarps = gthreads >> 5;
    int lane = tid & 31;
    int half = lane >> 4;
    int hl   = lane & 15;
    for (int node = gtid >> 5; node < N; node += gwarps) {
        int beg = g_rowstart[node];
        int end = g_rowstart[node + 1];

        float a0=0.f,a1=0.f,a2=0.f,a3=0.f,a4=0.f,a5=0.f,a6=0.f,a7=0.f;
        int i = beg + half;
        #pragma unroll 1
        for (; i + 2 < end; i += 4) {
            int2 eA = g_edges[i];
            int2 eB = g_edges[i + 2];
            uint4 uA = feat4[(size_t)eA.x * 16 + hl];
            uint4 uB = feat4[(size_t)eB.x * 16 + hl];
            float wA = __int_as_float(eA.y);
            float wB = __int_as_float(eB.y);
            float2 p;
            p = __half22float2(*reinterpret_cast<__half2*>(&uA.x));
            a0 = fmaf(p.x, wA, a0); a1 = fmaf(p.y, wA, a1);
            p = __half22float2(*reinterpret_cast<__half2*>(&uA.y));
            a2 = fmaf(p.x, wA, a2); a3 = fmaf(p.y, wA, a3);
            p = __half22float2(*reinterpret_cast<__half2*>(&uA.z));
            a4 = fmaf(p.x, wA, a4); a5 = fmaf(p.y, wA, a5);
            p = __half22float2(*reinterpret_cast<__half2*>(&uA.w));
            a6 = fmaf(p.x, wA, a6); a7 = fmaf(p.y, wA, a7);
            p = __half22float2(*reinterpret_cast<__half2*>(&uB.x));
            a0 = fmaf(p.x, wB, a0); a1 = fmaf(p.y, wB, a1);
            p = __half22float2(*reinterpret_cast<__half2*>(&uB.y));
            a2 = fmaf(p.x, wB, a2); a3 = fmaf(p.y, wB, a3);
            p = __half22float2(*reinterpret_cast<__half2*>(&uB.z));
            a4 = fmaf(p.x, wB, a4); a5 = fmaf(p.y, wB, a5);
            p = __half22float2(*reinterpret_cast<__half2*>(&uB.w));
            a6 = fmaf(p.x, wB, a6); a7 = fmaf(p.y, wB, a7);
        }
        for (; i < end; i += 2) {
            int2 eA = g_edges[i];
            uint4 uA = feat4[(size_t)eA.x * 16 + hl];
            float wA = __int_as_float(eA.y);
            float2 p;
            p = __half22float2(*reinterpret_cast<__half2*>(&uA.x));
            a0 = fmaf(p.x, wA, a0); a1 = fmaf(p.y, wA, a1);
            p = __half22float2(*reinterpret_cast<__half2*>(&uA.y));
            a2 = fmaf(p.x, wA, a2); a3 = fmaf(p.y, wA, a3);
            p = __half22float2(*reinterpret_cast<__half2*>(&uA.z));
            a4 = fmaf(p.x, wA, a4); a5 = fmaf(p.y, wA, a5);
            p = __half22float2(*reinterpret_cast<__half2*>(&uA.w));
            a6 = fmaf(p.x, wA, a6); a7 = fmaf(p.y, wA, a7);
        }

        a0 += __shfl_xor_sync(0xffffffffu, a0, 16);
        a1 += __shfl_xor_sync(0xffffffffu, a1, 16);
        a2 += __shfl_xor_sync(0xffffffffu, a2, 16);
        a3 += __shfl_xor_sync(0xffffffffu, a3, 16);
        a4 += __shfl_xor_sync(0xffffffffu, a4, 16);
        a5 += __shfl_xor_sync(0xffffffffu, a5, 16);
        a6 += __shfl_xor_sync(0xffffffffu, a6, 16);
        a7 += __shfl_xor_sync(0xffffffffu, a7, 16);

        if (half == 0) {
            int deg = end - beg;
            float inv = 1.0f / (float)(deg > 1 ? deg : 1);
            __half2 m0 = __floats2half2_rn(a0 * inv, a1 * inv);
            __half2 m1 = __floats2half2_rn(a2 * inv, a3 * inv);
            __half2 m2 = __floats2half2_rn(a4 * inv, a5 * inv);
            __half2 m3 = __floats2half2_rn(a6 * inv, a7 * inv);
            uint4 o;
            o.x = *reinterpret_cast<uint32_t*>(&m0);
            o.y = *reinterpret_cast<uint32_t*>(&m1);
            o.z = *reinterpret_cast<uint32_t*>(&m2);
            o.w = *reinterpret_cast<uint32_t*>(&m3);
            reinterpret_cast<uint4*>(g_mean16)[(size_t)node * 16 + hl] = o;
        }
    }
}

// ---------------------------------------------------------------------------
// GEMM: warp-private 32-row strips, col-half W per CTA, cp.async double
// buffer per warp, NO __syncthreads in the main loop. 2 CTAs/SM.
// ---------------------------------------------------------------------------
#define GEMM_THREADS 256
#define WS_STRIDE 132                          // uint32 per n-row (W half)
#define WH_WORDS (64 * WS_STRIDE)              // 8448
#define AC_STRIDE 36                           // uint32 per m-row per chunk
#define AW_CHUNK (32 * AC_STRIDE)              // 1152 words per warp chunk
#define GEMM_SMEM ((WH_WORDS + 8 * 2 * AW_CHUNK) * 4)   // 107520 B

__device__ __forceinline__ uint32_t smem_u32(const void* p) {
    uint32_t a;
    asm("{ .reg .u64 t; cvta.to.shared.u64 t, %1; cvt.u32.u64 %0, t; }"
        : "=r"(a) : "l"(p));
    return a;
}

__device__ __forceinline__ void cp_async16(uint32_t dst, const void* src,
                                           uint32_t zfill) {
    asm volatile("cp.async.cg.shared.global [%0], [%1], 16, %2;"
                 :: "r"(dst), "l"(src), "r"(zfill) : "memory");
}

__device__ __forceinline__ void mma_fp16(float& c0, float& c1, float& c2, float& c3,
                                         uint32_t a0, uint32_t a1, uint32_t a2, uint32_t a3,
                                         uint32_t b0, uint32_t b1) {
    asm volatile(
        "mma.sync.aligned.m16n8k16.row.col.f32.f16.f16.f32 "
        "{%0,%1,%2,%3}, {%4,%5,%6,%7}, {%8,%9}, {%0,%1,%2,%3};"
        : "+f"(c0), "+f"(c1), "+f"(c2), "+f"(c3)
        : "r"(a0), "r"(a1), "r"(a2), "r"(a3), "r"(b0), "r"(b1));
}

__global__ void __launch_bounds__(GEMM_THREADS, 2) gemm_kernel(
    const float* __restrict__ W,
    const float* __restrict__ b,
    float*       __restrict__ out,
    int N, int n_strips)
{
    extern __shared__ uint32_t smem[];
    uint32_t* Ws = smem;                       // [64 n][WS_STRIDE]
    uint32_t* Ab = smem + WH_WORDS;            // 8 warps x 2 x AW_CHUNK

    const int tid  = threadIdx.x;
    const int wid  = tid >> 5;
    const int lane = tid & 31;
    const int gid  = lane >> 2;
    const int tig  = lane & 3;
    const int ch   = blockIdx.x & 1;           // column half (grid is even)

    // --- stage W col-half once ---
    for (int idx = tid; idx < 64 * 128; idx += GEMM_THREADS) {
        int n  = idx & 63;
        int kp = idx >> 6;
        __half2 h = __floats2half2_rn(W[(2 * kp) * OUT_DIM + ch * 64 + n],
                                      W[(2 * kp + 1) * OUT_DIM + ch * 64 + n]);
        Ws[n * WS_STRIDE + kp] = *reinterpret_cast<uint32_t*>(&h);
    }
    __syncthreads();   // only block-wide sync in the kernel

    const uint32_t lmB = smem_u32(Ws)
        + (((lane & 7) + ((lane >> 4) & 1) * 8) * WS_STRIDE
           + ((lane >> 3) & 1) * 4) * 4;
    const uint32_t abw = smem_u32(Ab) + (uint32_t)(wid * 2 * AW_CHUNK) * 4;
    const uint32_t lmA_off =
        ((((lane >> 3) & 1) * 8 + (lane & 7)) * AC_STRIDE
         + ((lane >> 4) & 1) * 4) * 4;

    const int cp_r = lane >> 3;                // 0..3
    const int cp_q = lane & 7;                 // 0..7

    const uint4* feat4 = reinterpret_cast<const uint4*>(g_feat16);
    const uint4* mean4 = reinterpret_cast<const uint4*>(g_mean16);

    const int warp_g  = (blockIdx.x >> 1) * 8 + wid;
    const int wstride = (gridDim.x >> 1) * 8;

    for (int strip = warp_g; strip < n_strips; strip += wstride) {
        const int node0 = strip * 32;

        auto issue = [&](int c, int p) {
            const uint4* table = (c < 2) ? feat4 : mean4;
            int qoff = (c & 1) * 8;
            #pragma unroll
            for (int i = 0; i < 8; i++) {
                int row  = i * 4 + cp_r;
                int node = node0 + row;
                bool v = node < N;
                const uint4* src = &table[(size_t)(v ? node : 0) * 16 + qoff + cp_q];
                uint32_t dst = abw + (uint32_t)(p * AW_CHUNK
                              + row * AC_STRIDE + cp_q * 4) * 4;
                cp_async16(dst, src, v ? 16u : 0u);
            }
            asm volatile("cp.async.commit_group;" ::: "memory");
        };

        float acc[2][8][4];
        #pragma unroll
        for (int m = 0; m < 2; m++)
            #pragma unroll
            for (int nt = 0; nt < 8; nt++)
                #pragma unroll
                for (int q = 0; q < 4; q++) acc[m][nt][q] = 0.f;

        issue(0, 0);
        issue(1, 1);

        #pragma unroll
        for (int c = 0; c < 4; c++) {
            if (c < 3) {
                asm volatile("cp.async.wait_group 1;" ::: "memory");
            } else {
                asm volatile("cp.async.wait_group 0;" ::: "memory");
            }
            const uint32_t lmAc = abw + (uint32_t)((c & 1) * AW_CHUNK) * 4 + lmA_off;
            #pragma unroll
            for (int s2 = 0; s2 < 4; s2++) {
                const int step = c * 4 + s2;
                uint32_t a[2][4];
                #pragma unroll
                for (int m = 0; m < 2; m++) {
                    asm volatile(
                        "ldmatrix.sync.aligned.m8n8.x4.shared.b16 {%0,%1,%2,%3}, [%4];"
                        : "=r"(a[m][0]), "=r"(a[m][1]), "=r"(a[m][2]), "=r"(a[m][3])
                        : "r"(lmAc + (uint32_t)(m * 16 * AC_STRIDE * 4 + s2 * 32)));
                }
                const uint32_t kb = (uint32_t)(step * 32);
                #pragma unroll
                for (int p = 0; p < 4; p++) {
                    uint32_t b0, b1, b2, b3;
                    asm volatile(
                        "ldmatrix.sync.aligned.m8n8.x4.shared.b16 {%0,%1,%2,%3}, [%4];"
                        : "=r"(b0), "=r"(b1), "=r"(b2), "=r"(b3)
                        : "r"(lmB + (uint32_t)(p * 16 * WS_STRIDE * 4) + kb));
                    #pragma unroll
                    for (int m = 0; m < 2; m++) {
                        mma_fp16(acc[m][2*p][0], acc[m][2*p][1],
                                 acc[m][2*p][2], acc[m][2*p][3],
                                 a[m][0], a[m][1], a[m][2], a[m][3], b0, b1);
                        mma_fp16(acc[m][2*p+1][0], acc[m][2*p+1][1],
                                 acc[m][2*p+1][2], acc[m][2*p+1][3],
                                 a[m][0], a[m][1], a[m][2], a[m][3], b2, b3);
                    }
                }
            }
            if (c < 2) issue(c + 2, c & 1);   // warp-private buffer: no sync
        }

        // --- epilogue: bias + float2 stores ---
        #pragma unroll
        for (int m = 0; m < 2; m++) {
            int row0 = node0 + m * 16 + gid;
            int row1 = row0 + 8;
            #pragma unroll
            for (int nt = 0; nt < 8; nt++) {
                int col = ch * 64 + nt * 8 + tig * 2;
                float2 bi2 = *reinterpret_cast<const float2*>(&b[col]);
                if (row0 < N) {
                    float2 oo = make_float2(acc[m][nt][0] + bi2.x,
                                            acc[m][nt][1] + bi2.y);
                    *reinterpret_cast<float2*>(&out[(size_t)row0 * OUT_DIM + col]) = oo;
                }
                if (row1 < N) {
                    float2 oo = make_float2(acc[m][nt][2] + bi2.x,
                                            acc[m][nt][3] + bi2.y);
                    *reinterpret_cast<float2*>(&out[(size_t)row1 * OUT_DIM + col]) = oo;
                }
            }
        }
    }
}

// tiny dummy to set launch period = 4 so ncu (-s 5) profiles agg_kernel
__global__ void dummy_kernel() {}

// ---------------------------------------------------------------------------
// Launch
// ---------------------------------------------------------------------------
extern "C" void kernel_launch(void* const* d_in, const int* in_sizes, int n_in,
                              void* d_out, int out_size)
{
    const float* feat    = (const float*)d_in[0];
    const float* rw      = (const float*)d_in[1];
    const float* W       = (const float*)d_in[2];
    const float* b       = (const float*)d_in[3];
    const int*   rel_idx = (const int*)d_in[4];

    const int N = in_sizes[0] / D_FEAT;
    const int E = in_sizes[1];
    float* out = (float*)d_out;

    int sm = 0;
    cudaDeviceGetAttribute(&sm, cudaDevAttrMultiProcessorCount, 0);
    if (sm <= 0) sm = 148;

    build_kernel<<<sm, MEGA_THREADS>>>(feat, rw, rel_idx, N, E, sm);
    agg_kernel<<<sm, MEGA_THREADS>>>(N, sm);

    int n_strips = (N + 31) / 32;
    int grid = 2 * sm;                 // even: blockIdx parity = column half
    cudaFuncSetAttribute(gemm_kernel,
                         cudaFuncAttributeMaxDynamicSharedMemorySize, GEMM_SMEM);
    gemm_kernel<<<grid, GEMM_THREADS, GEMM_SMEM>>>(W, b, out, N, n_strips);

    dummy_kernel<<<1, 32>>>();
}

// round 13
// speedup vs baseline: 2.7924x; 1.0316x over previous
#include <cuda_runtime.h>
#include <cuda_bf16.h>
#include <cuda_fp16.h>
#include <cstdint>

// ---------------------------------------------------------------------------
// SAGESparseLayer:
//   mean[n] = (1/max(deg(n),1)) * sum_{e: dst[e]==n} feature[src[e]] * rw[e]
//   out[n]  = [feature[n], mean[n]] @ W + b
//
// R13: launches = [build, agg, gemm].
//  - build: P0 zero, P1 hist+fp16 convert, P2-4 scan, P5 scatter (6 gbars).
//  - agg:   warp-per-node, 16 lanes x uint4, 4 edges in flight per half-warp.
//  - gemm:  warp-private 32-row strips, cp.async double buffer, no main-loop
//           __syncthreads, W col-half per CTA, 2 CTAs/SM.
// ---------------------------------------------------------------------------

#define D_FEAT    128
#define OUT_DIM   128
#define MAX_NODES 131072
#define MAX_EDGES (1 << 20)
#define MAX_CHUNKS 256
#define MEGA_THREADS 1024

static __device__ __align__(16) uint2 g_feat16[(size_t)MAX_NODES * 32];  // fp16 feat
static __device__ __align__(16) uint2 g_mean16[(size_t)MAX_NODES * 32];  // fp16 mean
static __device__ int  g_cnt[MAX_NODES];
static __device__ int  g_rowstart[MAX_NODES + 1];
static __device__ int  g_cursor[MAX_NODES];
static __device__ int  g_chunksum[MAX_CHUNKS];
static __device__ __align__(8) int2 g_edges[MAX_EDGES];

// software grid barrier state (replay-safe: even #barriers per launch)
static __device__ int g_bar_cnt;
static __device__ volatile int g_bar_sense;

__device__ __forceinline__ void gbar(int grid, int* lsense) {
    __syncthreads();
    if (threadIdx.x == 0) {
        int s = *lsense ^ 1;
        *lsense = s;
        __threadfence();
        if (atomicAdd(&g_bar_cnt, 1) == grid - 1) {
            g_bar_cnt = 0;
            __threadfence();
            g_bar_sense = s;
        } else {
            while (g_bar_sense != s) __nanosleep(64);
        }
        __threadfence();
    }
    __syncthreads();
}

// ---------------------------------------------------------------------------
// build kernel: P0 zero, P1 hist + fp16 convert, P2-P4 scan, P5 scatter.
// ---------------------------------------------------------------------------
__global__ void __launch_bounds__(MEGA_THREADS, 1) build_kernel(
    const float* __restrict__ feat,
    const float* __restrict__ rw,
    const int*   __restrict__ rel_idx,
    int N, int E, int grid)
{
    __shared__ int ws[32];
    const int tid = threadIdx.x;
    const int cta = blockIdx.x;
    const int gthreads = grid * MEGA_THREADS;
    const int gtid = cta * MEGA_THREADS + tid;
    int lsense = 0;

    // ---- P0: zero counters ----
    for (int i = gtid; i < N; i += gthreads) g_cnt[i] = 0;
    gbar(grid, &lsense);   // 1

    // ---- P1: histogram + fp16 feature conversion (overlapped) ----
    for (int e = gtid; e < E; e += gthreads)
        atomicAdd(&g_cnt[rel_idx[e]], 1);
    {
        const float4* f4 = reinterpret_cast<const float4*>(feat);
        int total = N * 32;
        for (int i = gtid; i < total; i += gthreads) {
            float4 v = f4[i];
            __half2 a = __floats2half2_rn(v.x, v.y);
            __half2 c = __floats2half2_rn(v.z, v.w);
            uint2 o;
            o.x = *reinterpret_cast<uint32_t*>(&a);
            o.y = *reinterpret_cast<uint32_t*>(&c);
            g_feat16[i] = o;
        }
    }
    gbar(grid, &lsense);   // 2

    // ---- P2: per-chunk (1024) exclusive scan + chunk totals ----
    {
        int nchunks = (N + MEGA_THREADS - 1) / MEGA_THREADS;
        for (int c = cta; c < nchunks; c += grid) {
            int i = c * MEGA_THREADS + tid;
            int v = (i < N) ? g_cnt[i] : 0;
            int x = v;
            #pragma unroll
            for (int o = 1; o < 32; o <<= 1) {
                int y = __shfl_up_sync(0xffffffffu, x, o);
                if ((tid & 31) >= o) x += y;
            }
            if ((tid & 31) == 31) ws[tid >> 5] = x;
            __syncthreads();
            if (tid < 32) {
                int w = ws[tid];
                int xx = w;
                #pragma unroll
                for (int o = 1; o < 32; o <<= 1) {
                    int y = __shfl_up_sync(0xffffffffu, xx, o);
                    if (tid >= o) xx += y;
                }
                ws[tid] = xx - w;
            }
            __syncthreads();
            int excl = (x - v) + ws[tid >> 5];
            if (i < N) g_rowstart[i] = excl;
            if (tid == MEGA_THREADS - 1) g_chunksum[c] = excl + v;
            __syncthreads();
        }
    }
    gbar(grid, &lsense);   // 3

    // ---- P3: CTA 0 scans chunk totals ----
    if (cta == 0) {
        int nchunks = (N + MEGA_THREADS - 1) / MEGA_THREADS;
        int v = (tid < nchunks) ? g_chunksum[tid] : 0;
        int x = v;
        #pragma unroll
        for (int o = 1; o < 32; o <<= 1) {
            int y = __shfl_up_sync(0xffffffffu, x, o);
            if ((tid & 31) >= o) x += y;
        }
        if ((tid & 31) == 31) ws[tid >> 5] = x;
        __syncthreads();
        if (tid < 32) {
            int w = ws[tid];
            int xx = w;
            #pragma unroll
            for (int o = 1; o < 32; o <<= 1) {
                int y = __shfl_up_sync(0xffffffffu, xx, o);
                if (tid >= o) xx += y;
            }
            ws[tid] = xx - w;
        }
        __syncthreads();
        int excl = (x - v) + ws[tid >> 5];
        if (tid < nchunks) g_chunksum[tid] = excl;
    }
    gbar(grid, &lsense);   // 4

    // ---- P4: add chunk offsets, init cursor ----
    for (int i = gtid; i < N; i += gthreads) {
        int v = g_rowstart[i] + g_chunksum[i >> 10];
        g_rowstart[i] = v;
        g_cursor[i]   = v;
    }
    if (gtid == 0) g_rowstart[N] = E;
    gbar(grid, &lsense);   // 5

    // ---- P5: scatter edges into CSR buckets ----
    for (int e = gtid; e < E; e += gthreads) {
        int dst = rel_idx[e];
        int src = rel_idx[E + e];
        float w = rw[e];
        int p = atomicAdd(&g_cursor[dst], 1);
        g_edges[p] = make_int2(src, __float_as_int(w));
    }
    gbar(grid, &lsense);   // 6 (even count for graph replay)
}

// ---------------------------------------------------------------------------
// agg kernel: warp per node, 16 lanes x uint4, 4 edges in flight per half.
// ---------------------------------------------------------------------------
__device__ __forceinline__ void agg_edge(float* a, uint4 u, float w) {
    float2 p;
    p = __half22float2(*reinterpret_cast<__half2*>(&u.x));
    a[0] = fmaf(p.x, w, a[0]); a[1] = fmaf(p.y, w, a[1]);
    p = __half22float2(*reinterpret_cast<__half2*>(&u.y));
    a[2] = fmaf(p.x, w, a[2]); a[3] = fmaf(p.y, w, a[3]);
    p = __half22float2(*reinterpret_cast<__half2*>(&u.z));
    a[4] = fmaf(p.x, w, a[4]); a[5] = fmaf(p.y, w, a[5]);
    p = __half22float2(*reinterpret_cast<__half2*>(&u.w));
    a[6] = fmaf(p.x, w, a[6]); a[7] = fmaf(p.y, w, a[7]);
}

__global__ void __launch_bounds__(MEGA_THREADS, 1) agg_kernel(int N, int grid) {
    const uint4* feat4 = reinterpret_cast<const uint4*>(g_feat16);
    const int tid = threadIdx.x;
    const int gthreads = grid * MEGA_THREADS;
    const int gtid = blockIdx.x * MEGA_THREADS + tid;
    int gwarps = gthreads >> 5;
    int lane = tid & 31;
    int half = lane >> 4;
    int hl   = lane & 15;
    for (int node = gtid >> 5; node < N; node += gwarps) {
        int beg = g_rowstart[node];
        int end = g_rowstart[node + 1];

        float a[8] = {0.f,0.f,0.f,0.f,0.f,0.f,0.f,0.f};
        int i = beg + half;
        // 4 edges in flight per half-warp (8 per warp)
        #pragma unroll 1
        for (; i + 6 < end; i += 8) {
            int2 eA = g_edges[i];
            int2 eB = g_edges[i + 2];
            int2 eC = g_edges[i + 4];
            int2 eD = g_edges[i + 6];
            uint4 uA = feat4[(size_t)eA.x * 16 + hl];
            uint4 uB = feat4[(size_t)eB.x * 16 + hl];
            uint4 uC = feat4[(size_t)eC.x * 16 + hl];
            uint4 uD = feat4[(size_t)eD.x * 16 + hl];
            agg_edge(a, uA, __int_as_float(eA.y));
            agg_edge(a, uB, __int_as_float(eB.y));
            agg_edge(a, uC, __int_as_float(eC.y));
            agg_edge(a, uD, __int_as_float(eD.y));
        }
        #pragma unroll 1
        for (; i < end; i += 2) {
            int2 eA = g_edges[i];
            uint4 uA = feat4[(size_t)eA.x * 16 + hl];
            agg_edge(a, uA, __int_as_float(eA.y));
        }

        #pragma unroll
        for (int q = 0; q < 8; q++)
            a[q] += __shfl_xor_sync(0xffffffffu, a[q], 16);

        if (half == 0) {
            int deg = end - beg;
            float inv = 1.0f / (float)(deg > 1 ? deg : 1);
            __half2 m0 = __floats2half2_rn(a[0] * inv, a[1] * inv);
            __half2 m1 = __floats2half2_rn(a[2] * inv, a[3] * inv);
            __half2 m2 = __floats2half2_rn(a[4] * inv, a[5] * inv);
            __half2 m3 = __floats2half2_rn(a[6] * inv, a[7] * inv);
            uint4 o;
            o.x = *reinterpret_cast<uint32_t*>(&m0);
            o.y = *reinterpret_cast<uint32_t*>(&m1);
            o.z = *reinterpret_cast<uint32_t*>(&m2);
            o.w = *reinterpret_cast<uint32_t*>(&m3);
            reinterpret_cast<uint4*>(g_mean16)[(size_t)node * 16 + hl] = o;
        }
    }
}

// ---------------------------------------------------------------------------
// GEMM: warp-private 32-row strips, col-half W per CTA, cp.async double
// buffer per warp, NO __syncthreads in the main loop. 2 CTAs/SM.
// ---------------------------------------------------------------------------
#define GEMM_THREADS 256
#define WS_STRIDE 132                          // uint32 per n-row (W half)
#define WH_WORDS (64 * WS_STRIDE)              // 8448
#define AC_STRIDE 36                           // uint32 per m-row per chunk
#define AW_CHUNK (32 * AC_STRIDE)              // 1152 words per warp chunk
#define GEMM_SMEM ((WH_WORDS + 8 * 2 * AW_CHUNK) * 4)   // 107520 B

__device__ __forceinline__ uint32_t smem_u32(const void* p) {
    uint32_t a;
    asm("{ .reg .u64 t; cvta.to.shared.u64 t, %1; cvt.u32.u64 %0, t; }"
        : "=r"(a) : "l"(p));
    return a;
}

__device__ __forceinline__ void cp_async16(uint32_t dst, const void* src,
                                           uint32_t zfill) {
    asm volatile("cp.async.cg.shared.global [%0], [%1], 16, %2;"
                 :: "r"(dst), "l"(src), "r"(zfill) : "memory");
}

__device__ __forceinline__ void mma_fp16(float& c0, float& c1, float& c2, float& c3,
                                         uint32_t a0, uint32_t a1, uint32_t a2, uint32_t a3,
                                         uint32_t b0, uint32_t b1) {
    asm volatile(
        "mma.sync.aligned.m16n8k16.row.col.f32.f16.f16.f32 "
        "{%0,%1,%2,%3}, {%4,%5,%6,%7}, {%8,%9}, {%0,%1,%2,%3};"
        : "+f"(c0), "+f"(c1), "+f"(c2), "+f"(c3)
        : "r"(a0), "r"(a1), "r"(a2), "r"(a3), "r"(b0), "r"(b1));
}

__global__ void __launch_bounds__(GEMM_THREADS, 2) gemm_kernel(
    const float* __restrict__ W,
    const float* __restrict__ b,
    float*       __restrict__ out,
    int N, int n_strips)
{
    extern __shared__ uint32_t smem[];
    uint32_t* Ws = smem;                       // [64 n][WS_STRIDE]
    uint32_t* Ab = smem + WH_WORDS;            // 8 warps x 2 x AW_CHUNK

    const int tid  = threadIdx.x;
    const int wid  = tid >> 5;
    const int lane = tid & 31;
    const int gid  = lane >> 2;
    const int tig  = lane & 3;
    const int ch   = blockIdx.x & 1;           // column half (grid is even)

    // --- stage W col-half once ---
    for (int idx = tid; idx < 64 * 128; idx += GEMM_THREADS) {
        int n  = idx & 63;
        int kp = idx >> 6;
        __half2 h = __floats2half2_rn(W[(2 * kp) * OUT_DIM + ch * 64 + n],
                                      W[(2 * kp + 1) * OUT_DIM + ch * 64 + n]);
        Ws[n * WS_STRIDE + kp] = *reinterpret_cast<uint32_t*>(&h);
    }
    __syncthreads();   // only block-wide sync in the kernel

    const uint32_t lmB = smem_u32(Ws)
        + (((lane & 7) + ((lane >> 4) & 1) * 8) * WS_STRIDE
           + ((lane >> 3) & 1) * 4) * 4;
    const uint32_t abw = smem_u32(Ab) + (uint32_t)(wid * 2 * AW_CHUNK) * 4;
    const uint32_t lmA_off =
        ((((lane >> 3) & 1) * 8 + (lane & 7)) * AC_STRIDE
         + ((lane >> 4) & 1) * 4) * 4;

    const int cp_r = lane >> 3;                // 0..3
    const int cp_q = lane & 7;                 // 0..7

    const uint4* feat4 = reinterpret_cast<const uint4*>(g_feat16);
    const uint4* mean4 = reinterpret_cast<const uint4*>(g_mean16);

    const int warp_g  = (blockIdx.x >> 1) * 8 + wid;
    const int wstride = (gridDim.x >> 1) * 8;

    for (int strip = warp_g; strip < n_strips; strip += wstride) {
        const int node0 = strip * 32;

        auto issue = [&](int c, int p) {
            const uint4* table = (c < 2) ? feat4 : mean4;
            int qoff = (c & 1) * 8;
            #pragma unroll
            for (int i = 0; i < 8; i++) {
                int row  = i * 4 + cp_r;
                int node = node0 + row;
                bool v = node < N;
                const uint4* src = &table[(size_t)(v ? node : 0) * 16 + qoff + cp_q];
                uint32_t dst = abw + (uint32_t)(p * AW_CHUNK
                              + row * AC_STRIDE + cp_q * 4) * 4;
                cp_async16(dst, src, v ? 16u : 0u);
            }
            asm volatile("cp.async.commit_group;" ::: "memory");
        };

        float acc[2][8][4];
        #pragma unroll
        for (int m = 0; m < 2; m++)
            #pragma unroll
            for (int nt = 0; nt < 8; nt++)
                #pragma unroll
                for (int q = 0; q < 4; q++) acc[m][nt][q] = 0.f;

        issue(0, 0);
        issue(1, 1);

        #pragma unroll
        for (int c = 0; c < 4; c++) {
            if (c < 3) {
                asm volatile("cp.async.wait_group 1;" ::: "memory");
            } else {
                asm volatile("cp.async.wait_group 0;" ::: "memory");
            }
            const uint32_t lmAc = abw + (uint32_t)((c & 1) * AW_CHUNK) * 4 + lmA_off;
            #pragma unroll
            for (int s2 = 0; s2 < 4; s2++) {
                const int step = c * 4 + s2;
                uint32_t a[2][4];
                #pragma unroll
                for (int m = 0; m < 2; m++) {
                    asm volatile(
                        "ldmatrix.sync.aligned.m8n8.x4.shared.b16 {%0,%1,%2,%3}, [%4];"
                        : "=r"(a[m][0]), "=r"(a[m][1]), "=r"(a[m][2]), "=r"(a[m][3])
                        : "r"(lmAc + (uint32_t)(m * 16 * AC_STRIDE * 4 + s2 * 32)));
                }
                const uint32_t kb = (uint32_t)(step * 32);
                #pragma unroll
                for (int p = 0; p < 4; p++) {
                    uint32_t b0, b1, b2, b3;
                    asm volatile(
                        "ldmatrix.sync.aligned.m8n8.x4.shared.b16 {%0,%1,%2,%3}, [%4];"
                        : "=r"(b0), "=r"(b1), "=r"(b2), "=r"(b3)
                        : "r"(lmB + (uint32_t)(p * 16 * WS_STRIDE * 4) + kb));
                    #pragma unroll
                    for (int m = 0; m < 2; m++) {
                        mma_fp16(acc[m][2*p][0], acc[m][2*p][1],
                                 acc[m][2*p][2], acc[m][2*p][3],
                                 a[m][0], a[m][1], a[m][2], a[m][3], b0, b1);
                        mma_fp16(acc[m][2*p+1][0], acc[m][2*p+1][1],
                                 acc[m][2*p+1][2], acc[m][2*p+1][3],
                                 a[m][0], a[m][1], a[m][2], a[m][3], b2, b3);
                    }
                }
            }
            if (c < 2) issue(c + 2, c & 1);   // warp-private buffer: no sync
        }

        // --- epilogue: bias + float2 stores ---
        #pragma unroll
        for (int m = 0; m < 2; m++) {
            int row0 = node0 + m * 16 + gid;
            int row1 = row0 + 8;
            #pragma unroll
            for (int nt = 0; nt < 8; nt++) {
                int col = ch * 64 + nt * 8 + tig * 2;
                float2 bi2 = *reinterpret_cast<const float2*>(&b[col]);
                if (row0 < N) {
                    float2 oo = make_float2(acc[m][nt][0] + bi2.x,
                                            acc[m][nt][1] + bi2.y);
                    *reinterpret_cast<float2*>(&out[(size_t)row0 * OUT_DIM + col]) = oo;
                }
                if (row1 < N) {
                    float2 oo = make_float2(acc[m][nt][2] + bi2.x,
                                            acc[m][nt][3] + bi2.y);
                    *reinterpret_cast<float2*>(&out[(size_t)row1 * OUT_DIM + col]) = oo;
                }
            }
        }
    }
}

// ---------------------------------------------------------------------------
// Launch
// ---------------------------------------------------------------------------
extern "C" void kernel_launch(void* const* d_in, const int* in_sizes, int n_in,
                              void* d_out, int out_size)
{
    const float* feat    = (const float*)d_in[0];
    const float* rw      = (const float*)d_in[1];
    const float* W       = (const float*)d_in[2];
    const float* b       = (const float*)d_in[3];
    const int*   rel_idx = (const int*)d_in[4];

    const int N = in_sizes[0] / D_FEAT;
    const int E = in_sizes[1];
    float* out = (float*)d_out;

    int sm = 0;
    cudaDeviceGetAttribute(&sm, cudaDevAttrMultiProcessorCount, 0);
    if (sm <= 0) sm = 148;

    build_kernel<<<sm, MEGA_THREADS>>>(feat, rw, rel_idx, N, E, sm);
    agg_kernel<<<sm, MEGA_THREADS>>>(N, sm);

    int n_strips = (N + 31) / 32;
    int grid = 2 * sm;                 // even: blockIdx parity = column half
    cudaFuncSetAttribute(gemm_kernel,
                         cudaFuncAttributeMaxDynamicSharedMemorySize, GEMM_SMEM);
    gemm_kernel<<<grid, GEMM_THREADS, GEMM_SMEM>>>(W, b, out, N, n_strips);
}

// round 14
// speedup vs baseline: 2.9216x; 1.0463x over previous
#include <cuda_runtime.h>
#include <cuda_bf16.h>
#include <cuda_fp16.h>
#include <cstdint>

// ---------------------------------------------------------------------------
// SAGESparseLayer:
//   mean[n] = (1/max(deg(n),1)) * sum_{e: dst[e]==n} feature[src[e]] * rw[e]
//   out[n]  = [feature[n], mean[n]] @ W + b
//
// R14: launches = [mega, gemm].
//  mega (4 gbars, even -> replay-safe):
//   A: hist (cnt pre-zeroed by previous call / CUDA zero-init) + fp16 convert
//   B: per-chunk scan + chunk totals
//   C: redundant chunk-total scan (per CTA, smem) + offsets + cursor
//   D: scatter + re-zero cnt for next call
//   E: warp-per-node aggregation (4-edge ILP)
//  gemm: warp-private 32-row strips, cp.async double buffer, W col-half/CTA.
// ---------------------------------------------------------------------------

#define D_FEAT    128
#define OUT_DIM   128
#define MAX_NODES 131072
#define MAX_EDGES (1 << 20)
#define MAX_CHUNKS 256
#define MEGA_THREADS 1024

static __device__ __align__(16) uint2 g_feat16[(size_t)MAX_NODES * 32];  // fp16 feat
static __device__ __align__(16) uint2 g_mean16[(size_t)MAX_NODES * 32];  // fp16 mean
static __device__ int  g_cnt[MAX_NODES];          // ZERO at every launch entry
static __device__ int  g_rowstart[MAX_NODES + 1];
static __device__ int  g_cursor[MAX_NODES];
static __device__ int  g_chunksum[MAX_CHUNKS];
static __device__ __align__(8) int2 g_edges[MAX_EDGES];

// software grid barrier state (replay-safe: even #barriers per launch)
static __device__ int g_bar_cnt;
static __device__ volatile int g_bar_sense;

__device__ __forceinline__ void gbar(int grid, int* lsense) {
    __syncthreads();
    if (threadIdx.x == 0) {
        int s = *lsense ^ 1;
        *lsense = s;
        __threadfence();
        if (atomicAdd(&g_bar_cnt, 1) == grid - 1) {
            g_bar_cnt = 0;
            __threadfence();
            g_bar_sense = s;
        } else {
            while (g_bar_sense != s) __nanosleep(64);
        }
        __threadfence();
    }
    __syncthreads();
}

// ---------------------------------------------------------------------------
// agg helper: accumulate one edge's 8 features (fp16x2 -> f32 fma)
// ---------------------------------------------------------------------------
__device__ __forceinline__ void agg_edge(float* a, uint4 u, float w) {
    float2 p;
    p = __half22float2(*reinterpret_cast<__half2*>(&u.x));
    a[0] = fmaf(p.x, w, a[0]); a[1] = fmaf(p.y, w, a[1]);
    p = __half22float2(*reinterpret_cast<__half2*>(&u.y));
    a[2] = fmaf(p.x, w, a[2]); a[3] = fmaf(p.y, w, a[3]);
    p = __half22float2(*reinterpret_cast<__half2*>(&u.z));
    a[4] = fmaf(p.x, w, a[4]); a[5] = fmaf(p.y, w, a[5]);
    p = __half22float2(*reinterpret_cast<__half2*>(&u.w));
    a[6] = fmaf(p.x, w, a[6]); a[7] = fmaf(p.y, w, a[7]);
}

// ---------------------------------------------------------------------------
// mega kernel: hist+convert | chunk scan | offsets | scatter+zero | agg
// ---------------------------------------------------------------------------
__global__ void __launch_bounds__(MEGA_THREADS, 1) mega_kernel(
    const float* __restrict__ feat,
    const float* __restrict__ rw,
    const int*   __restrict__ rel_idx,
    int N, int E, int grid)
{
    __shared__ int ws[32];
    __shared__ int chunkoff[MAX_CHUNKS];
    const int tid = threadIdx.x;
    const int cta = blockIdx.x;
    const int gthreads = grid * MEGA_THREADS;
    const int gtid = cta * MEGA_THREADS + tid;
    const int nchunks = (N + MEGA_THREADS - 1) / MEGA_THREADS;
    int lsense = 0;

    // ---- A: histogram (g_cnt is pre-zeroed) + fp16 feature conversion ----
    for (int e = gtid; e < E; e += gthreads)
        atomicAdd(&g_cnt[rel_idx[e]], 1);
    {
        const float4* f4 = reinterpret_cast<const float4*>(feat);
        int total = N * 32;
        for (int i = gtid; i < total; i += gthreads) {
            float4 v = f4[i];
            __half2 a = __floats2half2_rn(v.x, v.y);
            __half2 c = __floats2half2_rn(v.z, v.w);
            uint2 o;
            o.x = *reinterpret_cast<uint32_t*>(&a);
            o.y = *reinterpret_cast<uint32_t*>(&c);
            g_feat16[i] = o;
        }
    }
    gbar(grid, &lsense);   // 1

    // ---- B: per-chunk (1024) exclusive scan + chunk totals ----
    for (int c = cta; c < nchunks; c += grid) {
        int i = c * MEGA_THREADS + tid;
        int v = (i < N) ? g_cnt[i] : 0;
        int x = v;
        #pragma unroll
        for (int o = 1; o < 32; o <<= 1) {
            int y = __shfl_up_sync(0xffffffffu, x, o);
            if ((tid & 31) >= o) x += y;
        }
        if ((tid & 31) == 31) ws[tid >> 5] = x;
        __syncthreads();
        if (tid < 32) {
            int w = ws[tid];
            int xx = w;
            #pragma unroll
            for (int o = 1; o < 32; o <<= 1) {
                int y = __shfl_up_sync(0xffffffffu, xx, o);
                if (tid >= o) xx += y;
            }
            ws[tid] = xx - w;
        }
        __syncthreads();
        int excl = (x - v) + ws[tid >> 5];
        if (i < N) g_rowstart[i] = excl;
        if (tid == MEGA_THREADS - 1) g_chunksum[c] = excl + v;
        __syncthreads();
    }
    gbar(grid, &lsense);   // 2

    // ---- C: redundant chunk-total scan (per CTA) + offsets + cursor ----
    {
        int v = (tid < nchunks) ? g_chunksum[tid] : 0;
        int x = v;
        #pragma unroll
        for (int o = 1; o < 32; o <<= 1) {
            int y = __shfl_up_sync(0xffffffffu, x, o);
            if ((tid & 31) >= o) x += y;
        }
        if ((tid & 31) == 31) ws[tid >> 5] = x;
        __syncthreads();
        if (tid < 32) {
            int w = ws[tid];
            int xx = w;
            #pragma unroll
            for (int o = 1; o < 32; o <<= 1) {
                int y = __shfl_up_sync(0xffffffffu, xx, o);
                if (tid >= o) xx += y;
            }
            ws[tid] = xx - w;
        }
        __syncthreads();
        int excl = (x - v) + ws[tid >> 5];
        if (tid < nchunks) chunkoff[tid] = excl;
        __syncthreads();

        for (int i = gtid; i < N; i += gthreads) {
            int v2 = g_rowstart[i] + chunkoff[i >> 10];
            g_rowstart[i] = v2;
            g_cursor[i]   = v2;
        }
        if (gtid == 0) g_rowstart[N] = E;
    }
    gbar(grid, &lsense);   // 3

    // ---- D: scatter edges into CSR buckets + re-zero cnt for next call ----
    for (int e = gtid; e < E; e += gthreads) {
        int dst = rel_idx[e];
        int src = rel_idx[E + e];
        float w = rw[e];
        int p = atomicAdd(&g_cursor[dst], 1);
        g_edges[p] = make_int2(src, __float_as_int(w));
    }
    for (int i = gtid; i < N; i += gthreads) g_cnt[i] = 0;
    gbar(grid, &lsense);   // 4 (even -> sense back to 0 for replay)

    // ---- E: warp-per-node aggregation, 4 edges in flight per half-warp ----
    {
        const uint4* feat4 = reinterpret_cast<const uint4*>(g_feat16);
        int gwarps = gthreads >> 5;
        int lane = tid & 31;
        int half = lane >> 4;
        int hl   = lane & 15;
        for (int node = gtid >> 5; node < N; node += gwarps) {
            int beg = g_rowstart[node];
            int end = g_rowstart[node + 1];

            float a[8] = {0.f,0.f,0.f,0.f,0.f,0.f,0.f,0.f};
            int i = beg + half;
            #pragma unroll 1
            for (; i + 6 < end; i += 8) {
                int2 eA = g_edges[i];
                int2 eB = g_edges[i + 2];
                int2 eC = g_edges[i + 4];
                int2 eD = g_edges[i + 6];
                uint4 uA = feat4[(size_t)eA.x * 16 + hl];
                uint4 uB = feat4[(size_t)eB.x * 16 + hl];
                uint4 uC = feat4[(size_t)eC.x * 16 + hl];
                uint4 uD = feat4[(size_t)eD.x * 16 + hl];
                agg_edge(a, uA, __int_as_float(eA.y));
                agg_edge(a, uB, __int_as_float(eB.y));
                agg_edge(a, uC, __int_as_float(eC.y));
                agg_edge(a, uD, __int_as_float(eD.y));
            }
            #pragma unroll 1
            for (; i < end; i += 2) {
                int2 eA = g_edges[i];
                uint4 uA = feat4[(size_t)eA.x * 16 + hl];
                agg_edge(a, uA, __int_as_float(eA.y));
            }

            #pragma unroll
            for (int q = 0; q < 8; q++)
                a[q] += __shfl_xor_sync(0xffffffffu, a[q], 16);

            if (half == 0) {
                int deg = end - beg;
                float inv = 1.0f / (float)(deg > 1 ? deg : 1);
                __half2 m0 = __floats2half2_rn(a[0] * inv, a[1] * inv);
                __half2 m1 = __floats2half2_rn(a[2] * inv, a[3] * inv);
                __half2 m2 = __floats2half2_rn(a[4] * inv, a[5] * inv);
                __half2 m3 = __floats2half2_rn(a[6] * inv, a[7] * inv);
                uint4 o;
                o.x = *reinterpret_cast<uint32_t*>(&m0);
                o.y = *reinterpret_cast<uint32_t*>(&m1);
                o.z = *reinterpret_cast<uint32_t*>(&m2);
                o.w = *reinterpret_cast<uint32_t*>(&m3);
                reinterpret_cast<uint4*>(g_mean16)[(size_t)node * 16 + hl] = o;
            }
        }
    }
}

// ---------------------------------------------------------------------------
// GEMM: warp-private 32-row strips, col-half W per CTA, cp.async double
// buffer per warp, NO __syncthreads in the main loop. 2 CTAs/SM.
// ---------------------------------------------------------------------------
#define GEMM_THREADS 256
#define WS_STRIDE 132                          // uint32 per n-row (W half)
#define WH_WORDS (64 * WS_STRIDE)              // 8448
#define AC_STRIDE 36                           // uint32 per m-row per chunk
#define AW_CHUNK (32 * AC_STRIDE)              // 1152 words per warp chunk
#define GEMM_SMEM ((WH_WORDS + 8 * 2 * AW_CHUNK) * 4)   // 107520 B

__device__ __forceinline__ uint32_t smem_u32(const void* p) {
    uint32_t a;
    asm("{ .reg .u64 t; cvta.to.shared.u64 t, %1; cvt.u32.u64 %0, t; }"
        : "=r"(a) : "l"(p));
    return a;
}

__device__ __forceinline__ void cp_async16(uint32_t dst, const void* src,
                                           uint32_t zfill) {
    asm volatile("cp.async.cg.shared.global [%0], [%1], 16, %2;"
                 :: "r"(dst), "l"(src), "r"(zfill) : "memory");
}

__device__ __forceinline__ void mma_fp16(float& c0, float& c1, float& c2, float& c3,
                                         uint32_t a0, uint32_t a1, uint32_t a2, uint32_t a3,
                                         uint32_t b0, uint32_t b1) {
    asm volatile(
        "mma.sync.aligned.m16n8k16.row.col.f32.f16.f16.f32 "
        "{%0,%1,%2,%3}, {%4,%5,%6,%7}, {%8,%9}, {%0,%1,%2,%3};"
        : "+f"(c0), "+f"(c1), "+f"(c2), "+f"(c3)
        : "r"(a0), "r"(a1), "r"(a2), "r"(a3), "r"(b0), "r"(b1));
}

__global__ void __launch_bounds__(GEMM_THREADS, 2) gemm_kernel(
    const float* __restrict__ W,
    const float* __restrict__ b,
    float*       __restrict__ out,
    int N, int n_strips)
{
    extern __shared__ uint32_t smem[];
    uint32_t* Ws = smem;                       // [64 n][WS_STRIDE]
    uint32_t* Ab = smem + WH_WORDS;            // 8 warps x 2 x AW_CHUNK

    const int tid  = threadIdx.x;
    const int wid  = tid >> 5;
    const int lane = tid & 31;
    const int gid  = lane >> 2;
    const int tig  = lane & 3;
    const int ch   = blockIdx.x & 1;           // column half (grid is even)

    // --- stage W col-half once ---
    for (int idx = tid; idx < 64 * 128; idx += GEMM_THREADS) {
        int n  = idx & 63;
        int kp = idx >> 6;
        __half2 h = __floats2half2_rn(W[(2 * kp) * OUT_DIM + ch * 64 + n],
                                      W[(2 * kp + 1) * OUT_DIM + ch * 64 + n]);
        Ws[n * WS_STRIDE + kp] = *reinterpret_cast<uint32_t*>(&h);
    }
    __syncthreads();   // only block-wide sync in the kernel

    const uint32_t lmB = smem_u32(Ws)
        + (((lane & 7) + ((lane >> 4) & 1) * 8) * WS_STRIDE
           + ((lane >> 3) & 1) * 4) * 4;
    const uint32_t abw = smem_u32(Ab) + (uint32_t)(wid * 2 * AW_CHUNK) * 4;
    const uint32_t lmA_off =
        ((((lane >> 3) & 1) * 8 + (lane & 7)) * AC_STRIDE
         + ((lane >> 4) & 1) * 4) * 4;

    const int cp_r = lane >> 3;                // 0..3
    const int cp_q = lane & 7;                 // 0..7

    const uint4* feat4 = reinterpret_cast<const uint4*>(g_feat16);
    const uint4* mean4 = reinterpret_cast<const uint4*>(g_mean16);

    const int warp_g  = (blockIdx.x >> 1) * 8 + wid;
    const int wstride = (gridDim.x >> 1) * 8;

    for (int strip = warp_g; strip < n_strips; strip += wstride) {
        const int node0 = strip * 32;

        auto issue = [&](int c, int p) {
            const uint4* table = (c < 2) ? feat4 : mean4;
            int qoff = (c & 1) * 8;
            #pragma unroll
            for (int i = 0; i < 8; i++) {
                int row  = i * 4 + cp_r;
                int node = node0 + row;
                bool v = node < N;
                const uint4* src = &table[(size_t)(v ? node : 0) * 16 + qoff + cp_q];
                uint32_t dst = abw + (uint32_t)(p * AW_CHUNK
                              + row * AC_STRIDE + cp_q * 4) * 4;
                cp_async16(dst, src, v ? 16u : 0u);
            }
            asm volatile("cp.async.commit_group;" ::: "memory");
        };

        float acc[2][8][4];
        #pragma unroll
        for (int m = 0; m < 2; m++)
            #pragma unroll
            for (int nt = 0; nt < 8; nt++)
                #pragma unroll
                for (int q = 0; q < 4; q++) acc[m][nt][q] = 0.f;

        issue(0, 0);
        issue(1, 1);

        #pragma unroll
        for (int c = 0; c < 4; c++) {
            if (c < 3) {
                asm volatile("cp.async.wait_group 1;" ::: "memory");
            } else {
                asm volatile("cp.async.wait_group 0;" ::: "memory");
            }
            const uint32_t lmAc = abw + (uint32_t)((c & 1) * AW_CHUNK) * 4 + lmA_off;
            #pragma unroll
            for (int s2 = 0; s2 < 4; s2++) {
                const int step = c * 4 + s2;
                uint32_t a[2][4];
                #pragma unroll
                for (int m = 0; m < 2; m++) {
                    asm volatile(
                        "ldmatrix.sync.aligned.m8n8.x4.shared.b16 {%0,%1,%2,%3}, [%4];"
                        : "=r"(a[m][0]), "=r"(a[m][1]), "=r"(a[m][2]), "=r"(a[m][3])
                        : "r"(lmAc + (uint32_t)(m * 16 * AC_STRIDE * 4 + s2 * 32)));
                }
                const uint32_t kb = (uint32_t)(step * 32);
                #pragma unroll
                for (int p = 0; p < 4; p++) {
                    uint32_t b0, b1, b2, b3;
                    asm volatile(
                        "ldmatrix.sync.aligned.m8n8.x4.shared.b16 {%0,%1,%2,%3}, [%4];"
                        : "=r"(b0), "=r"(b1), "=r"(b2), "=r"(b3)
                        : "r"(lmB + (uint32_t)(p * 16 * WS_STRIDE * 4) + kb));
                    #pragma unroll
                    for (int m = 0; m < 2; m++) {
                        mma_fp16(acc[m][2*p][0], acc[m][2*p][1],
                                 acc[m][2*p][2], acc[m][2*p][3],
                                 a[m][0], a[m][1], a[m][2], a[m][3], b0, b1);
                        mma_fp16(acc[m][2*p+1][0], acc[m][2*p+1][1],
                                 acc[m][2*p+1][2], acc[m][2*p+1][3],
                                 a[m][0], a[m][1], a[m][2], a[m][3], b2, b3);
                    }
                }
            }
            if (c < 2) issue(c + 2, c & 1);   // warp-private buffer: no sync
        }

        // --- epilogue: bias + float2 stores ---
        #pragma unroll
        for (int m = 0; m < 2; m++) {
            int row0 = node0 + m * 16 + gid;
            int row1 = row0 + 8;
            #pragma unroll
            for (int nt = 0; nt < 8; nt++) {
                int col = ch * 64 + nt * 8 + tig * 2;
                float2 bi2 = *reinterpret_cast<const float2*>(&b[col]);
                if (row0 < N) {
                    float2 oo = make_float2(acc[m][nt][0] + bi2.x,
                                            acc[m][nt][1] + bi2.y);
                    *reinterpret_cast<float2*>(&out[(size_t)row0 * OUT_DIM + col]) = oo;
                }
                if (row1 < N) {
                    float2 oo = make_float2(acc[m][nt][2] + bi2.x,
                                            acc[m][nt][3] + bi2.y);
                    *reinterpret_cast<float2*>(&out[(size_t)row1 * OUT_DIM + col]) = oo;
                }
            }
        }
    }
}

// ---------------------------------------------------------------------------
// Launch
// ---------------------------------------------------------------------------
extern "C" void kernel_launch(void* const* d_in, const int* in_sizes, int n_in,
                              void* d_out, int out_size)
{
    const float* feat    = (const float*)d_in[0];
    const float* rw      = (const float*)d_in[1];
    const float* W       = (const float*)d_in[2];
    const float* b       = (const float*)d_in[3];
    const int*   rel_idx = (const int*)d_in[4];

    const int N = in_sizes[0] / D_FEAT;
    const int E = in_sizes[1];
    float* out = (float*)d_out;

    int sm = 0;
    cudaDeviceGetAttribute(&sm, cudaDevAttrMultiProcessorCount, 0);
    if (sm <= 0) sm = 148;

    mega_kernel<<<sm, MEGA_THREADS>>>(feat, rw, rel_idx, N, E, sm);

    int n_strips = (N + 31) / 32;
    int grid = 2 * sm;                 // even: blockIdx parity = column half
    cudaFuncSetAttribute(gemm_kernel,
                         cudaFuncAttributeMaxDynamicSharedMemorySize, GEMM_SMEM);
    gemm_kernel<<<grid, GEMM_THREADS, GEMM_SMEM>>>(W, b, out, N, n_strips);
}